// round 2
// baseline (speedup 1.0000x reference)
#include <cuda_runtime.h>
#include <math.h>

#define Bdim 2
#define Ndim 128
#define Cdim 256
#define Hdim 8
#define Ddim 32
#define ROWS (Bdim*Ndim*Ndim)          // 32768
#define QKVW (3*Cdim)                   // 768
#define SCALE 0.17677669529663687f      // 1/sqrt(32)
#define LN_EPS 1e-5f

// ------------------------- scratch (device globals; no allocs) -------------
__device__ float g_eln[ROWS * Cdim];            // 33.5 MB
__device__ float g_qkv_in[ROWS * QKVW];         // 100 MB
__device__ float g_qkv_out[ROWS * QKVW];        // 100 MB
__device__ float g_bias_in[Bdim * Hdim * Ndim * Ndim];   // [b,h,k,i]  1 MB
__device__ float g_bias_out[Bdim * Hdim * Ndim * Ndim];  // [b,h,k,i]  1 MB
__device__ float g_va[ROWS * 2 * Cdim];         // 67 MB

// ------------------------- LayerNorm + E projections -----------------------
// one block per row (b,i,j), 256 threads (one per channel)
__global__ __launch_bounds__(256) void ln_kernel(
    const float* __restrict__ e,
    const float* __restrict__ ln_g, const float* __restrict__ ln_b,
    const float* __restrict__ WEin, const float* __restrict__ bEin,
    const float* __restrict__ WEout, const float* __restrict__ bEout,
    const float* __restrict__ mask,
    float* __restrict__ eln, float* __restrict__ bias_in, float* __restrict__ bias_out)
{
    const int row = blockIdx.x;
    const int t = threadIdx.x;
    const int lane = t & 31, warp = t >> 5;
    __shared__ float sred[8];
    __shared__ float sE[8][16];

    float x = e[(size_t)row * Cdim + t];

    // mean
    float s = x;
    #pragma unroll
    for (int o = 16; o; o >>= 1) s += __shfl_xor_sync(0xffffffffu, s, o);
    if (lane == 0) sred[warp] = s;
    __syncthreads();
    float mu = 0.f;
    #pragma unroll
    for (int w = 0; w < 8; w++) mu += sred[w];
    mu *= (1.0f / Cdim);
    __syncthreads();

    // variance
    float d = x - mu;
    float v = d * d;
    #pragma unroll
    for (int o = 16; o; o >>= 1) v += __shfl_xor_sync(0xffffffffu, v, o);
    if (lane == 0) sred[warp] = v;
    __syncthreads();
    float var = 0.f;
    #pragma unroll
    for (int w = 0; w < 8; w++) var += sred[w];
    var *= (1.0f / Cdim);

    float y = d * rsqrtf(var + LN_EPS) * ln_g[t] + ln_b[t];
    eln[(size_t)row * Cdim + t] = y;

    // E projections: 16 block-wide reductions (8 in + 8 out)
    float acc[16];
    #pragma unroll
    for (int h = 0; h < 8; h++) {
        acc[h]     = y * WEin [t * 8 + h];
        acc[8 + h] = y * WEout[t * 8 + h];
    }
    #pragma unroll
    for (int k = 0; k < 16; k++) {
        #pragma unroll
        for (int o = 16; o; o >>= 1) acc[k] += __shfl_xor_sync(0xffffffffu, acc[k], o);
    }
    if (lane == 0) {
        #pragma unroll
        for (int k = 0; k < 16; k++) sE[warp][k] = acc[k];
    }
    __syncthreads();
    if (t < 16) {
        int h2 = t & 7;
        float tot = 0.f;
        #pragma unroll
        for (int w = 0; w < 8; w++) tot += sE[w][t];
        float mk = mask[(size_t)row * 8 + h2];
        int b2 = row >> 14;           // / (128*128)
        int xx = (row >> 7) & 127;    // i-coordinate of this row
        int yy = row & 127;           // j-coordinate
        if (t < 8) {
            // in-pass: value used at (query i = xx, key k = yy) -> [b,h,k,i] = [b,h,yy,xx]
            bias_in[((size_t)(b2 * Hdim + h2) * Ndim + yy) * Ndim + xx] = tot + bEin[h2] + mk;
        } else {
            // out-pass: value used at (key k = xx, query i = yy) -> [b,h,k,i] = [b,h,xx,yy]
            bias_out[((size_t)(b2 * Hdim + h2) * Ndim + xx) * Ndim + yy] = tot + bEout[h2] + mk;
        }
    }
}

// ------------------------- tiled SGEMM + bias (+ optional Q scale) ---------
// C[M,N] = A[M,K] @ B[K,N] + bias[N];  cols < 256 scaled by SCALE if scaleQ
#define BM 64
#define BN 64
#define BKt 16
__global__ __launch_bounds__(256) void sgemm_bias(
    const float* __restrict__ A, const float* __restrict__ B,
    const float* __restrict__ bias, float* __restrict__ C,
    int K, int N, int scaleQ)
{
    __shared__ __align__(16) float As[BKt][BM];
    __shared__ __align__(16) float Bs[BKt][BN];
    const int tid = threadIdx.x;
    const int tx = tid & 15, ty = tid >> 4;
    const int bm = blockIdx.x * BM, bn = blockIdx.y * BN;

    float acc[4][4];
    #pragma unroll
    for (int i = 0; i < 4; i++)
        #pragma unroll
        for (int j = 0; j < 4; j++) acc[i][j] = 0.f;

    const int ar = tid >> 2, ac = (tid & 3) * 4;
    const int br = tid >> 4, bc = (tid & 15) * 4;
    const float* Aptr = A + (size_t)(bm + ar) * K + ac;
    const float* Bptr = B + (size_t)br * N + bn + bc;

    for (int k0 = 0; k0 < K; k0 += BKt) {
        float4 av = *(const float4*)(Aptr + k0);
        As[ac + 0][ar] = av.x; As[ac + 1][ar] = av.y;
        As[ac + 2][ar] = av.z; As[ac + 3][ar] = av.w;
        *(float4*)&Bs[br][bc] = *(const float4*)(Bptr + (size_t)k0 * N);
        __syncthreads();
        #pragma unroll
        for (int kk = 0; kk < BKt; kk++) {
            float4 a = *(const float4*)&As[kk][ty * 4];
            float4 b = *(const float4*)&Bs[kk][tx * 4];
            float ai[4] = {a.x, a.y, a.z, a.w};
            float bj[4] = {b.x, b.y, b.z, b.w};
            #pragma unroll
            for (int i = 0; i < 4; i++)
                #pragma unroll
                for (int j = 0; j < 4; j++) acc[i][j] += ai[i] * bj[j];
        }
        __syncthreads();
    }

    const int c = bn + tx * 4;
    float4 bv = *(const float4*)&bias[c];
    const float sc = (scaleQ && c < Cdim) ? SCALE : 1.0f;
    #pragma unroll
    for (int i = 0; i < 4; i++) {
        int r = bm + ty * 4 + i;
        float4 o;
        o.x = (acc[i][0] + bv.x) * sc;
        o.y = (acc[i][1] + bv.y) * sc;
        o.z = (acc[i][2] + bv.z) * sc;
        o.w = (acc[i][3] + bv.w) * sc;
        *(float4*)&C[(size_t)r * N + c] = o;
    }
}

// ------------------------- attention (both passes) -------------------------
// grid: x=j (128), y=b*8+h (16), z=pass (2); 128 threads, one query i each
__global__ __launch_bounds__(128) void attn_kernel(
    const float* __restrict__ qkv_in, const float* __restrict__ qkv_out,
    const float* __restrict__ bias_in, const float* __restrict__ bias_out,
    float* __restrict__ Va)
{
    __shared__ float Ks[Ndim][33];
    __shared__ float Vs[Ndim][33];
    const int j = blockIdx.x;
    const int h = blockIdx.y & 7;
    const int b = blockIdx.y >> 3;
    const int pass = blockIdx.z;
    const int i = threadIdx.x;

    const float* qkv = pass ? qkv_out : qkv_in;

    // stage K/V for this (b,j,h): in-pass rows (b,j,k); out-pass rows (b,k,j)
    {
        const int k = i;
        const int row = pass ? ((b * Ndim + k) * Ndim + j) : ((b * Ndim + j) * Ndim + k);
        const float* base = qkv + (size_t)row * QKVW + h;
        #pragma unroll
        for (int d = 0; d < Ddim; d++) {
            Ks[k][d] = base[Cdim + d * Hdim];
            Vs[k][d] = base[2 * Cdim + d * Hdim];
        }
    }
    float q[Ddim];
    {
        const int row = (b * Ndim + i) * Ndim + j;
        const float* base = qkv + (size_t)row * QKVW + h;
        #pragma unroll
        for (int d = 0; d < Ddim; d++) q[d] = base[d * Hdim];
    }
    __syncthreads();

    const float* brow = (pass ? bias_out : bias_in)
                        + (size_t)(b * Hdim + h) * Ndim * Ndim;   // [k][i]

    float m = -1e30f, l = 0.f;
    float acc[Ddim];
    #pragma unroll
    for (int d = 0; d < Ddim; d++) acc[d] = 0.f;

    for (int k = 0; k < Ndim; k++) {
        float s = brow[k * Ndim + i];
        #pragma unroll
        for (int d = 0; d < Ddim; d++) s += q[d] * Ks[k][d];
        if (s > m) {
            float corr = __expf(m - s);
            l *= corr;
            #pragma unroll
            for (int d = 0; d < Ddim; d++) acc[d] *= corr;
            m = s;
        }
        float p = __expf(s - m);
        l += p;
        #pragma unroll
        for (int d = 0; d < Ddim; d++) acc[d] += p * Vs[k][d];
    }

    const float inv = 1.0f / l;
    float* o = Va + (size_t)((b * Ndim + i) * Ndim + j) * (2 * Cdim) + h + (pass ? Hdim : 0);
    #pragma unroll
    for (int d = 0; d < Ddim; d++) o[d * 2 * Hdim] = acc[d] * inv;
}

// ------------------------- launcher ---------------------------------------
extern "C" void kernel_launch(void* const* d_in, const int* in_sizes, int n_in,
                              void* d_out, int out_size)
{
    (void)in_sizes; (void)n_in; (void)out_size;
    const float* e        = (const float*)d_in[0];
    const float* mask     = (const float*)d_in[1];
    const float* ln_g     = (const float*)d_in[2];
    const float* ln_b     = (const float*)d_in[3];
    const float* W_qkv_in = (const float*)d_in[4];
    const float* b_qkv_in = (const float*)d_in[5];
    const float* W_E_in   = (const float*)d_in[6];
    const float* b_E_in   = (const float*)d_in[7];
    const float* W_qkv_out= (const float*)d_in[8];
    const float* b_qkv_out= (const float*)d_in[9];
    const float* W_E_out  = (const float*)d_in[10];
    const float* b_E_out  = (const float*)d_in[11];
    const float* W_O      = (const float*)d_in[12];
    const float* b_O      = (const float*)d_in[13];

    float *p_eln, *p_qin, *p_qout, *p_bin, *p_bout, *p_va;
    cudaGetSymbolAddress((void**)&p_eln,  g_eln);
    cudaGetSymbolAddress((void**)&p_qin,  g_qkv_in);
    cudaGetSymbolAddress((void**)&p_qout, g_qkv_out);
    cudaGetSymbolAddress((void**)&p_bin,  g_bias_in);
    cudaGetSymbolAddress((void**)&p_bout, g_bias_out);
    cudaGetSymbolAddress((void**)&p_va,   g_va);

    ln_kernel<<<ROWS, 256>>>(e, ln_g, ln_b, W_E_in, b_E_in, W_E_out, b_E_out,
                             mask, p_eln, p_bin, p_bout);

    sgemm_bias<<<dim3(ROWS / BM, QKVW / BN), 256>>>(p_eln, W_qkv_in,  b_qkv_in,  p_qin,  Cdim, QKVW, 1);
    sgemm_bias<<<dim3(ROWS / BM, QKVW / BN), 256>>>(p_eln, W_qkv_out, b_qkv_out, p_qout, Cdim, QKVW, 1);

    attn_kernel<<<dim3(Ndim, Bdim * Hdim, 2), 128>>>(p_qin, p_qout, p_bin, p_bout, p_va);

    sgemm_bias<<<dim3(ROWS / BM, Cdim / BN), 256>>>(p_va, W_O, b_O, (float*)d_out, 2 * Cdim, Cdim, 0);
}

// round 5
// speedup vs baseline: 1.9054x; 1.9054x over previous
#include <cuda_runtime.h>
#include <cuda_bf16.h>
#include <cstdint>
#include <math.h>

#define Bdim 2
#define Ndim 128
#define Cdim 256
#define Hdim 8
#define Ddim 32
#define ROWS (Bdim*Ndim*Ndim)          // 32768
#define QKVW (3*Cdim)                   // 768
#define SCALE 0.17677669529663687f
#define LN_EPS 1e-5f
#define PLANE_ELEMS (Bdim*Hdim*Ndim*Ndim*Ddim)   // 8388608

// ======================= helpers ==========================================
__device__ __forceinline__ uint32_t smem_u32(const void* p) {
    uint32_t a;
    asm("{ .reg .u64 t; cvta.to.shared.u64 t, %1; cvt.u32.u64 %0, t; }" : "=r"(a) : "l"(p));
    return a;
}
__device__ __forceinline__ void ldsm4(uint32_t* r, uint32_t addr) {
    asm volatile("ldmatrix.sync.aligned.m8n8.x4.shared.b16 {%0,%1,%2,%3}, [%4];"
        : "=r"(r[0]), "=r"(r[1]), "=r"(r[2]), "=r"(r[3]) : "r"(addr));
}
__device__ __forceinline__ void mma16816(float* d, const uint32_t* a, const uint32_t* b) {
    asm volatile("mma.sync.aligned.m16n8k16.row.col.f32.bf16.bf16.f32 "
        "{%0,%1,%2,%3}, {%4,%5,%6,%7}, {%8,%9}, {%0,%1,%2,%3};"
        : "+f"(d[0]), "+f"(d[1]), "+f"(d[2]), "+f"(d[3])
        : "r"(a[0]), "r"(a[1]), "r"(a[2]), "r"(a[3]), "r"(b[0]), "r"(b[1]));
}

// ======================= scratch (device globals) ==========================
__device__ __align__(16) __nv_bfloat16 g_ahi[ROWS * Cdim];
__device__ __align__(16) __nv_bfloat16 g_alo[ROWS * Cdim];
__device__ __align__(16) __nv_bfloat16 g_win_hi[QKVW * Cdim];
__device__ __align__(16) __nv_bfloat16 g_win_lo[QKVW * Cdim];
__device__ __align__(16) __nv_bfloat16 g_wout_hi[QKVW * Cdim];
__device__ __align__(16) __nv_bfloat16 g_wout_lo[QKVW * Cdim];
__device__ __align__(16) __nv_bfloat16 g_wo_hi[Cdim * 2 * Cdim];
__device__ __align__(16) __nv_bfloat16 g_wo_lo[Cdim * 2 * Cdim];
__device__ __align__(16) float g_Qin[PLANE_ELEMS];
__device__ __align__(16) float g_Kin[PLANE_ELEMS];
__device__ __align__(16) float g_Vin[PLANE_ELEMS];
__device__ __align__(16) float g_Qout[PLANE_ELEMS];
__device__ __align__(16) float g_Kout[PLANE_ELEMS];
__device__ __align__(16) float g_Vout[PLANE_ELEMS];
__device__ __align__(16) float g_bias_in[Bdim * Hdim * Ndim * Ndim];
__device__ __align__(16) float g_bias_out[Bdim * Hdim * Ndim * Ndim];
__device__ __align__(16) float g_va[ROWS * 2 * Cdim];
__device__ __align__(16) __nv_bfloat16 g_vahi[ROWS * 2 * Cdim];
__device__ __align__(16) __nv_bfloat16 g_valo[ROWS * 2 * Cdim];

// ======================= weight convert (transpose + split) ================
__global__ void convert_w(const float* __restrict__ W, __nv_bfloat16* __restrict__ th,
                          __nv_bfloat16* __restrict__ tl, int K, int Nout, int perm)
{
    const int n = blockIdx.x;
    const int k = threadIdx.x;
    int orig = n;
    if (perm) {
        int part = n >> 8, rem = n & 255;
        int h = rem >> 5, d = rem & 31;
        orig = part * 256 + d * 8 + h;
    }
    float w = W[(size_t)k * Nout + orig];
    __nv_bfloat16 hi = __float2bfloat16(w);
    th[(size_t)n * K + k] = hi;
    tl[(size_t)n * K + k] = __float2bfloat16(w - __bfloat162float(hi));
}

// ======================= LayerNorm + E projections + bf16 split ============
__global__ __launch_bounds__(256) void ln_kernel(
    const float* __restrict__ e,
    const float* __restrict__ ln_g, const float* __restrict__ ln_b,
    const float* __restrict__ WEin, const float* __restrict__ bEin,
    const float* __restrict__ WEout, const float* __restrict__ bEout,
    const float* __restrict__ mask,
    __nv_bfloat16* __restrict__ ahi, __nv_bfloat16* __restrict__ alo,
    float* __restrict__ bias_in, float* __restrict__ bias_out)
{
    const int row = blockIdx.x;
    const int t = threadIdx.x;
    const int lane = t & 31, warp = t >> 5;
    __shared__ float sred[8];
    __shared__ float sE[8][16];

    float x = e[(size_t)row * Cdim + t];
    float s = x;
    #pragma unroll
    for (int o = 16; o; o >>= 1) s += __shfl_xor_sync(0xffffffffu, s, o);
    if (lane == 0) sred[warp] = s;
    __syncthreads();
    float mu = 0.f;
    #pragma unroll
    for (int w = 0; w < 8; w++) mu += sred[w];
    mu *= (1.0f / Cdim);
    __syncthreads();

    float d = x - mu;
    float v = d * d;
    #pragma unroll
    for (int o = 16; o; o >>= 1) v += __shfl_xor_sync(0xffffffffu, v, o);
    if (lane == 0) sred[warp] = v;
    __syncthreads();
    float var = 0.f;
    #pragma unroll
    for (int w = 0; w < 8; w++) var += sred[w];
    var *= (1.0f / Cdim);

    float y = d * rsqrtf(var + LN_EPS) * ln_g[t] + ln_b[t];
    __nv_bfloat16 hi = __float2bfloat16(y);
    ahi[(size_t)row * Cdim + t] = hi;
    alo[(size_t)row * Cdim + t] = __float2bfloat16(y - __bfloat162float(hi));

    float acc[16];
    #pragma unroll
    for (int h = 0; h < 8; h++) {
        acc[h]     = y * WEin [t * 8 + h];
        acc[8 + h] = y * WEout[t * 8 + h];
    }
    #pragma unroll
    for (int k = 0; k < 16; k++) {
        #pragma unroll
        for (int o = 16; o; o >>= 1) acc[k] += __shfl_xor_sync(0xffffffffu, acc[k], o);
    }
    if (lane == 0) {
        #pragma unroll
        for (int k = 0; k < 16; k++) sE[warp][k] = acc[k];
    }
    __syncthreads();
    if (t < 16) {
        int h2 = t & 7;
        float tot = 0.f;
        #pragma unroll
        for (int w = 0; w < 8; w++) tot += sE[w][t];
        float mk = mask[(size_t)row * 8 + h2];
        int b2 = row >> 14;
        int xx = (row >> 7) & 127;
        int yy = row & 127;
        if (t < 8)
            bias_in[((size_t)(b2 * Hdim + h2) * Ndim + yy) * Ndim + xx] = tot + bEin[h2] + mk;
        else
            bias_out[((size_t)(b2 * Hdim + h2) * Ndim + xx) * Ndim + yy] = tot + bEout[h2] + mk;
    }
}

// ======================= HMMA GEMM (split-bf16, fp32 acc) ==================
// C tile 128x64; A[M,K] row-major bf16 hi/lo, B[N,K] row-major bf16 hi/lo
// modes as before: 0 qkv-in planes, 1 qkv-out planes, 2 plain [M,256]
#define SM_A_HI 0
#define SM_A_LO 16384
#define SM_B_HI 32768
#define SM_B_LO 40960
#define SM_TOTAL 49152

__global__ __launch_bounds__(256) void mma_gemm(
    const __nv_bfloat16* __restrict__ Ah, const __nv_bfloat16* __restrict__ Al,
    const __nv_bfloat16* __restrict__ Bh, const __nv_bfloat16* __restrict__ Bl,
    const float* __restrict__ bias, int K, int mode,
    float* __restrict__ o0, float* __restrict__ o1, float* __restrict__ o2)
{
    extern __shared__ __align__(1024) char smem[];
    const uint32_t sb = smem_u32(smem);
    const int tid = threadIdx.x;
    const int wid = tid >> 5, lane = tid & 31;
    const int bm = blockIdx.x * 128;
    const int bn = blockIdx.y * 64;
    const int NCH = K >> 6;
    const int m0 = (wid & 3) * 32;
    const int n0w = (wid >> 2) * 32;

    float acc[2][4][4];
    #pragma unroll
    for (int a = 0; a < 2; a++)
        #pragma unroll
        for (int b = 0; b < 4; b++)
            #pragma unroll
            for (int cc = 0; cc < 4; cc++) acc[a][b][cc] = 0.f;

    // per-thread ldmatrix row offsets + swizzle keys
    uint32_t aOff[2], aKey[2], bOff[2], bKey[2];
    #pragma unroll
    for (int mi = 0; mi < 2; mi++) {
        int r = m0 + mi * 16 + (lane & 15);
        aOff[mi] = r * 128; aKey[mi] = (r & 7) << 4;
    }
    #pragma unroll
    for (int pi = 0; pi < 2; pi++) {
        int r = n0w + pi * 16 + ((lane >> 4) << 3) + (lane & 7);
        bOff[pi] = r * 128; bKey[pi] = (r & 7) << 4;
    }
    const uint32_t aK = (lane >> 4) * 16;
    const uint32_t bK = ((lane >> 3) & 1) * 16;

    for (int c = 0; c < NCH; c++) {
        if (c) __syncthreads();
        // stage A hi/lo: 128 rows x 64 bf16 each
        #pragma unroll
        for (int it = 0; it < 4; it++) {
            int t = tid + it * 256;
            int row = t >> 3, seg = t & 7;
            size_t gidx = (size_t)(bm + row) * K + c * 64 + seg * 8;
            uint32_t off = row * 128 + ((seg * 16) ^ ((row & 7) << 4));
            *(uint4*)(smem + SM_A_HI + off) = *(const uint4*)(Ah + gidx);
            *(uint4*)(smem + SM_A_LO + off) = *(const uint4*)(Al + gidx);
        }
        // stage B hi/lo: 64 rows x 64 bf16 each
        #pragma unroll
        for (int it = 0; it < 2; it++) {
            int t = tid + it * 256;
            int row = t >> 3, seg = t & 7;
            size_t gidx = (size_t)(bn + row) * K + c * 64 + seg * 8;
            uint32_t off = row * 128 + ((seg * 16) ^ ((row & 7) << 4));
            *(uint4*)(smem + SM_B_HI + off) = *(const uint4*)(Bh + gidx);
            *(uint4*)(smem + SM_B_LO + off) = *(const uint4*)(Bl + gidx);
        }
        __syncthreads();

        #pragma unroll
        for (int ks = 0; ks < 4; ks++) {
            const uint32_t ka = ks * 32 + aK;
            const uint32_t kb = ks * 32 + bK;
            uint32_t ah[2][4], al[2][4], bh2[2][4], bl2[2][4];
            #pragma unroll
            for (int mi = 0; mi < 2; mi++) {
                ldsm4(ah[mi], sb + SM_A_HI + aOff[mi] + (ka ^ aKey[mi]));
                ldsm4(al[mi], sb + SM_A_LO + aOff[mi] + (ka ^ aKey[mi]));
            }
            #pragma unroll
            for (int pi = 0; pi < 2; pi++) {
                ldsm4(bh2[pi], sb + SM_B_HI + bOff[pi] + (kb ^ bKey[pi]));
                ldsm4(bl2[pi], sb + SM_B_LO + bOff[pi] + (kb ^ bKey[pi]));
            }
            #pragma unroll
            for (int mi = 0; mi < 2; mi++)
                #pragma unroll
                for (int ni = 0; ni < 4; ni++) {
                    const uint32_t* bh_f = &bh2[ni >> 1][(ni & 1) * 2];
                    const uint32_t* bl_f = &bl2[ni >> 1][(ni & 1) * 2];
                    mma16816(acc[mi][ni], ah[mi], bh_f);
                    mma16816(acc[mi][ni], al[mi], bh_f);
                    mma16816(acc[mi][ni], ah[mi], bl_f);
                }
        }
    }

    // epilogue
    const int lane4 = lane >> 2;
    const int col2 = (lane & 3) * 2;
    #pragma unroll
    for (int mi = 0; mi < 2; mi++) {
        #pragma unroll
        for (int half = 0; half < 2; half++) {
            const int row = bm + m0 + mi * 16 + lane4 + half * 8;
            if (mode == 2) {
                size_t ob = (size_t)row * Cdim;
                #pragma unroll
                for (int ni = 0; ni < 4; ni++) {
                    int cg = bn + n0w + ni * 8 + col2;
                    float2 o;
                    o.x = acc[mi][ni][half * 2 + 0] + bias[cg];
                    o.y = acc[mi][ni][half * 2 + 1] + bias[cg + 1];
                    *(float2*)&o0[ob + cg] = o;
                }
            } else {
                const int b2 = row >> 14;
                const int rx = (row >> 7) & 127;
                const int ry = row & 127;
                const int xx = mode ? ry : rx;
                const int yy = mode ? rx : ry;
                #pragma unroll
                for (int ni = 0; ni < 4; ni++) {
                    int cg = bn + n0w + ni * 8 + col2;
                    int part = cg >> 8, hh = (cg >> 5) & 7, dd = cg & 31;
                    float* plane = (part == 0) ? o0 : (part == 1) ? o1 : o2;
                    float sc = (part == 0) ? SCALE : 1.0f;
                    size_t pb = ((((size_t)b2 * Hdim + hh) * Ndim + xx) * Ndim + yy) * Ddim + dd;
                    float2 o;
                    o.x = (acc[mi][ni][half * 2 + 0] + bias[part * 256 + dd * 8 + hh]) * sc;
                    o.y = (acc[mi][ni][half * 2 + 1] + bias[part * 256 + (dd + 1) * 8 + hh]) * sc;
                    *(float2*)&plane[pb] = o;
                }
            }
        }
    }
}

// ======================= attention (both passes, plane layout) =============
__global__ __launch_bounds__(128) void attn_kernel(
    const float* __restrict__ Qin, const float* __restrict__ Kin, const float* __restrict__ Vin,
    const float* __restrict__ Qout, const float* __restrict__ Kout, const float* __restrict__ Vout,
    const float* __restrict__ bias_in, const float* __restrict__ bias_out,
    float* __restrict__ Va)
{
    __shared__ __align__(16) float Ks[Ndim * Ddim];
    __shared__ __align__(16) float Vs[Ndim * Ddim];
    const int j = blockIdx.x;
    const int bh = blockIdx.y;
    const int pass = blockIdx.z;
    const int i = threadIdx.x;

    const float* Qp = pass ? Qout : Qin;
    const float* Kp = pass ? Kout : Kin;
    const float* Vp = pass ? Vout : Vin;
    const size_t base = ((size_t)bh * Ndim + j) * (Ndim * Ddim);

    {
        const float4* Kg = (const float4*)(Kp + base);
        const float4* Vg = (const float4*)(Vp + base);
        float4* Ks4 = (float4*)Ks;
        float4* Vs4 = (float4*)Vs;
        #pragma unroll
        for (int it = 0; it < 8; it++) {
            int t = i + it * 128;
            Ks4[t] = Kg[t];
            Vs4[t] = Vg[t];
        }
    }
    float q[Ddim];
    {
        const float* qp = pass ? (Qp + base + (size_t)i * Ddim)
                               : (Qp + ((size_t)bh * Ndim + i) * (Ndim * Ddim) + (size_t)j * Ddim);
        #pragma unroll
        for (int w = 0; w < 8; w++) {
            float4 t = ((const float4*)qp)[w];
            q[w * 4 + 0] = t.x; q[w * 4 + 1] = t.y; q[w * 4 + 2] = t.z; q[w * 4 + 3] = t.w;
        }
    }
    __syncthreads();

    const float* brow = (pass ? bias_out : bias_in) + (size_t)bh * Ndim * Ndim;

    float m = -1e30f, l = 0.f;
    float acc[Ddim];
    #pragma unroll
    for (int d = 0; d < Ddim; d++) acc[d] = 0.f;

    for (int k = 0; k < Ndim; k++) {
        float s = brow[k * Ndim + i];
        const float4* kr = (const float4*)&Ks[k * Ddim];
        #pragma unroll
        for (int w = 0; w < 8; w++) {
            float4 kv = kr[w];
            s += q[w * 4 + 0] * kv.x + q[w * 4 + 1] * kv.y + q[w * 4 + 2] * kv.z + q[w * 4 + 3] * kv.w;
        }
        if (s > m) {
            float corr = __expf(m - s);
            l *= corr;
            #pragma unroll
            for (int d = 0; d < Ddim; d++) acc[d] *= corr;
            m = s;
        }
        float p = __expf(s - m);
        l += p;
        const float4* vr = (const float4*)&Vs[k * Ddim];
        #pragma unroll
        for (int w = 0; w < 8; w++) {
            float4 vv = vr[w];
            acc[w * 4 + 0] += p * vv.x; acc[w * 4 + 1] += p * vv.y;
            acc[w * 4 + 2] += p * vv.z; acc[w * 4 + 3] += p * vv.w;
        }
    }

    const float inv = 1.0f / l;
    const int b2 = bh >> 3, h = bh & 7;
    float* o = Va + ((size_t)(b2 * Ndim + i) * Ndim + j) * (2 * Cdim) + pass * Hdim + h;
    #pragma unroll
    for (int d = 0; d < Ddim; d++) o[d * 16] = acc[d] * inv;
}

// ======================= va fp32 -> bf16 hi/lo split =======================
__global__ __launch_bounds__(256) void va_split(
    const float* __restrict__ va, __nv_bfloat16* __restrict__ vh, __nv_bfloat16* __restrict__ vl)
{
    size_t idx = (size_t)blockIdx.x * 256 + threadIdx.x;
    float x = va[idx];
    __nv_bfloat16 hi = __float2bfloat16(x);
    vh[idx] = hi;
    vl[idx] = __float2bfloat16(x - __bfloat162float(hi));
}

// ======================= launcher ==========================================
extern "C" void kernel_launch(void* const* d_in, const int* in_sizes, int n_in,
                              void* d_out, int out_size)
{
    (void)in_sizes; (void)n_in; (void)out_size;
    const float* e        = (const float*)d_in[0];
    const float* mask     = (const float*)d_in[1];
    const float* ln_g     = (const float*)d_in[2];
    const float* ln_b     = (const float*)d_in[3];
    const float* W_qkv_in = (const float*)d_in[4];
    const float* b_qkv_in = (const float*)d_in[5];
    const float* W_E_in   = (const float*)d_in[6];
    const float* b_E_in   = (const float*)d_in[7];
    const float* W_qkv_out= (const float*)d_in[8];
    const float* b_qkv_out= (const float*)d_in[9];
    const float* W_E_out  = (const float*)d_in[10];
    const float* b_E_out  = (const float*)d_in[11];
    const float* W_O      = (const float*)d_in[12];
    const float* b_O      = (const float*)d_in[13];

    __nv_bfloat16 *p_ahi, *p_alo, *p_winh, *p_winl, *p_wouth, *p_woutl, *p_woh, *p_wol, *p_vah, *p_val;
    float *p_Qin, *p_Kin, *p_Vin, *p_Qout, *p_Kout, *p_Vout, *p_bin, *p_bout, *p_va;
    cudaGetSymbolAddress((void**)&p_ahi,  g_ahi);
    cudaGetSymbolAddress((void**)&p_alo,  g_alo);
    cudaGetSymbolAddress((void**)&p_winh, g_win_hi);
    cudaGetSymbolAddress((void**)&p_winl, g_win_lo);
    cudaGetSymbolAddress((void**)&p_wouth, g_wout_hi);
    cudaGetSymbolAddress((void**)&p_woutl, g_wout_lo);
    cudaGetSymbolAddress((void**)&p_woh,  g_wo_hi);
    cudaGetSymbolAddress((void**)&p_wol,  g_wo_lo);
    cudaGetSymbolAddress((void**)&p_Qin,  g_Qin);
    cudaGetSymbolAddress((void**)&p_Kin,  g_Kin);
    cudaGetSymbolAddress((void**)&p_Vin,  g_Vin);
    cudaGetSymbolAddress((void**)&p_Qout, g_Qout);
    cudaGetSymbolAddress((void**)&p_Kout, g_Kout);
    cudaGetSymbolAddress((void**)&p_Vout, g_Vout);
    cudaGetSymbolAddress((void**)&p_bin,  g_bias_in);
    cudaGetSymbolAddress((void**)&p_bout, g_bias_out);
    cudaGetSymbolAddress((void**)&p_va,   g_va);
    cudaGetSymbolAddress((void**)&p_vah,  g_vahi);
    cudaGetSymbolAddress((void**)&p_val,  g_valo);

    cudaFuncSetAttribute(mma_gemm, cudaFuncAttributeMaxDynamicSharedMemorySize, SM_TOTAL);

    convert_w<<<QKVW, Cdim>>>(W_qkv_in,  p_winh,  p_winl,  Cdim, QKVW, 1);
    convert_w<<<QKVW, Cdim>>>(W_qkv_out, p_wouth, p_woutl, Cdim, QKVW, 1);
    convert_w<<<Cdim, 2 * Cdim>>>(W_O, p_woh, p_wol, 2 * Cdim, Cdim, 0);

    ln_kernel<<<ROWS, 256>>>(e, ln_g, ln_b, W_E_in, b_E_in, W_E_out, b_E_out,
                             mask, p_ahi, p_alo, p_bin, p_bout);

    mma_gemm<<<dim3(ROWS / 128, QKVW / 64), 256, SM_TOTAL>>>(
        p_ahi, p_alo, p_winh, p_winl, b_qkv_in, Cdim, 0, p_Qin, p_Kin, p_Vin);
    mma_gemm<<<dim3(ROWS / 128, QKVW / 64), 256, SM_TOTAL>>>(
        p_ahi, p_alo, p_wouth, p_woutl, b_qkv_out, Cdim, 1, p_Qout, p_Kout, p_Vout);

    attn_kernel<<<dim3(Ndim, Bdim * Hdim, 2), 128>>>(
        p_Qin, p_Kin, p_Vin, p_Qout, p_Kout, p_Vout, p_bin, p_bout, p_va);

    va_split<<<(ROWS * 2 * Cdim) / 256, 256>>>(p_va, p_vah, p_val);

    mma_gemm<<<dim3(ROWS / 128, Cdim / 64), 256, SM_TOTAL>>>(
        p_vah, p_val, p_woh, p_wol, b_O, 2 * Cdim, 2, (float*)d_out, nullptr, nullptr);
}

// round 7
// speedup vs baseline: 2.2956x; 1.2048x over previous
#include <cuda_runtime.h>
#include <cuda_bf16.h>
#include <cstdint>
#include <math.h>

#define Bdim 2
#define Ndim 128
#define Cdim 256
#define Hdim 8
#define Ddim 32
#define ROWS (Bdim*Ndim*Ndim)          // 32768
#define QKVW (3*Cdim)                   // 768
#define SCALE 0.17677669529663687f
#define LN_EPS 1e-5f
#define PLANE_ELEMS (Bdim*Hdim*Ndim*Ndim*Ddim)   // 8388608

// ======================= helpers ==========================================
__device__ __forceinline__ uint32_t smem_u32(const void* p) {
    uint32_t a;
    asm("{ .reg .u64 t; cvta.to.shared.u64 t, %1; cvt.u32.u64 %0, t; }" : "=r"(a) : "l"(p));
    return a;
}
__device__ __forceinline__ void ldsm4(uint32_t* r, uint32_t addr) {
    asm volatile("ldmatrix.sync.aligned.m8n8.x4.shared.b16 {%0,%1,%2,%3}, [%4];"
        : "=r"(r[0]), "=r"(r[1]), "=r"(r[2]), "=r"(r[3]) : "r"(addr));
}
__device__ __forceinline__ void mma16816(float* d, const uint32_t* a, const uint32_t* b) {
    asm volatile("mma.sync.aligned.m16n8k16.row.col.f32.bf16.bf16.f32 "
        "{%0,%1,%2,%3}, {%4,%5,%6,%7}, {%8,%9}, {%0,%1,%2,%3};"
        : "+f"(d[0]), "+f"(d[1]), "+f"(d[2]), "+f"(d[3])
        : "r"(a[0]), "r"(a[1]), "r"(a[2]), "r"(a[3]), "r"(b[0]), "r"(b[1]));
}

// ======================= scratch (device globals) ==========================
__device__ __align__(16) __nv_bfloat16 g_ahi[ROWS * Cdim];
__device__ __align__(16) __nv_bfloat16 g_alo[ROWS * Cdim];
__device__ __align__(16) __nv_bfloat16 g_win_hi[QKVW * Cdim];
__device__ __align__(16) __nv_bfloat16 g_win_lo[QKVW * Cdim];
__device__ __align__(16) __nv_bfloat16 g_wout_hi[QKVW * Cdim];
__device__ __align__(16) __nv_bfloat16 g_wout_lo[QKVW * Cdim];
__device__ __align__(16) __nv_bfloat16 g_wo_hi[Cdim * 2 * Cdim];
__device__ __align__(16) __nv_bfloat16 g_wo_lo[Cdim * 2 * Cdim];
__device__ __align__(16) float g_Qin[PLANE_ELEMS];
__device__ __align__(16) float g_Kin[PLANE_ELEMS];
__device__ __align__(16) float g_Vin[PLANE_ELEMS];
__device__ __align__(16) float g_Qout[PLANE_ELEMS];
__device__ __align__(16) float g_Kout[PLANE_ELEMS];
__device__ __align__(16) float g_Vout[PLANE_ELEMS];
__device__ __align__(16) float g_bias_in[Bdim * Hdim * Ndim * Ndim];
__device__ __align__(16) float g_bias_out[Bdim * Hdim * Ndim * Ndim];
__device__ __align__(16) __nv_bfloat16 g_vahi[ROWS * 2 * Cdim];
__device__ __align__(16) __nv_bfloat16 g_valo[ROWS * 2 * Cdim];

// ======================= weight convert (transpose + split) ================
// perm 0: Bmat[n][k] = W[k][n]
// perm 1: qkv head-permute on n: n = part*256 + h*32 + d -> orig n = part*256 + d*8 + h
// perm 2: W_O K-dim permute on k (c'' layout): k = pass*256 + h*32 + d -> orig k = d*16 + pass*8 + h
__global__ void convert_w(const float* __restrict__ W, __nv_bfloat16* __restrict__ th,
                          __nv_bfloat16* __restrict__ tl, int K, int Nout, int perm)
{
    const int n = blockIdx.x;
    const int k = threadIdx.x;
    int orig_n = n, orig_k = k;
    if (perm == 1) {
        int part = n >> 8, rem = n & 255;
        int h = rem >> 5, d = rem & 31;
        orig_n = part * 256 + d * 8 + h;
    } else if (perm == 2) {
        int part = k >> 8, rem = k & 255;
        int h = rem >> 5, d = rem & 31;
        orig_k = d * 16 + part * 8 + h;
    }
    float w = W[(size_t)orig_k * Nout + orig_n];
    __nv_bfloat16 hi = __float2bfloat16(w);
    th[(size_t)n * K + k] = hi;
    tl[(size_t)n * K + k] = __float2bfloat16(w - __bfloat162float(hi));
}

// ======================= LayerNorm + E projections + bf16 split ============
__global__ __launch_bounds__(256) void ln_kernel(
    const float* __restrict__ e,
    const float* __restrict__ ln_g, const float* __restrict__ ln_b,
    const float* __restrict__ WEin, const float* __restrict__ bEin,
    const float* __restrict__ WEout, const float* __restrict__ bEout,
    const float* __restrict__ mask,
    __nv_bfloat16* __restrict__ ahi, __nv_bfloat16* __restrict__ alo,
    float* __restrict__ bias_in, float* __restrict__ bias_out)
{
    const int row = blockIdx.x;
    const int t = threadIdx.x;
    const int lane = t & 31, warp = t >> 5;
    __shared__ float sred[8];
    __shared__ float sE[16];
    __shared__ float sy[256];
    __shared__ float sW[16][257];

    // stage E-weights transposed (coalesced global reads, conflict-free smem)
    #pragma unroll
    for (int it = 0; it < 8; it++) {
        int idx = it * 256 + t;      // 0..2047
        int c = idx >> 3, h = idx & 7;
        sW[h][c]     = WEin[idx];
        sW[8 + h][c] = WEout[idx];
    }

    float x = e[(size_t)row * Cdim + t];
    float s = x;
    #pragma unroll
    for (int o = 16; o; o >>= 1) s += __shfl_xor_sync(0xffffffffu, s, o);
    if (lane == 0) sred[warp] = s;
    __syncthreads();
    float mu = 0.f;
    #pragma unroll
    for (int w = 0; w < 8; w++) mu += sred[w];
    mu *= (1.0f / Cdim);
    __syncthreads();

    float d = x - mu;
    float v = d * d;
    #pragma unroll
    for (int o = 16; o; o >>= 1) v += __shfl_xor_sync(0xffffffffu, v, o);
    if (lane == 0) sred[warp] = v;
    __syncthreads();
    float var = 0.f;
    #pragma unroll
    for (int w = 0; w < 8; w++) var += sred[w];
    var *= (1.0f / Cdim);

    float y = d * rsqrtf(var + LN_EPS) * ln_g[t] + ln_b[t];
    __nv_bfloat16 hi = __float2bfloat16(y);
    ahi[(size_t)row * Cdim + t] = hi;
    alo[(size_t)row * Cdim + t] = __float2bfloat16(y - __bfloat162float(hi));
    sy[t] = y;
    __syncthreads();

    // E projections: warp w computes outputs 2w, 2w+1 (0..7 = in, 8..15 = out)
    {
        const int o0 = warp * 2, o1 = warp * 2 + 1;
        float a0 = 0.f, a1 = 0.f;
        #pragma unroll
        for (int q = 0; q < 8; q++) {
            int c = lane + q * 32;
            float yv = sy[c];
            a0 += yv * sW[o0][c];
            a1 += yv * sW[o1][c];
        }
        #pragma unroll
        for (int o = 16; o; o >>= 1) {
            a0 += __shfl_xor_sync(0xffffffffu, a0, o);
            a1 += __shfl_xor_sync(0xffffffffu, a1, o);
        }
        if (lane == 0) { sE[o0] = a0; sE[o1] = a1; }
    }
    __syncthreads();
    if (t < 16) {
        int h2 = t & 7;
        float tot = sE[t];
        float mk = mask[(size_t)row * 8 + h2];
        int b2 = row >> 14;
        int xx = (row >> 7) & 127;
        int yy = row & 127;
        if (t < 8)
            bias_in[((size_t)(b2 * Hdim + h2) * Ndim + yy) * Ndim + xx] = tot + bEin[h2] + mk;
        else
            bias_out[((size_t)(b2 * Hdim + h2) * Ndim + xx) * Ndim + yy] = tot + bEout[h2] + mk;
    }
}

// ======================= HMMA GEMM (split-bf16, fp32 acc) ==================
#define SM_A_HI 0
#define SM_A_LO 16384
#define SM_B_HI 32768
#define SM_B_LO 40960
#define SM_TOTAL 49152

__global__ __launch_bounds__(256) void mma_gemm(
    const __nv_bfloat16* __restrict__ Ah, const __nv_bfloat16* __restrict__ Al,
    const __nv_bfloat16* __restrict__ Bh, const __nv_bfloat16* __restrict__ Bl,
    const float* __restrict__ bias, int K, int mode,
    float* __restrict__ o0, float* __restrict__ o1, float* __restrict__ o2)
{
    extern __shared__ __align__(1024) char smem[];
    const uint32_t sb = smem_u32(smem);
    const int tid = threadIdx.x;
    const int wid = tid >> 5, lane = tid & 31;
    const int bm = blockIdx.x * 128;
    const int bn = blockIdx.y * 64;
    const int NCH = K >> 6;
    const int m0 = (wid & 3) * 32;
    const int n0w = (wid >> 2) * 32;

    float acc[2][4][4];
    #pragma unroll
    for (int a = 0; a < 2; a++)
        #pragma unroll
        for (int b = 0; b < 4; b++)
            #pragma unroll
            for (int cc = 0; cc < 4; cc++) acc[a][b][cc] = 0.f;

    uint32_t aOff[2], aKey[2], bOff[2], bKey[2];
    #pragma unroll
    for (int mi = 0; mi < 2; mi++) {
        int r = m0 + mi * 16 + (lane & 15);
        aOff[mi] = r * 128; aKey[mi] = (r & 7) << 4;
    }
    #pragma unroll
    for (int pi = 0; pi < 2; pi++) {
        int r = n0w + pi * 16 + ((lane >> 4) << 3) + (lane & 7);
        bOff[pi] = r * 128; bKey[pi] = (r & 7) << 4;
    }
    const uint32_t aK = (lane >> 4) * 16;
    const uint32_t bK = ((lane >> 3) & 1) * 16;

    for (int c = 0; c < NCH; c++) {
        if (c) __syncthreads();
        #pragma unroll
        for (int it = 0; it < 4; it++) {
            int t = tid + it * 256;
            int row = t >> 3, seg = t & 7;
            size_t gidx = (size_t)(bm + row) * K + c * 64 + seg * 8;
            uint32_t off = row * 128 + ((seg * 16) ^ ((row & 7) << 4));
            *(uint4*)(smem + SM_A_HI + off) = *(const uint4*)(Ah + gidx);
            *(uint4*)(smem + SM_A_LO + off) = *(const uint4*)(Al + gidx);
        }
        #pragma unroll
        for (int it = 0; it < 2; it++) {
            int t = tid + it * 256;
            int row = t >> 3, seg = t & 7;
            size_t gidx = (size_t)(bn + row) * K + c * 64 + seg * 8;
            uint32_t off = row * 128 + ((seg * 16) ^ ((row & 7) << 4));
            *(uint4*)(smem + SM_B_HI + off) = *(const uint4*)(Bh + gidx);
            *(uint4*)(smem + SM_B_LO + off) = *(const uint4*)(Bl + gidx);
        }
        __syncthreads();

        #pragma unroll
        for (int ks = 0; ks < 4; ks++) {
            const uint32_t ka = ks * 32 + aK;
            const uint32_t kb = ks * 32 + bK;
            uint32_t ah[2][4], al[2][4], bh2[2][4], bl2[2][4];
            #pragma unroll
            for (int mi = 0; mi < 2; mi++) {
                ldsm4(ah[mi], sb + SM_A_HI + aOff[mi] + (ka ^ aKey[mi]));
                ldsm4(al[mi], sb + SM_A_LO + aOff[mi] + (ka ^ aKey[mi]));
            }
            #pragma unroll
            for (int pi = 0; pi < 2; pi++) {
                ldsm4(bh2[pi], sb + SM_B_HI + bOff[pi] + (kb ^ bKey[pi]));
                ldsm4(bl2[pi], sb + SM_B_LO + bOff[pi] + (kb ^ bKey[pi]));
            }
            #pragma unroll
            for (int mi = 0; mi < 2; mi++)
                #pragma unroll
                for (int ni = 0; ni < 4; ni++) {
                    const uint32_t* bh_f = &bh2[ni >> 1][(ni & 1) * 2];
                    const uint32_t* bl_f = &bl2[ni >> 1][(ni & 1) * 2];
                    mma16816(acc[mi][ni], ah[mi], bh_f);
                    mma16816(acc[mi][ni], al[mi], bh_f);
                    mma16816(acc[mi][ni], ah[mi], bl_f);
                }
        }
    }

    const int lane4 = lane >> 2;
    const int col2 = (lane & 3) * 2;
    #pragma unroll
    for (int mi = 0; mi < 2; mi++) {
        #pragma unroll
        for (int half = 0; half < 2; half++) {
            const int row = bm + m0 + mi * 16 + lane4 + half * 8;
            if (mode == 2) {
                // row = (b, j, i) -> out row (b, i, j)
                const int b2 = row >> 14;
                const int j2 = (row >> 7) & 127;
                const int i2 = row & 127;
                size_t ob = ((size_t)((b2 * Ndim + i2) * Ndim + j2)) * Cdim;
                #pragma unroll
                for (int ni = 0; ni < 4; ni++) {
                    int cg = bn + n0w + ni * 8 + col2;
                    float2 o;
                    o.x = acc[mi][ni][half * 2 + 0] + bias[cg];
                    o.y = acc[mi][ni][half * 2 + 1] + bias[cg + 1];
                    *(float2*)&o0[ob + cg] = o;
                }
            } else {
                const int b2 = row >> 14;
                const int rx = (row >> 7) & 127;
                const int ry = row & 127;
                const int xx = mode ? ry : rx;
                const int yy = mode ? rx : ry;
                #pragma unroll
                for (int ni = 0; ni < 4; ni++) {
                    int cg = bn + n0w + ni * 8 + col2;
                    int part = cg >> 8, hh = (cg >> 5) & 7, dd = cg & 31;
                    float* plane = (part == 0) ? o0 : (part == 1) ? o1 : o2;
                    float sc = (part == 0) ? SCALE : 1.0f;
                    int px = xx, py = yy;
                    if (mode == 0 && part == 0) { px = yy; py = xx; }  // Q-in transposed
                    size_t pb = ((((size_t)b2 * Hdim + hh) * Ndim + px) * Ndim + py) * Ddim + dd;
                    float2 o;
                    o.x = (acc[mi][ni][half * 2 + 0] + bias[part * 256 + dd * 8 + hh]) * sc;
                    o.y = (acc[mi][ni][half * 2 + 1] + bias[part * 256 + (dd + 1) * 8 + hh]) * sc;
                    *(float2*)&plane[pb] = o;
                }
            }
        }
    }
}

// ======================= attention (both passes, plane layout) =============
// va layout: row R = (b*128 + j)*128 + i, col c'' = (pass*8+h)*32 + d ; bf16 hi/lo direct
__global__ __launch_bounds__(128) void attn_kernel(
    const float* __restrict__ Qin, const float* __restrict__ Kin, const float* __restrict__ Vin,
    const float* __restrict__ Qout, const float* __restrict__ Kout, const float* __restrict__ Vout,
    const float* __restrict__ bias_in, const float* __restrict__ bias_out,
    __nv_bfloat16* __restrict__ vah, __nv_bfloat16* __restrict__ val)
{
    __shared__ __align__(16) float KV[2 * Ndim * Ddim];   // Ks | Vs ; reused as staging
    float* Ks = KV;
    float* Vs = KV + Ndim * Ddim;
    const int j = blockIdx.x;
    const int bh = blockIdx.y;
    const int pass = blockIdx.z;
    const int i = threadIdx.x;

    const float* Qp = pass ? Qout : Qin;
    const float* Kp = pass ? Kout : Kin;
    const float* Vp = pass ? Vout : Vin;
    const size_t base = ((size_t)bh * Ndim + j) * (Ndim * Ddim);

    {
        const float4* Kg = (const float4*)(Kp + base);
        const float4* Vg = (const float4*)(Vp + base);
        float4* Ks4 = (float4*)Ks;
        float4* Vs4 = (float4*)Vs;
        #pragma unroll
        for (int it = 0; it < 8; it++) {
            int t = i + it * 128;
            Ks4[t] = Kg[t];
            Vs4[t] = Vg[t];
        }
    }
    float q[Ddim];
    {
        const float* qp = Qp + base + (size_t)i * Ddim;   // both passes contiguous
        #pragma unroll
        for (int w = 0; w < 8; w++) {
            float4 t = ((const float4*)qp)[w];
            q[w * 4 + 0] = t.x; q[w * 4 + 1] = t.y; q[w * 4 + 2] = t.z; q[w * 4 + 3] = t.w;
        }
    }
    __syncthreads();

    const float* brow = (pass ? bias_out : bias_in) + (size_t)bh * Ndim * Ndim;

    float m = -1e30f, l = 0.f;
    float acc[Ddim];
    #pragma unroll
    for (int d = 0; d < Ddim; d++) acc[d] = 0.f;

    for (int k = 0; k < Ndim; k++) {
        float s = brow[k * Ndim + i];
        const float4* kr = (const float4*)&Ks[k * Ddim];
        #pragma unroll
        for (int w = 0; w < 8; w++) {
            float4 kv = kr[w];
            s += q[w * 4 + 0] * kv.x + q[w * 4 + 1] * kv.y + q[w * 4 + 2] * kv.z + q[w * 4 + 3] * kv.w;
        }
        if (s > m) {
            float corr = __expf(m - s);
            l *= corr;
            #pragma unroll
            for (int d = 0; d < Ddim; d++) acc[d] *= corr;
            m = s;
        }
        float p = __expf(s - m);
        l += p;
        const float4* vr = (const float4*)&Vs[k * Ddim];
        #pragma unroll
        for (int w = 0; w < 8; w++) {
            float4 vv = vr[w];
            acc[w * 4 + 0] += p * vv.x; acc[w * 4 + 1] += p * vv.y;
            acc[w * 4 + 2] += p * vv.z; acc[w * 4 + 3] += p * vv.w;
        }
    }

    const float inv = 1.0f / l;
    __syncthreads();                 // everyone done with Ks/Vs
    float* st = KV;                  // [128][33] staging
    #pragma unroll
    for (int d = 0; d < Ddim; d++) st[i * 33 + d] = acc[d] * inv;
    __syncthreads();

    const int wid = i >> 5, lane = i & 31;
    const int b2 = bh >> 3, h = bh & 7;
    const size_t R0 = (size_t)(b2 * Ndim + j) * Ndim;
    const int cb = (pass * 8 + h) * 32;
    #pragma unroll
    for (int rr = wid; rr < Ndim; rr += 4) {
        float v = st[rr * 33 + lane];
        __nv_bfloat16 hi = __float2bfloat16(v);
        __nv_bfloat16 lo = __float2bfloat16(v - __bfloat162float(hi));
        size_t idx = (R0 + rr) * (2 * Cdim) + cb + lane;
        vah[idx] = hi;
        val[idx] = lo;
    }
}

// ======================= launcher ==========================================
extern "C" void kernel_launch(void* const* d_in, const int* in_sizes, int n_in,
                              void* d_out, int out_size)
{
    (void)in_sizes; (void)n_in; (void)out_size;
    const float* e        = (const float*)d_in[0];
    const float* mask     = (const float*)d_in[1];
    const float* ln_g     = (const float*)d_in[2];
    const float* ln_b     = (const float*)d_in[3];
    const float* W_qkv_in = (const float*)d_in[4];
    const float* b_qkv_in = (const float*)d_in[5];
    const float* W_E_in   = (const float*)d_in[6];
    const float* b_E_in   = (const float*)d_in[7];
    const float* W_qkv_out= (const float*)d_in[8];
    const float* b_qkv_out= (const float*)d_in[9];
    const float* W_E_out  = (const float*)d_in[10];
    const float* b_E_out  = (const float*)d_in[11];
    const float* W_O      = (const float*)d_in[12];
    const float* b_O      = (const float*)d_in[13];

    __nv_bfloat16 *p_ahi, *p_alo, *p_winh, *p_winl, *p_wouth, *p_woutl, *p_woh, *p_wol, *p_vah, *p_val;
    float *p_Qin, *p_Kin, *p_Vin, *p_Qout, *p_Kout, *p_Vout, *p_bin, *p_bout;
    cudaGetSymbolAddress((void**)&p_ahi,  g_ahi);
    cudaGetSymbolAddress((void**)&p_alo,  g_alo);
    cudaGetSymbolAddress((void**)&p_winh, g_win_hi);
    cudaGetSymbolAddress((void**)&p_winl, g_win_lo);
    cudaGetSymbolAddress((void**)&p_wouth, g_wout_hi);
    cudaGetSymbolAddress((void**)&p_woutl, g_wout_lo);
    cudaGetSymbolAddress((void**)&p_woh,  g_wo_hi);
    cudaGetSymbolAddress((void**)&p_wol,  g_wo_lo);
    cudaGetSymbolAddress((void**)&p_Qin,  g_Qin);
    cudaGetSymbolAddress((void**)&p_Kin,  g_Kin);
    cudaGetSymbolAddress((void**)&p_Vin,  g_Vin);
    cudaGetSymbolAddress((void**)&p_Qout, g_Qout);
    cudaGetSymbolAddress((void**)&p_Kout, g_Kout);
    cudaGetSymbolAddress((void**)&p_Vout, g_Vout);
    cudaGetSymbolAddress((void**)&p_bin,  g_bias_in);
    cudaGetSymbolAddress((void**)&p_bout, g_bias_out);
    cudaGetSymbolAddress((void**)&p_vah,  g_vahi);
    cudaGetSymbolAddress((void**)&p_val,  g_valo);

    cudaFuncSetAttribute(mma_gemm, cudaFuncAttributeMaxDynamicSharedMemorySize, SM_TOTAL);

    convert_w<<<QKVW, Cdim>>>(W_qkv_in,  p_winh,  p_winl,  Cdim, QKVW, 1);
    convert_w<<<QKVW, Cdim>>>(W_qkv_out, p_wouth, p_woutl, Cdim, QKVW, 1);
    convert_w<<<Cdim, 2 * Cdim>>>(W_O, p_woh, p_wol, 2 * Cdim, Cdim, 2);

    ln_kernel<<<ROWS, 256>>>(e, ln_g, ln_b, W_E_in, b_E_in, W_E_out, b_E_out,
                             mask, p_ahi, p_alo, p_bin, p_bout);

    mma_gemm<<<dim3(ROWS / 128, QKVW / 64), 256, SM_TOTAL>>>(
        p_ahi, p_alo, p_winh, p_winl, b_qkv_in, Cdim, 0, p_Qin, p_Kin, p_Vin);
    mma_gemm<<<dim3(ROWS / 128, QKVW / 64), 256, SM_TOTAL>>>(
        p_ahi, p_alo, p_wouth, p_woutl, b_qkv_out, Cdim, 1, p_Qout, p_Kout, p_Vout);

    attn_kernel<<<dim3(Ndim, Bdim * Hdim, 2), 128>>>(
        p_Qin, p_Kin, p_Vin, p_Qout, p_Kout, p_Vout, p_bin, p_bout, p_vah, p_val);

    mma_gemm<<<dim3(ROWS / 128, Cdim / 64), 256, SM_TOTAL>>>(
        p_vah, p_val, p_woh, p_wol, b_O, 2 * Cdim, 2, (float*)d_out, nullptr, nullptr);
}

// round 9
// speedup vs baseline: 3.5124x; 1.5300x over previous
#include <cuda_runtime.h>
#include <cuda_bf16.h>
#include <cstdint>
#include <math.h>

#define Bdim 2
#define Ndim 128
#define Cdim 256
#define Hdim 8
#define Ddim 32
#define ROWS (Bdim*Ndim*Ndim)          // 32768
#define QKVW (3*Cdim)                   // 768
#define SCALE 0.17677669529663687f
#define LN_EPS 1e-5f
#define PLANE_ELEMS (Bdim*Hdim*Ndim*Ndim*Ddim)   // 8388608

// ======================= helpers ==========================================
__device__ __forceinline__ uint32_t smem_u32(const void* p) {
    uint32_t a;
    asm("{ .reg .u64 t; cvta.to.shared.u64 t, %1; cvt.u32.u64 %0, t; }" : "=r"(a) : "l"(p));
    return a;
}
__device__ __forceinline__ void ldsm4(uint32_t* r, uint32_t addr) {
    asm volatile("ldmatrix.sync.aligned.m8n8.x4.shared.b16 {%0,%1,%2,%3}, [%4];"
        : "=r"(r[0]), "=r"(r[1]), "=r"(r[2]), "=r"(r[3]) : "r"(addr));
}
__device__ __forceinline__ void ldsm4t(uint32_t* r, uint32_t addr) {
    asm volatile("ldmatrix.sync.aligned.m8n8.x4.trans.shared.b16 {%0,%1,%2,%3}, [%4];"
        : "=r"(r[0]), "=r"(r[1]), "=r"(r[2]), "=r"(r[3]) : "r"(addr));
}
__device__ __forceinline__ void mma16816(float* d, const uint32_t* a, const uint32_t* b) {
    asm volatile("mma.sync.aligned.m16n8k16.row.col.f32.bf16.bf16.f32 "
        "{%0,%1,%2,%3}, {%4,%5,%6,%7}, {%8,%9}, {%0,%1,%2,%3};"
        : "+f"(d[0]), "+f"(d[1]), "+f"(d[2]), "+f"(d[3])
        : "r"(a[0]), "r"(a[1]), "r"(a[2]), "r"(a[3]), "r"(b[0]), "r"(b[1]));
}
// split (x,y) into bf16x2 hi + lo pair
__device__ __forceinline__ void split2(float x, float y, uint32_t& hi, uint32_t& lo) {
    __nv_bfloat162 h = __floats2bfloat162_rn(x, y);
    float hx = __bfloat162float(h.x), hy = __bfloat162float(h.y);
    __nv_bfloat162 l = __floats2bfloat162_rn(x - hx, y - hy);
    hi = *(uint32_t*)&h;
    lo = *(uint32_t*)&l;
}

// ======================= scratch (device globals) ==========================
__device__ __align__(16) __nv_bfloat16 g_ahi[ROWS * Cdim];
__device__ __align__(16) __nv_bfloat16 g_alo[ROWS * Cdim];
__device__ __align__(16) __nv_bfloat16 g_win_hi[QKVW * Cdim];
__device__ __align__(16) __nv_bfloat16 g_win_lo[QKVW * Cdim];
__device__ __align__(16) __nv_bfloat16 g_wout_hi[QKVW * Cdim];
__device__ __align__(16) __nv_bfloat16 g_wout_lo[QKVW * Cdim];
__device__ __align__(16) __nv_bfloat16 g_wo_hi[Cdim * 2 * Cdim];
__device__ __align__(16) __nv_bfloat16 g_wo_lo[Cdim * 2 * Cdim];
__device__ __align__(16) float g_wet[16 * Cdim];          // transposed E weights [o][c]
__device__ __align__(16) float g_Qin[PLANE_ELEMS];
__device__ __align__(16) float g_Kin[PLANE_ELEMS];
__device__ __align__(16) float g_Vin[PLANE_ELEMS];
__device__ __align__(16) float g_Qout[PLANE_ELEMS];
__device__ __align__(16) float g_Kout[PLANE_ELEMS];
__device__ __align__(16) float g_Vout[PLANE_ELEMS];
__device__ __align__(16) float g_bias_in[Bdim * Hdim * Ndim * Ndim];   // [b,h,i,k]
__device__ __align__(16) float g_bias_out[Bdim * Hdim * Ndim * Ndim];  // [b,h,i,k]
__device__ __align__(16) __nv_bfloat16 g_vahi[ROWS * 2 * Cdim];
__device__ __align__(16) __nv_bfloat16 g_valo[ROWS * 2 * Cdim];

// ======================= weight converts ===================================
__global__ void convert_w(const float* __restrict__ W, __nv_bfloat16* __restrict__ th,
                          __nv_bfloat16* __restrict__ tl, int K, int Nout, int perm)
{
    const int n = blockIdx.x;
    const int k = threadIdx.x;
    int orig_n = n, orig_k = k;
    if (perm == 1) {
        int part = n >> 8, rem = n & 255;
        int h = rem >> 5, d = rem & 31;
        orig_n = part * 256 + d * 8 + h;
    } else if (perm == 2) {
        int part = k >> 8, rem = k & 255;
        int h = rem >> 5, d = rem & 31;
        orig_k = d * 16 + part * 8 + h;
    }
    float w = W[(size_t)orig_k * Nout + orig_n];
    __nv_bfloat16 hi = __float2bfloat16(w);
    th[(size_t)n * K + k] = hi;
    tl[(size_t)n * K + k] = __float2bfloat16(w - __bfloat162float(hi));
}

__global__ void convert_wet(const float* __restrict__ WEin, const float* __restrict__ WEout,
                            float* __restrict__ wet)
{
    const int o = blockIdx.x;      // 0..15
    const int c = threadIdx.x;     // 0..255
    wet[o * Cdim + c] = (o < 8) ? WEin[c * 8 + o] : WEout[c * 8 + (o - 8)];
}

// ======================= LayerNorm + E projections + bf16 split ============
__global__ __launch_bounds__(256) void ln_kernel(
    const float* __restrict__ e,
    const float* __restrict__ ln_g, const float* __restrict__ ln_b,
    const float* __restrict__ wet,
    const float* __restrict__ bEin, const float* __restrict__ bEout,
    const float* __restrict__ mask,
    __nv_bfloat16* __restrict__ ahi, __nv_bfloat16* __restrict__ alo,
    float* __restrict__ bias_in, float* __restrict__ bias_out)
{
    const int row = blockIdx.x;
    const int t = threadIdx.x;
    const int lane = t & 31, warp = t >> 5;
    __shared__ float sred[8];
    __shared__ float sE[16];
    __shared__ float sy[256];

    float x = e[(size_t)row * Cdim + t];
    float s = x;
    #pragma unroll
    for (int o = 16; o; o >>= 1) s += __shfl_xor_sync(0xffffffffu, s, o);
    if (lane == 0) sred[warp] = s;
    __syncthreads();
    float mu = 0.f;
    #pragma unroll
    for (int w = 0; w < 8; w++) mu += sred[w];
    mu *= (1.0f / Cdim);
    __syncthreads();

    float d = x - mu;
    float v = d * d;
    #pragma unroll
    for (int o = 16; o; o >>= 1) v += __shfl_xor_sync(0xffffffffu, v, o);
    if (lane == 0) sred[warp] = v;
    __syncthreads();
    float var = 0.f;
    #pragma unroll
    for (int w = 0; w < 8; w++) var += sred[w];
    var *= (1.0f / Cdim);

    float y = d * rsqrtf(var + LN_EPS) * ln_g[t] + ln_b[t];
    __nv_bfloat16 hi = __float2bfloat16(y);
    ahi[(size_t)row * Cdim + t] = hi;
    alo[(size_t)row * Cdim + t] = __float2bfloat16(y - __bfloat162float(hi));
    sy[t] = y;
    __syncthreads();

    // E projections: warp w computes outputs 2w, 2w+1 (0..7 = in, 8..15 = out)
    {
        const int o0 = warp * 2, o1 = warp * 2 + 1;
        const float* w0 = wet + o0 * Cdim;
        const float* w1 = wet + o1 * Cdim;
        float a0 = 0.f, a1 = 0.f;
        #pragma unroll
        for (int q = 0; q < 8; q++) {
            int c = lane + q * 32;
            float yv = sy[c];
            a0 += yv * w0[c];
            a1 += yv * w1[c];
        }
        #pragma unroll
        for (int o = 16; o; o >>= 1) {
            a0 += __shfl_xor_sync(0xffffffffu, a0, o);
            a1 += __shfl_xor_sync(0xffffffffu, a1, o);
        }
        if (lane == 0) { sE[o0] = a0; sE[o1] = a1; }
    }
    __syncthreads();
    if (t < 16) {
        int h2 = t & 7;
        float tot = sE[t];
        float mk = mask[(size_t)row * 8 + h2];
        int b2 = row >> 14;
        int xx = (row >> 7) & 127;   // i coordinate of this e-row
        int yy = row & 127;          // j coordinate
        if (t < 8)
            // in-pass: used at (query i=xx, key k=yy) -> [b,h,i,k] = [b,h,xx,yy]
            bias_in[((size_t)(b2 * Hdim + h2) * Ndim + xx) * Ndim + yy] = tot + bEin[h2] + mk;
        else
            // out-pass: used at (key k=xx, query i=yy) -> [b,h,i,k] = [b,h,yy,xx]
            bias_out[((size_t)(b2 * Hdim + h2) * Ndim + yy) * Ndim + xx] = tot + bEout[h2] + mk;
    }
}

// ======================= HMMA GEMM (split-bf16, fp32 acc) ==================
#define SM_A_HI 0
#define SM_A_LO 16384
#define SM_B_HI 32768
#define SM_B_LO 40960
#define SM_TOTAL 49152

__global__ __launch_bounds__(256) void mma_gemm(
    const __nv_bfloat16* __restrict__ Ah, const __nv_bfloat16* __restrict__ Al,
    const __nv_bfloat16* __restrict__ Bh, const __nv_bfloat16* __restrict__ Bl,
    const float* __restrict__ bias, int K, int mode,
    float* __restrict__ o0, float* __restrict__ o1, float* __restrict__ o2)
{
    extern __shared__ __align__(1024) char smem[];
    const uint32_t sb = smem_u32(smem);
    const int tid = threadIdx.x;
    const int wid = tid >> 5, lane = tid & 31;
    const int bm = blockIdx.x * 128;
    const int bn = blockIdx.y * 64;
    const int NCH = K >> 6;
    const int m0 = (wid & 3) * 32;
    const int n0w = (wid >> 2) * 32;

    float acc[2][4][4];
    #pragma unroll
    for (int a = 0; a < 2; a++)
        #pragma unroll
        for (int b = 0; b < 4; b++)
            #pragma unroll
            for (int cc = 0; cc < 4; cc++) acc[a][b][cc] = 0.f;

    uint32_t aOff[2], aKey[2], bOff[2], bKey[2];
    #pragma unroll
    for (int mi = 0; mi < 2; mi++) {
        int r = m0 + mi * 16 + (lane & 15);
        aOff[mi] = r * 128; aKey[mi] = (r & 7) << 4;
    }
    #pragma unroll
    for (int pi = 0; pi < 2; pi++) {
        int r = n0w + pi * 16 + ((lane >> 4) << 3) + (lane & 7);
        bOff[pi] = r * 128; bKey[pi] = (r & 7) << 4;
    }
    const uint32_t aK = (lane >> 4) * 16;
    const uint32_t bK = ((lane >> 3) & 1) * 16;

    for (int c = 0; c < NCH; c++) {
        if (c) __syncthreads();
        #pragma unroll
        for (int it = 0; it < 4; it++) {
            int t = tid + it * 256;
            int row = t >> 3, seg = t & 7;
            size_t gidx = (size_t)(bm + row) * K + c * 64 + seg * 8;
            uint32_t off = row * 128 + ((seg * 16) ^ ((row & 7) << 4));
            *(uint4*)(smem + SM_A_HI + off) = *(const uint4*)(Ah + gidx);
            *(uint4*)(smem + SM_A_LO + off) = *(const uint4*)(Al + gidx);
        }
        #pragma unroll
        for (int it = 0; it < 2; it++) {
            int t = tid + it * 256;
            int row = t >> 3, seg = t & 7;
            size_t gidx = (size_t)(bn + row) * K + c * 64 + seg * 8;
            uint32_t off = row * 128 + ((seg * 16) ^ ((row & 7) << 4));
            *(uint4*)(smem + SM_B_HI + off) = *(const uint4*)(Bh + gidx);
            *(uint4*)(smem + SM_B_LO + off) = *(const uint4*)(Bl + gidx);
        }
        __syncthreads();

        #pragma unroll
        for (int ks = 0; ks < 4; ks++) {
            const uint32_t ka = ks * 32 + aK;
            const uint32_t kb = ks * 32 + bK;
            uint32_t ah[2][4], al[2][4], bh2[2][4], bl2[2][4];
            #pragma unroll
            for (int mi = 0; mi < 2; mi++) {
                ldsm4(ah[mi], sb + SM_A_HI + aOff[mi] + (ka ^ aKey[mi]));
                ldsm4(al[mi], sb + SM_A_LO + aOff[mi] + (ka ^ aKey[mi]));
            }
            #pragma unroll
            for (int pi = 0; pi < 2; pi++) {
                ldsm4(bh2[pi], sb + SM_B_HI + bOff[pi] + (kb ^ bKey[pi]));
                ldsm4(bl2[pi], sb + SM_B_LO + bOff[pi] + (kb ^ bKey[pi]));
            }
            #pragma unroll
            for (int mi = 0; mi < 2; mi++)
                #pragma unroll
                for (int ni = 0; ni < 4; ni++) {
                    const uint32_t* bh_f = &bh2[ni >> 1][(ni & 1) * 2];
                    const uint32_t* bl_f = &bl2[ni >> 1][(ni & 1) * 2];
                    mma16816(acc[mi][ni], ah[mi], bh_f);
                    mma16816(acc[mi][ni], al[mi], bh_f);
                    mma16816(acc[mi][ni], ah[mi], bl_f);
                }
        }
    }

    const int lane4 = lane >> 2;
    const int col2 = (lane & 3) * 2;
    #pragma unroll
    for (int mi = 0; mi < 2; mi++) {
        #pragma unroll
        for (int half = 0; half < 2; half++) {
            const int row = bm + m0 + mi * 16 + lane4 + half * 8;
            if (mode == 2) {
                const int b2 = row >> 14;
                const int j2 = (row >> 7) & 127;
                const int i2 = row & 127;
                size_t ob = ((size_t)((b2 * Ndim + i2) * Ndim + j2)) * Cdim;
                #pragma unroll
                for (int ni = 0; ni < 4; ni++) {
                    int cg = bn + n0w + ni * 8 + col2;
                    float2 o;
                    o.x = acc[mi][ni][half * 2 + 0] + bias[cg];
                    o.y = acc[mi][ni][half * 2 + 1] + bias[cg + 1];
                    *(float2*)&o0[ob + cg] = o;
                }
            } else {
                const int b2 = row >> 14;
                const int rx = (row >> 7) & 127;
                const int ry = row & 127;
                const int xx = mode ? ry : rx;
                const int yy = mode ? rx : ry;
                #pragma unroll
                for (int ni = 0; ni < 4; ni++) {
                    int cg = bn + n0w + ni * 8 + col2;
                    int part = cg >> 8, hh = (cg >> 5) & 7, dd = cg & 31;
                    float* plane = (part == 0) ? o0 : (part == 1) ? o1 : o2;
                    float sc = (part == 0) ? SCALE : 1.0f;
                    int px = xx, py = yy;
                    if (mode == 0 && part == 0) { px = yy; py = xx; }  // Q-in transposed
                    size_t pb = ((((size_t)b2 * Hdim + hh) * Ndim + px) * Ndim + py) * Ddim + dd;
                    float2 o;
                    o.x = (acc[mi][ni][half * 2 + 0] + bias[part * 256 + dd * 8 + hh]) * sc;
                    o.y = (acc[mi][ni][half * 2 + 1] + bias[part * 256 + (dd + 1) * 8 + hh]) * sc;
                    *(float2*)&plane[pb] = o;
                }
            }
        }
    }
}

// ======================= HMMA attention ====================================
// grid: x=j (128), y=bh (16), z=pass (2); 256 threads / 8 warps, 16 query rows each
// smem per tensor: 128 rows * 80B pitch; hi at base, lo at +10240
#define AT_Q 0
#define AT_K 20480
#define AT_V 40960
#define AT_LO 10240
#define AT_SMEM 61440

__global__ __launch_bounds__(256, 2) void attn_mma(
    const float* __restrict__ Qin, const float* __restrict__ Kin, const float* __restrict__ Vin,
    const float* __restrict__ Qout, const float* __restrict__ Kout, const float* __restrict__ Vout,
    const float* __restrict__ bias_in, const float* __restrict__ bias_out,
    __nv_bfloat16* __restrict__ vah, __nv_bfloat16* __restrict__ val)
{
    extern __shared__ __align__(128) char sm[];
    const uint32_t sb = smem_u32(sm);
    const int j = blockIdx.x;
    const int bh = blockIdx.y;
    const int pass = blockIdx.z;
    const int tid = threadIdx.x;
    const int wid = tid >> 5, lane = tid & 31;

    const float* Qp = pass ? Qout : Qin;
    const float* Kp = pass ? Kout : Kin;
    const float* Vp = pass ? Vout : Vin;
    const size_t pbase = ((size_t)(bh * Ndim + j)) * (Ndim * Ddim);

    // ---- stage Q/K/V -> bf16 hi/lo smem (80B pitch rows) ----
    {
        const int r = tid & 127;
        const int half = tid >> 7;          // 0/1 -> d-cols 0-15 / 16-31
        const float* srcs[3] = {Qp + pbase, Kp + pbase, Vp + pbase};
        const uint32_t dsto[3] = {AT_Q, AT_K, AT_V};
        #pragma unroll
        for (int t = 0; t < 3; t++) {
            const float4* s4 = (const float4*)(srcs[t] + r * 32 + half * 16);
            float4 v0 = s4[0], v1 = s4[1], v2 = s4[2], v3 = s4[3];
            uint32_t hi[8], lo[8];
            split2(v0.x, v0.y, hi[0], lo[0]); split2(v0.z, v0.w, hi[1], lo[1]);
            split2(v1.x, v1.y, hi[2], lo[2]); split2(v1.z, v1.w, hi[3], lo[3]);
            split2(v2.x, v2.y, hi[4], lo[4]); split2(v2.z, v2.w, hi[5], lo[5]);
            split2(v3.x, v3.y, hi[6], lo[6]); split2(v3.z, v3.w, hi[7], lo[7]);
            char* d = sm + dsto[t] + r * 80 + half * 32;
            *(uint4*)d = make_uint4(hi[0], hi[1], hi[2], hi[3]);
            *(uint4*)(d + 16) = make_uint4(hi[4], hi[5], hi[6], hi[7]);
            *(uint4*)(d + AT_LO) = make_uint4(lo[0], lo[1], lo[2], lo[3]);
            *(uint4*)(d + AT_LO + 16) = make_uint4(lo[4], lo[5], lo[6], lo[7]);
        }
    }
    __syncthreads();

    const int m0 = wid * 16;

    // ---- S = Q K^T (3-term hi/lo) ----
    float accS[16][4];
    #pragma unroll
    for (int n = 0; n < 16; n++)
        #pragma unroll
        for (int c = 0; c < 4; c++) accS[n][c] = 0.f;

    #pragma unroll
    for (int kc = 0; kc < 2; kc++) {
        uint32_t qaddr = sb + AT_Q + (m0 + (lane & 15)) * 80 + kc * 32 + (lane >> 4) * 16;
        uint32_t qh[4], ql[4];
        ldsm4(qh, qaddr);
        ldsm4(ql, qaddr + AT_LO);
        #pragma unroll
        for (int pi = 0; pi < 8; pi++) {
            uint32_t kaddr = sb + AT_K + (pi * 16 + ((lane >> 4) << 3) + (lane & 7)) * 80
                           + kc * 32 + ((lane >> 3) & 1) * 16;
            uint32_t kh[4], kl[4];
            ldsm4(kh, kaddr);
            ldsm4(kl, kaddr + AT_LO);
            #pragma unroll
            for (int t = 0; t < 2; t++) {
                mma16816(accS[2 * pi + t], qh, &kh[t * 2]);
                mma16816(accS[2 * pi + t], ql, &kh[t * 2]);
                mma16816(accS[2 * pi + t], qh, &kl[t * 2]);
            }
        }
    }

    // ---- bias + softmax (fp32, in fragments) ----
    {
        const float* bb = (pass ? bias_out : bias_in) + (size_t)bh * Ndim * Ndim;
        const int r0 = m0 + (lane >> 2);
        const int r1 = r0 + 8;
        const int c0 = (lane & 3) * 2;
        #pragma unroll
        for (int ni = 0; ni < 16; ni++) {
            float2 b0 = *(const float2*)(bb + r0 * Ndim + ni * 8 + c0);
            float2 b1 = *(const float2*)(bb + r1 * Ndim + ni * 8 + c0);
            accS[ni][0] += b0.x; accS[ni][1] += b0.y;
            accS[ni][2] += b1.x; accS[ni][3] += b1.y;
        }
        float mx0 = -1e30f, mx1 = -1e30f;
        #pragma unroll
        for (int ni = 0; ni < 16; ni++) {
            mx0 = fmaxf(mx0, fmaxf(accS[ni][0], accS[ni][1]));
            mx1 = fmaxf(mx1, fmaxf(accS[ni][2], accS[ni][3]));
        }
        mx0 = fmaxf(mx0, __shfl_xor_sync(0xffffffffu, mx0, 1));
        mx0 = fmaxf(mx0, __shfl_xor_sync(0xffffffffu, mx0, 2));
        mx1 = fmaxf(mx1, __shfl_xor_sync(0xffffffffu, mx1, 1));
        mx1 = fmaxf(mx1, __shfl_xor_sync(0xffffffffu, mx1, 2));
        float s0 = 0.f, s1 = 0.f;
        #pragma unroll
        for (int ni = 0; ni < 16; ni++) {
            accS[ni][0] = __expf(accS[ni][0] - mx0);
            accS[ni][1] = __expf(accS[ni][1] - mx0);
            accS[ni][2] = __expf(accS[ni][2] - mx1);
            accS[ni][3] = __expf(accS[ni][3] - mx1);
            s0 += accS[ni][0] + accS[ni][1];
            s1 += accS[ni][2] + accS[ni][3];
        }
        s0 += __shfl_xor_sync(0xffffffffu, s0, 1);
        s0 += __shfl_xor_sync(0xffffffffu, s0, 2);
        s1 += __shfl_xor_sync(0xffffffffu, s1, 1);
        s1 += __shfl_xor_sync(0xffffffffu, s1, 2);

        // ---- O = P V (3-term hi/lo, P packed from fragments) ----
        float accO[4][4];
        #pragma unroll
        for (int n = 0; n < 4; n++)
            #pragma unroll
            for (int c = 0; c < 4; c++) accO[n][c] = 0.f;

        #pragma unroll
        for (int kc = 0; kc < 8; kc++) {
            uint32_t ph[4], pl[4];
            split2(accS[2 * kc][0], accS[2 * kc][1], ph[0], pl[0]);
            split2(accS[2 * kc][2], accS[2 * kc][3], ph[1], pl[1]);
            split2(accS[2 * kc + 1][0], accS[2 * kc + 1][1], ph[2], pl[2]);
            split2(accS[2 * kc + 1][2], accS[2 * kc + 1][3], ph[3], pl[3]);
            #pragma unroll
            for (int dh = 0; dh < 2; dh++) {
                uint32_t vaddr = sb + AT_V + (kc * 16 + ((lane >> 3) & 1) * 8 + (lane & 7)) * 80
                               + dh * 32 + (lane >> 4) * 16;
                uint32_t vh4[4], vl4[4];
                ldsm4t(vh4, vaddr);
                ldsm4t(vl4, vaddr + AT_LO);
                #pragma unroll
                for (int t = 0; t < 2; t++) {
                    mma16816(accO[dh * 2 + t], ph, &vh4[t * 2]);
                    mma16816(accO[dh * 2 + t], pl, &vh4[t * 2]);
                    mma16816(accO[dh * 2 + t], ph, &vl4[t * 2]);
                }
            }
        }

        // ---- normalize + write va (bf16 hi/lo) ----
        const float inv0 = 1.0f / s0;
        const float inv1 = 1.0f / s1;
        const int b2 = bh >> 3, h = bh & 7;
        const size_t R0 = (size_t)(b2 * Ndim + j) * Ndim;
        const int cb = (pass * 8 + h) * 32;
        #pragma unroll
        for (int nd = 0; nd < 4; nd++) {
            uint32_t hi, lo;
            split2(accO[nd][0] * inv0, accO[nd][1] * inv0, hi, lo);
            size_t idx = (R0 + r0) * (2 * Cdim) + cb + nd * 8 + c0;
            *(uint32_t*)&vah[idx] = hi;
            *(uint32_t*)&val[idx] = lo;
            split2(accO[nd][2] * inv1, accO[nd][3] * inv1, hi, lo);
            idx = (R0 + r1) * (2 * Cdim) + cb + nd * 8 + c0;
            *(uint32_t*)&vah[idx] = hi;
            *(uint32_t*)&val[idx] = lo;
        }
    }
}

// ======================= launcher ==========================================
extern "C" void kernel_launch(void* const* d_in, const int* in_sizes, int n_in,
                              void* d_out, int out_size)
{
    (void)in_sizes; (void)n_in; (void)out_size;
    const float* e        = (const float*)d_in[0];
    const float* mask     = (const float*)d_in[1];
    const float* ln_g     = (const float*)d_in[2];
    const float* ln_b     = (const float*)d_in[3];
    const float* W_qkv_in = (const float*)d_in[4];
    const float* b_qkv_in = (const float*)d_in[5];
    const float* W_E_in   = (const float*)d_in[6];
    const float* b_E_in   = (const float*)d_in[7];
    const float* W_qkv_out= (const float*)d_in[8];
    const float* b_qkv_out= (const float*)d_in[9];
    const float* W_E_out  = (const float*)d_in[10];
    const float* b_E_out  = (const float*)d_in[11];
    const float* W_O      = (const float*)d_in[12];
    const float* b_O      = (const float*)d_in[13];

    __nv_bfloat16 *p_ahi, *p_alo, *p_winh, *p_winl, *p_wouth, *p_woutl, *p_woh, *p_wol, *p_vah, *p_val;
    float *p_Qin, *p_Kin, *p_Vin, *p_Qout, *p_Kout, *p_Vout, *p_bin, *p_bout, *p_wet;
    cudaGetSymbolAddress((void**)&p_ahi,  g_ahi);
    cudaGetSymbolAddress((void**)&p_alo,  g_alo);
    cudaGetSymbolAddress((void**)&p_winh, g_win_hi);
    cudaGetSymbolAddress((void**)&p_winl, g_win_lo);
    cudaGetSymbolAddress((void**)&p_wouth, g_wout_hi);
    cudaGetSymbolAddress((void**)&p_woutl, g_wout_lo);
    cudaGetSymbolAddress((void**)&p_woh,  g_wo_hi);
    cudaGetSymbolAddress((void**)&p_wol,  g_wo_lo);
    cudaGetSymbolAddress((void**)&p_wet,  g_wet);
    cudaGetSymbolAddress((void**)&p_Qin,  g_Qin);
    cudaGetSymbolAddress((void**)&p_Kin,  g_Kin);
    cudaGetSymbolAddress((void**)&p_Vin,  g_Vin);
    cudaGetSymbolAddress((void**)&p_Qout, g_Qout);
    cudaGetSymbolAddress((void**)&p_Kout, g_Kout);
    cudaGetSymbolAddress((void**)&p_Vout, g_Vout);
    cudaGetSymbolAddress((void**)&p_bin,  g_bias_in);
    cudaGetSymbolAddress((void**)&p_bout, g_bias_out);
    cudaGetSymbolAddress((void**)&p_vah,  g_vahi);
    cudaGetSymbolAddress((void**)&p_val,  g_valo);

    cudaFuncSetAttribute(mma_gemm, cudaFuncAttributeMaxDynamicSharedMemorySize, SM_TOTAL);
    cudaFuncSetAttribute(attn_mma, cudaFuncAttributeMaxDynamicSharedMemorySize, AT_SMEM);

    convert_w<<<QKVW, Cdim>>>(W_qkv_in,  p_winh,  p_winl,  Cdim, QKVW, 1);
    convert_w<<<QKVW, Cdim>>>(W_qkv_out, p_wouth, p_woutl, Cdim, QKVW, 1);
    convert_w<<<Cdim, 2 * Cdim>>>(W_O, p_woh, p_wol, 2 * Cdim, Cdim, 2);
    convert_wet<<<16, Cdim>>>(W_E_in, W_E_out, p_wet);

    ln_kernel<<<ROWS, 256>>>(e, ln_g, ln_b, p_wet, b_E_in, b_E_out,
                             mask, p_ahi, p_alo, p_bin, p_bout);

    mma_gemm<<<dim3(ROWS / 128, QKVW / 64), 256, SM_TOTAL>>>(
        p_ahi, p_alo, p_winh, p_winl, b_qkv_in, Cdim, 0, p_Qin, p_Kin, p_Vin);
    mma_gemm<<<dim3(ROWS / 128, QKVW / 64), 256, SM_TOTAL>>>(
        p_ahi, p_alo, p_wouth, p_woutl, b_qkv_out, Cdim, 1, p_Qout, p_Kout, p_Vout);

    attn_mma<<<dim3(Ndim, Bdim * Hdim, 2), 256, AT_SMEM>>>(
        p_Qin, p_Kin, p_Vin, p_Qout, p_Kout, p_Vout, p_bin, p_bout, p_vah, p_val);

    mma_gemm<<<dim3(ROWS / 128, Cdim / 64), 256, SM_TOTAL>>>(
        p_vah, p_val, p_woh, p_wol, b_O, 2 * Cdim, 2, (float*)d_out, nullptr, nullptr);
}

// round 10
// speedup vs baseline: 3.6530x; 1.0400x over previous
#include <cuda_runtime.h>
#include <cuda_bf16.h>
#include <cstdint>
#include <math.h>

#define Bdim 2
#define Ndim 128
#define Cdim 256
#define Hdim 8
#define Ddim 32
#define ROWS (Bdim*Ndim*Ndim)          // 32768
#define QKVW (3*Cdim)                   // 768
#define NEXT (QKVW + 64)                // 832 = qkv + E tile
#define SCALE 0.17677669529663687f
#define LN_EPS 1e-5f
#define PLANE_ELEMS (Bdim*Hdim*Ndim*Ndim*Ddim)   // 8388608

// ======================= helpers ==========================================
__device__ __forceinline__ uint32_t smem_u32(const void* p) {
    uint32_t a;
    asm("{ .reg .u64 t; cvta.to.shared.u64 t, %1; cvt.u32.u64 %0, t; }" : "=r"(a) : "l"(p));
    return a;
}
__device__ __forceinline__ void ldsm4(uint32_t* r, uint32_t addr) {
    asm volatile("ldmatrix.sync.aligned.m8n8.x4.shared.b16 {%0,%1,%2,%3}, [%4];"
        : "=r"(r[0]), "=r"(r[1]), "=r"(r[2]), "=r"(r[3]) : "r"(addr));
}
__device__ __forceinline__ void ldsm4t(uint32_t* r, uint32_t addr) {
    asm volatile("ldmatrix.sync.aligned.m8n8.x4.trans.shared.b16 {%0,%1,%2,%3}, [%4];"
        : "=r"(r[0]), "=r"(r[1]), "=r"(r[2]), "=r"(r[3]) : "r"(addr));
}
__device__ __forceinline__ void mma16816(float* d, const uint32_t* a, const uint32_t* b) {
    asm volatile("mma.sync.aligned.m16n8k16.row.col.f32.bf16.bf16.f32 "
        "{%0,%1,%2,%3}, {%4,%5,%6,%7}, {%8,%9}, {%0,%1,%2,%3};"
        : "+f"(d[0]), "+f"(d[1]), "+f"(d[2]), "+f"(d[3])
        : "r"(a[0]), "r"(a[1]), "r"(a[2]), "r"(a[3]), "r"(b[0]), "r"(b[1]));
}
__device__ __forceinline__ void split2(float x, float y, uint32_t& hi, uint32_t& lo) {
    __nv_bfloat162 h = __floats2bfloat162_rn(x, y);
    float hx = __bfloat162float(h.x), hy = __bfloat162float(h.y);
    __nv_bfloat162 l = __floats2bfloat162_rn(x - hx, y - hy);
    hi = *(uint32_t*)&h;
    lo = *(uint32_t*)&l;
}

// ======================= scratch (device globals) ==========================
__device__ __align__(16) __nv_bfloat16 g_ahi[ROWS * Cdim];
__device__ __align__(16) __nv_bfloat16 g_alo[ROWS * Cdim];
__device__ __align__(16) __nv_bfloat16 g_win_hi[NEXT * Cdim];
__device__ __align__(16) __nv_bfloat16 g_win_lo[NEXT * Cdim];
__device__ __align__(16) __nv_bfloat16 g_wout_hi[NEXT * Cdim];
__device__ __align__(16) __nv_bfloat16 g_wout_lo[NEXT * Cdim];
__device__ __align__(16) __nv_bfloat16 g_wo_hi[Cdim * 2 * Cdim];
__device__ __align__(16) __nv_bfloat16 g_wo_lo[Cdim * 2 * Cdim];
__device__ __align__(16) __nv_bfloat16 g_Qinh[PLANE_ELEMS],  g_Qinl[PLANE_ELEMS];
__device__ __align__(16) __nv_bfloat16 g_Kinh[PLANE_ELEMS],  g_Kinl[PLANE_ELEMS];
__device__ __align__(16) __nv_bfloat16 g_Vinh[PLANE_ELEMS],  g_Vinl[PLANE_ELEMS];
__device__ __align__(16) __nv_bfloat16 g_Qouth[PLANE_ELEMS], g_Qoutl[PLANE_ELEMS];
__device__ __align__(16) __nv_bfloat16 g_Kouth[PLANE_ELEMS], g_Koutl[PLANE_ELEMS];
__device__ __align__(16) __nv_bfloat16 g_Vouth[PLANE_ELEMS], g_Voutl[PLANE_ELEMS];
__device__ __align__(16) float g_bias_in[Bdim * Hdim * Ndim * Ndim];   // [b,h,i,k]
__device__ __align__(16) float g_bias_out[Bdim * Hdim * Ndim * Ndim];  // [b,h,i,k]
__device__ __align__(16) __nv_bfloat16 g_vahi[ROWS * 2 * Cdim];
__device__ __align__(16) __nv_bfloat16 g_valo[ROWS * 2 * Cdim];

// ======================= weight converts ===================================
// qkv weights (permuted) + E weights appended as cols 768..775, 776..831 zero
__global__ void convert_wqkv(const float* __restrict__ W, const float* __restrict__ WE,
                             __nv_bfloat16* __restrict__ th, __nv_bfloat16* __restrict__ tl)
{
    const int n = blockIdx.x;      // 0..831
    const int k = threadIdx.x;     // 0..255
    float w;
    if (n < QKVW) {
        int part = n >> 8, rem = n & 255;
        int h = rem >> 5, d = rem & 31;
        w = W[(size_t)k * QKVW + part * 256 + d * 8 + h];
    } else if (n < QKVW + 8) {
        w = WE[k * 8 + (n - QKVW)];
    } else {
        w = 0.f;
    }
    __nv_bfloat16 hi = __float2bfloat16(w);
    th[(size_t)n * Cdim + k] = hi;
    tl[(size_t)n * Cdim + k] = __float2bfloat16(w - __bfloat162float(hi));
}

// W_O with K-permute (c'' layout): k = pass*256 + h*32 + d -> orig k = d*16 + pass*8 + h
__global__ void convert_wo(const float* __restrict__ W, __nv_bfloat16* __restrict__ th,
                           __nv_bfloat16* __restrict__ tl)
{
    const int n = blockIdx.x;      // 0..255
    const int k = threadIdx.x;     // 0..511
    int part = k >> 8, rem = k & 255;
    int h = rem >> 5, d = rem & 31;
    int orig_k = d * 16 + part * 8 + h;
    float w = W[(size_t)orig_k * Cdim + n];
    __nv_bfloat16 hi = __float2bfloat16(w);
    th[(size_t)n * 2 * Cdim + k] = hi;
    tl[(size_t)n * 2 * Cdim + k] = __float2bfloat16(w - __bfloat162float(hi));
}

// ======================= LayerNorm + bf16 split ============================
__global__ __launch_bounds__(256) void ln_kernel(
    const float* __restrict__ e,
    const float* __restrict__ ln_g, const float* __restrict__ ln_b,
    __nv_bfloat16* __restrict__ ahi, __nv_bfloat16* __restrict__ alo)
{
    const int row = blockIdx.x;
    const int t = threadIdx.x;
    const int lane = t & 31, warp = t >> 5;
    __shared__ float sred[8];

    float x = e[(size_t)row * Cdim + t];
    float s = x;
    #pragma unroll
    for (int o = 16; o; o >>= 1) s += __shfl_xor_sync(0xffffffffu, s, o);
    if (lane == 0) sred[warp] = s;
    __syncthreads();
    float mu = 0.f;
    #pragma unroll
    for (int w = 0; w < 8; w++) mu += sred[w];
    mu *= (1.0f / Cdim);
    __syncthreads();

    float d = x - mu;
    float v = d * d;
    #pragma unroll
    for (int o = 16; o; o >>= 1) v += __shfl_xor_sync(0xffffffffu, v, o);
    if (lane == 0) sred[warp] = v;
    __syncthreads();
    float var = 0.f;
    #pragma unroll
    for (int w = 0; w < 8; w++) var += sred[w];
    var *= (1.0f / Cdim);

    float y = d * rsqrtf(var + LN_EPS) * ln_g[t] + ln_b[t];
    __nv_bfloat16 hi = __float2bfloat16(y);
    ahi[(size_t)row * Cdim + t] = hi;
    alo[(size_t)row * Cdim + t] = __float2bfloat16(y - __bfloat162float(hi));
}

// ======================= HMMA GEMM (split-bf16, fp32 acc) ==================
// mode 0/1: qkv+E GEMM (N=832). Planes written bf16 hi/lo; E tile -> bias plane.
// mode 2: out-GEMM (N=256), fp32 + bias -> d_out with row un-permute.
#define SM_A_HI 0
#define SM_A_LO 16384
#define SM_B_HI 32768
#define SM_B_LO 40960
#define SM_TOTAL 49152

__global__ __launch_bounds__(256) void mma_gemm(
    const __nv_bfloat16* __restrict__ Ah, const __nv_bfloat16* __restrict__ Al,
    const __nv_bfloat16* __restrict__ Bh, const __nv_bfloat16* __restrict__ Bl,
    const float* __restrict__ bias,       // qkv bias (768) or out bias (256)
    const float* __restrict__ bE,         // E bias (8)  [mode 0/1]
    const float* __restrict__ mask,       // [ROWS][8]   [mode 0/1]
    int K, int mode,
    __nv_bfloat16* __restrict__ o0h, __nv_bfloat16* __restrict__ o0l,
    __nv_bfloat16* __restrict__ o1h, __nv_bfloat16* __restrict__ o1l,
    __nv_bfloat16* __restrict__ o2h, __nv_bfloat16* __restrict__ o2l,
    float* __restrict__ bp,               // bias plane  [mode 0/1]
    float* __restrict__ outf)             // fp32 out    [mode 2]
{
    extern __shared__ __align__(1024) char smem[];
    const uint32_t sb = smem_u32(smem);
    const int tid = threadIdx.x;
    const int wid = tid >> 5, lane = tid & 31;
    const int bm = blockIdx.x * 128;
    const int bn = blockIdx.y * 64;
    const int NCH = K >> 6;
    const int m0 = (wid & 3) * 32;
    const int n0w = (wid >> 2) * 32;

    float acc[2][4][4];
    #pragma unroll
    for (int a = 0; a < 2; a++)
        #pragma unroll
        for (int b = 0; b < 4; b++)
            #pragma unroll
            for (int cc = 0; cc < 4; cc++) acc[a][b][cc] = 0.f;

    uint32_t aOff[2], aKey[2], bOff[2], bKey[2];
    #pragma unroll
    for (int mi = 0; mi < 2; mi++) {
        int r = m0 + mi * 16 + (lane & 15);
        aOff[mi] = r * 128; aKey[mi] = (r & 7) << 4;
    }
    #pragma unroll
    for (int pi = 0; pi < 2; pi++) {
        int r = n0w + pi * 16 + ((lane >> 4) << 3) + (lane & 7);
        bOff[pi] = r * 128; bKey[pi] = (r & 7) << 4;
    }
    const uint32_t aK = (lane >> 4) * 16;
    const uint32_t bK = ((lane >> 3) & 1) * 16;

    for (int c = 0; c < NCH; c++) {
        if (c) __syncthreads();
        #pragma unroll
        for (int it = 0; it < 4; it++) {
            int t = tid + it * 256;
            int row = t >> 3, seg = t & 7;
            size_t gidx = (size_t)(bm + row) * K + c * 64 + seg * 8;
            uint32_t off = row * 128 + ((seg * 16) ^ ((row & 7) << 4));
            *(uint4*)(smem + SM_A_HI + off) = *(const uint4*)(Ah + gidx);
            *(uint4*)(smem + SM_A_LO + off) = *(const uint4*)(Al + gidx);
        }
        #pragma unroll
        for (int it = 0; it < 2; it++) {
            int t = tid + it * 256;
            int row = t >> 3, seg = t & 7;
            size_t gidx = (size_t)(bn + row) * K + c * 64 + seg * 8;
            uint32_t off = row * 128 + ((seg * 16) ^ ((row & 7) << 4));
            *(uint4*)(smem + SM_B_HI + off) = *(const uint4*)(Bh + gidx);
            *(uint4*)(smem + SM_B_LO + off) = *(const uint4*)(Bl + gidx);
        }
        __syncthreads();

        #pragma unroll
        for (int ks = 0; ks < 4; ks++) {
            const uint32_t ka = ks * 32 + aK;
            const uint32_t kb = ks * 32 + bK;
            uint32_t ah[2][4], al[2][4], bh2[2][4], bl2[2][4];
            #pragma unroll
            for (int mi = 0; mi < 2; mi++) {
                ldsm4(ah[mi], sb + SM_A_HI + aOff[mi] + (ka ^ aKey[mi]));
                ldsm4(al[mi], sb + SM_A_LO + aOff[mi] + (ka ^ aKey[mi]));
            }
            #pragma unroll
            for (int pi = 0; pi < 2; pi++) {
                ldsm4(bh2[pi], sb + SM_B_HI + bOff[pi] + (kb ^ bKey[pi]));
                ldsm4(bl2[pi], sb + SM_B_LO + bOff[pi] + (kb ^ bKey[pi]));
            }
            #pragma unroll
            for (int mi = 0; mi < 2; mi++)
                #pragma unroll
                for (int ni = 0; ni < 4; ni++) {
                    const uint32_t* bh_f = &bh2[ni >> 1][(ni & 1) * 2];
                    const uint32_t* bl_f = &bl2[ni >> 1][(ni & 1) * 2];
                    mma16816(acc[mi][ni], ah[mi], bh_f);
                    mma16816(acc[mi][ni], al[mi], bh_f);
                    mma16816(acc[mi][ni], ah[mi], bl_f);
                }
        }
    }

    const int lane4 = lane >> 2;
    const int col2 = (lane & 3) * 2;
    #pragma unroll
    for (int mi = 0; mi < 2; mi++) {
        #pragma unroll
        for (int half = 0; half < 2; half++) {
            const int row = bm + m0 + mi * 16 + lane4 + half * 8;
            if (mode == 2) {
                const int b2 = row >> 14;
                const int j2 = (row >> 7) & 127;
                const int i2 = row & 127;
                size_t ob = ((size_t)((b2 * Ndim + i2) * Ndim + j2)) * Cdim;
                #pragma unroll
                for (int ni = 0; ni < 4; ni++) {
                    int cg = bn + n0w + ni * 8 + col2;
                    float2 o;
                    o.x = acc[mi][ni][half * 2 + 0] + bias[cg];
                    o.y = acc[mi][ni][half * 2 + 1] + bias[cg + 1];
                    *(float2*)&outf[ob + cg] = o;
                }
            } else {
                const int b2 = row >> 14;
                const int rx = (row >> 7) & 127;
                const int ry = row & 127;
                const int xx = mode ? ry : rx;
                const int yy = mode ? rx : ry;
                #pragma unroll
                for (int ni = 0; ni < 4; ni++) {
                    int cg = bn + n0w + ni * 8 + col2;
                    if (cg < QKVW) {
                        int part = cg >> 8, hh = (cg >> 5) & 7, dd = cg & 31;
                        __nv_bfloat16 *ph, *pl;
                        if (part == 0)      { ph = o0h; pl = o0l; }
                        else if (part == 1) { ph = o1h; pl = o1l; }
                        else                { ph = o2h; pl = o2l; }
                        float sc = (part == 0) ? SCALE : 1.0f;
                        int px = xx, py = yy;
                        if (mode == 0 && part == 0) { px = yy; py = xx; }  // Q-in transposed
                        size_t pb = ((((size_t)b2 * Hdim + hh) * Ndim + px) * Ndim + py) * Ddim + dd;
                        float ox = (acc[mi][ni][half * 2 + 0] + bias[part * 256 + dd * 8 + hh]) * sc;
                        float oy = (acc[mi][ni][half * 2 + 1] + bias[part * 256 + (dd + 1) * 8 + hh]) * sc;
                        uint32_t hi, lo;
                        split2(ox, oy, hi, lo);
                        *(uint32_t*)&ph[pb] = hi;
                        *(uint32_t*)&pl[pb] = lo;
                    } else if (cg < QKVW + 8) {
                        int h = cg - QKVW;   // even
                        float v0 = acc[mi][ni][half * 2 + 0] + bE[h]     + mask[(size_t)row * 8 + h];
                        float v1 = acc[mi][ni][half * 2 + 1] + bE[h + 1] + mask[(size_t)row * 8 + h + 1];
                        if (mode == 0) {
                            // bias_in[b,h,i=rx,k=ry]
                            bp[(((size_t)(b2 * Hdim + h))     * Ndim + rx) * Ndim + ry] = v0;
                            bp[(((size_t)(b2 * Hdim + h + 1)) * Ndim + rx) * Ndim + ry] = v1;
                        } else {
                            // bias_out[b,h,i=ry,k=rx]
                            bp[(((size_t)(b2 * Hdim + h))     * Ndim + ry) * Ndim + rx] = v0;
                            bp[(((size_t)(b2 * Hdim + h + 1)) * Ndim + ry) * Ndim + rx] = v1;
                        }
                    }
                }
            }
        }
    }
}

// ======================= HMMA attention ====================================
// grid: x=j (128), y=bh (16), z=pass (2); 256 threads / 8 warps, 16 query rows each
#define AT_Q 0
#define AT_K 20480
#define AT_V 40960
#define AT_LO 10240
#define AT_SMEM 61440

__global__ __launch_bounds__(256, 2) void attn_mma(
    const __nv_bfloat16* __restrict__ Qinh, const __nv_bfloat16* __restrict__ Qinl,
    const __nv_bfloat16* __restrict__ Kinh, const __nv_bfloat16* __restrict__ Kinl,
    const __nv_bfloat16* __restrict__ Vinh, const __nv_bfloat16* __restrict__ Vinl,
    const __nv_bfloat16* __restrict__ Qouth, const __nv_bfloat16* __restrict__ Qoutl,
    const __nv_bfloat16* __restrict__ Kouth, const __nv_bfloat16* __restrict__ Koutl,
    const __nv_bfloat16* __restrict__ Vouth, const __nv_bfloat16* __restrict__ Voutl,
    const float* __restrict__ bias_in, const float* __restrict__ bias_out,
    __nv_bfloat16* __restrict__ vah, __nv_bfloat16* __restrict__ val)
{
    extern __shared__ __align__(128) char sm[];
    const uint32_t sb = smem_u32(sm);
    const int j = blockIdx.x;
    const int bh = blockIdx.y;
    const int pass = blockIdx.z;
    const int tid = threadIdx.x;
    const int wid = tid >> 5, lane = tid & 31;

    const size_t pbase = ((size_t)(bh * Ndim + j)) * (Ndim * Ddim);

    // ---- stage bf16 hi/lo planes -> smem (pure copy) ----
    {
        const int r = tid & 127;
        const int half = tid >> 7;
        const __nv_bfloat16* srcs[6];
        if (pass) {
            srcs[0] = Qouth; srcs[1] = Qoutl; srcs[2] = Kouth;
            srcs[3] = Koutl; srcs[4] = Vouth; srcs[5] = Voutl;
        } else {
            srcs[0] = Qinh; srcs[1] = Qinl; srcs[2] = Kinh;
            srcs[3] = Kinl; srcs[4] = Vinh; srcs[5] = Vinl;
        }
        const uint32_t dsto[6] = {AT_Q, AT_Q + AT_LO, AT_K, AT_K + AT_LO, AT_V, AT_V + AT_LO};
        const int eoff = r * 32 + half * 16;
        #pragma unroll
        for (int t = 0; t < 6; t++) {
            const uint4* s4 = (const uint4*)(srcs[t] + pbase + eoff);
            char* d = sm + dsto[t] + r * 80 + half * 32;
            *(uint4*)d = s4[0];
            *(uint4*)(d + 16) = s4[1];
        }
    }
    __syncthreads();

    const int m0 = wid * 16;

    // ---- S = Q K^T (3-term hi/lo) ----
    float accS[16][4];
    #pragma unroll
    for (int n = 0; n < 16; n++)
        #pragma unroll
        for (int c = 0; c < 4; c++) accS[n][c] = 0.f;

    #pragma unroll
    for (int kc = 0; kc < 2; kc++) {
        uint32_t qaddr = sb + AT_Q + (m0 + (lane & 15)) * 80 + kc * 32 + (lane >> 4) * 16;
        uint32_t qh[4], ql[4];
        ldsm4(qh, qaddr);
        ldsm4(ql, qaddr + AT_LO);
        #pragma unroll
        for (int pi = 0; pi < 8; pi++) {
            uint32_t kaddr = sb + AT_K + (pi * 16 + ((lane >> 4) << 3) + (lane & 7)) * 80
                           + kc * 32 + ((lane >> 3) & 1) * 16;
            uint32_t kh[4], kl[4];
            ldsm4(kh, kaddr);
            ldsm4(kl, kaddr + AT_LO);
            #pragma unroll
            for (int t = 0; t < 2; t++) {
                mma16816(accS[2 * pi + t], qh, &kh[t * 2]);
                mma16816(accS[2 * pi + t], ql, &kh[t * 2]);
                mma16816(accS[2 * pi + t], qh, &kl[t * 2]);
            }
        }
    }

    // ---- bias + softmax ----
    {
        const float* bb = (pass ? bias_out : bias_in) + (size_t)bh * Ndim * Ndim;
        const int r0 = m0 + (lane >> 2);
        const int r1 = r0 + 8;
        const int c0 = (lane & 3) * 2;
        #pragma unroll
        for (int ni = 0; ni < 16; ni++) {
            float2 b0 = *(const float2*)(bb + r0 * Ndim + ni * 8 + c0);
            float2 b1 = *(const float2*)(bb + r1 * Ndim + ni * 8 + c0);
            accS[ni][0] += b0.x; accS[ni][1] += b0.y;
            accS[ni][2] += b1.x; accS[ni][3] += b1.y;
        }
        float mx0 = -1e30f, mx1 = -1e30f;
        #pragma unroll
        for (int ni = 0; ni < 16; ni++) {
            mx0 = fmaxf(mx0, fmaxf(accS[ni][0], accS[ni][1]));
            mx1 = fmaxf(mx1, fmaxf(accS[ni][2], accS[ni][3]));
        }
        mx0 = fmaxf(mx0, __shfl_xor_sync(0xffffffffu, mx0, 1));
        mx0 = fmaxf(mx0, __shfl_xor_sync(0xffffffffu, mx0, 2));
        mx1 = fmaxf(mx1, __shfl_xor_sync(0xffffffffu, mx1, 1));
        mx1 = fmaxf(mx1, __shfl_xor_sync(0xffffffffu, mx1, 2));
        float s0 = 0.f, s1 = 0.f;
        #pragma unroll
        for (int ni = 0; ni < 16; ni++) {
            accS[ni][0] = __expf(accS[ni][0] - mx0);
            accS[ni][1] = __expf(accS[ni][1] - mx0);
            accS[ni][2] = __expf(accS[ni][2] - mx1);
            accS[ni][3] = __expf(accS[ni][3] - mx1);
            s0 += accS[ni][0] + accS[ni][1];
            s1 += accS[ni][2] + accS[ni][3];
        }
        s0 += __shfl_xor_sync(0xffffffffu, s0, 1);
        s0 += __shfl_xor_sync(0xffffffffu, s0, 2);
        s1 += __shfl_xor_sync(0xffffffffu, s1, 1);
        s1 += __shfl_xor_sync(0xffffffffu, s1, 2);

        // ---- O = P V (3-term hi/lo) ----
        float accO[4][4];
        #pragma unroll
        for (int n = 0; n < 4; n++)
            #pragma unroll
            for (int c = 0; c < 4; c++) accO[n][c] = 0.f;

        #pragma unroll
        for (int kc = 0; kc < 8; kc++) {
            uint32_t ph[4], pl[4];
            split2(accS[2 * kc][0], accS[2 * kc][1], ph[0], pl[0]);
            split2(accS[2 * kc][2], accS[2 * kc][3], ph[1], pl[1]);
            split2(accS[2 * kc + 1][0], accS[2 * kc + 1][1], ph[2], pl[2]);
            split2(accS[2 * kc + 1][2], accS[2 * kc + 1][3], ph[3], pl[3]);
            #pragma unroll
            for (int dh = 0; dh < 2; dh++) {
                uint32_t vaddr = sb + AT_V + (kc * 16 + ((lane >> 3) & 1) * 8 + (lane & 7)) * 80
                               + dh * 32 + (lane >> 4) * 16;
                uint32_t vh4[4], vl4[4];
                ldsm4t(vh4, vaddr);
                ldsm4t(vl4, vaddr + AT_LO);
                #pragma unroll
                for (int t = 0; t < 2; t++) {
                    mma16816(accO[dh * 2 + t], ph, &vh4[t * 2]);
                    mma16816(accO[dh * 2 + t], pl, &vh4[t * 2]);
                    mma16816(accO[dh * 2 + t], ph, &vl4[t * 2]);
                }
            }
        }

        // ---- normalize + write va (bf16 hi/lo) ----
        const float inv0 = 1.0f / s0;
        const float inv1 = 1.0f / s1;
        const int b2 = bh >> 3, h = bh & 7;
        const size_t R0 = (size_t)(b2 * Ndim + j) * Ndim;
        const int cb = (pass * 8 + h) * 32;
        #pragma unroll
        for (int nd = 0; nd < 4; nd++) {
            uint32_t hi, lo;
            split2(accO[nd][0] * inv0, accO[nd][1] * inv0, hi, lo);
            size_t idx = (R0 + r0) * (2 * Cdim) + cb + nd * 8 + c0;
            *(uint32_t*)&vah[idx] = hi;
            *(uint32_t*)&val[idx] = lo;
            split2(accO[nd][2] * inv1, accO[nd][3] * inv1, hi, lo);
            idx = (R0 + r1) * (2 * Cdim) + cb + nd * 8 + c0;
            *(uint32_t*)&vah[idx] = hi;
            *(uint32_t*)&val[idx] = lo;
        }
    }
}

// ======================= launcher ==========================================
extern "C" void kernel_launch(void* const* d_in, const int* in_sizes, int n_in,
                              void* d_out, int out_size)
{
    (void)in_sizes; (void)n_in; (void)out_size;
    const float* e        = (const float*)d_in[0];
    const float* mask     = (const float*)d_in[1];
    const float* ln_g     = (const float*)d_in[2];
    const float* ln_b     = (const float*)d_in[3];
    const float* W_qkv_in = (const float*)d_in[4];
    const float* b_qkv_in = (const float*)d_in[5];
    const float* W_E_in   = (const float*)d_in[6];
    const float* b_E_in   = (const float*)d_in[7];
    const float* W_qkv_out= (const float*)d_in[8];
    const float* b_qkv_out= (const float*)d_in[9];
    const float* W_E_out  = (const float*)d_in[10];
    const float* b_E_out  = (const float*)d_in[11];
    const float* W_O      = (const float*)d_in[12];
    const float* b_O      = (const float*)d_in[13];

    __nv_bfloat16 *p_ahi, *p_alo, *p_winh, *p_winl, *p_wouth, *p_woutl, *p_woh, *p_wol, *p_vah, *p_val;
    __nv_bfloat16 *pQih, *pQil, *pKih, *pKil, *pVih, *pVil, *pQoh, *pQol, *pKoh, *pKol, *pVoh, *pVol;
    float *p_bin, *p_bout;
    cudaGetSymbolAddress((void**)&p_ahi,  g_ahi);
    cudaGetSymbolAddress((void**)&p_alo,  g_alo);
    cudaGetSymbolAddress((void**)&p_winh, g_win_hi);
    cudaGetSymbolAddress((void**)&p_winl, g_win_lo);
    cudaGetSymbolAddress((void**)&p_wouth, g_wout_hi);
    cudaGetSymbolAddress((void**)&p_woutl, g_wout_lo);
    cudaGetSymbolAddress((void**)&p_woh,  g_wo_hi);
    cudaGetSymbolAddress((void**)&p_wol,  g_wo_lo);
    cudaGetSymbolAddress((void**)&pQih, g_Qinh);  cudaGetSymbolAddress((void**)&pQil, g_Qinl);
    cudaGetSymbolAddress((void**)&pKih, g_Kinh);  cudaGetSymbolAddress((void**)&pKil, g_Kinl);
    cudaGetSymbolAddress((void**)&pVih, g_Vinh);  cudaGetSymbolAddress((void**)&pVil, g_Vinl);
    cudaGetSymbolAddress((void**)&pQoh, g_Qouth); cudaGetSymbolAddress((void**)&pQol, g_Qoutl);
    cudaGetSymbolAddress((void**)&pKoh, g_Kouth); cudaGetSymbolAddress((void**)&pKol, g_Koutl);
    cudaGetSymbolAddress((void**)&pVoh, g_Vouth); cudaGetSymbolAddress((void**)&pVol, g_Voutl);
    cudaGetSymbolAddress((void**)&p_bin,  g_bias_in);
    cudaGetSymbolAddress((void**)&p_bout, g_bias_out);
    cudaGetSymbolAddress((void**)&p_vah,  g_vahi);
    cudaGetSymbolAddress((void**)&p_val,  g_valo);

    cudaFuncSetAttribute(mma_gemm, cudaFuncAttributeMaxDynamicSharedMemorySize, SM_TOTAL);
    cudaFuncSetAttribute(attn_mma, cudaFuncAttributeMaxDynamicSharedMemorySize, AT_SMEM);

    convert_wqkv<<<NEXT, Cdim>>>(W_qkv_in,  W_E_in,  p_winh,  p_winl);
    convert_wqkv<<<NEXT, Cdim>>>(W_qkv_out, W_E_out, p_wouth, p_woutl);
    convert_wo<<<Cdim, 2 * Cdim>>>(W_O, p_woh, p_wol);

    ln_kernel<<<ROWS, 256>>>(e, ln_g, ln_b, p_ahi, p_alo);

    mma_gemm<<<dim3(ROWS / 128, NEXT / 64), 256, SM_TOTAL>>>(
        p_ahi, p_alo, p_winh, p_winl, b_qkv_in, b_E_in, mask, Cdim, 0,
        pQih, pQil, pKih, pKil, pVih, pVil, p_bin, nullptr);
    mma_gemm<<<dim3(ROWS / 128, NEXT / 64), 256, SM_TOTAL>>>(
        p_ahi, p_alo, p_wouth, p_woutl, b_qkv_out, b_E_out, mask, Cdim, 1,
        pQoh, pQol, pKoh, pKol, pVoh, pVol, p_bout, nullptr);

    attn_mma<<<dim3(Ndim, Bdim * Hdim, 2), 256, AT_SMEM>>>(
        pQih, pQil, pKih, pKil, pVih, pVil,
        pQoh, pQol, pKoh, pKol, pVoh, pVol,
        p_bin, p_bout, p_vah, p_val);

    mma_gemm<<<dim3(ROWS / 128, Cdim / 64), 256, SM_TOTAL>>>(
        p_vah, p_val, p_woh, p_wol, b_O, nullptr, nullptr, 2 * Cdim, 2,
        nullptr, nullptr, nullptr, nullptr, nullptr, nullptr, nullptr, (float*)d_out);
}

// round 14
// speedup vs baseline: 3.8548x; 1.0552x over previous
#include <cuda_runtime.h>
#include <cuda_bf16.h>
#include <cstdint>
#include <math.h>

#define Bdim 2
#define Ndim 128
#define Cdim 256
#define Hdim 8
#define Ddim 32
#define ROWS (Bdim*Ndim*Ndim)          // 32768
#define QKVW (3*Cdim)                   // 768
#define NEXT (QKVW + 64)                // 832 = qkv + E tile
#define SCALE 0.17677669529663687f
#define LN_EPS 1e-5f
#define PLANE_ELEMS (Bdim*Hdim*Ndim*Ndim*Ddim)   // 8388608

// ======================= helpers ==========================================
__device__ __forceinline__ uint32_t smem_u32(const void* p) {
    uint32_t a;
    asm("{ .reg .u64 t; cvta.to.shared.u64 t, %1; cvt.u32.u64 %0, t; }" : "=r"(a) : "l"(p));
    return a;
}
__device__ __forceinline__ void ldsm4(uint32_t* r, uint32_t addr) {
    asm volatile("ldmatrix.sync.aligned.m8n8.x4.shared.b16 {%0,%1,%2,%3}, [%4];"
        : "=r"(r[0]), "=r"(r[1]), "=r"(r[2]), "=r"(r[3]) : "r"(addr));
}
__device__ __forceinline__ void ldsm4t(uint32_t* r, uint32_t addr) {
    asm volatile("ldmatrix.sync.aligned.m8n8.x4.trans.shared.b16 {%0,%1,%2,%3}, [%4];"
        : "=r"(r[0]), "=r"(r[1]), "=r"(r[2]), "=r"(r[3]) : "r"(addr));
}
__device__ __forceinline__ void mma16816(float* d, const uint32_t* a, const uint32_t* b) {
    asm volatile("mma.sync.aligned.m16n8k16.row.col.f32.bf16.bf16.f32 "
        "{%0,%1,%2,%3}, {%4,%5,%6,%7}, {%8,%9}, {%0,%1,%2,%3};"
        : "+f"(d[0]), "+f"(d[1]), "+f"(d[2]), "+f"(d[3])
        : "r"(a[0]), "r"(a[1]), "r"(a[2]), "r"(a[3]), "r"(b[0]), "r"(b[1]));
}
__device__ __forceinline__ void split2(float x, float y, uint32_t& hi, uint32_t& lo) {
    __nv_bfloat162 h = __floats2bfloat162_rn(x, y);
    float hx = __bfloat162float(h.x), hy = __bfloat162float(h.y);
    __nv_bfloat162 l = __floats2bfloat162_rn(x - hx, y - hy);
    hi = *(uint32_t*)&h;
    lo = *(uint32_t*)&l;
}

// ======================= scratch (device globals) ==========================
__device__ __align__(16) __nv_bfloat16 g_ahi[ROWS * Cdim];
__device__ __align__(16) __nv_bfloat16 g_alo[ROWS * Cdim];
__device__ __align__(16) __nv_bfloat16 g_win_hi[NEXT * Cdim];
__device__ __align__(16) __nv_bfloat16 g_win_lo[NEXT * Cdim];
__device__ __align__(16) __nv_bfloat16 g_wout_hi[NEXT * Cdim];
__device__ __align__(16) __nv_bfloat16 g_wout_lo[NEXT * Cdim];
__device__ __align__(16) __nv_bfloat16 g_wo_hi[Cdim * 2 * Cdim];
__device__ __align__(16) __nv_bfloat16 g_wo_lo[Cdim * 2 * Cdim];
__device__ __align__(16) __nv_bfloat16 g_Qinh[PLANE_ELEMS],  g_Qinl[PLANE_ELEMS];
__device__ __align__(16) __nv_bfloat16 g_Kinh[PLANE_ELEMS],  g_Kinl[PLANE_ELEMS];
__device__ __align__(16) __nv_bfloat16 g_Vinh[PLANE_ELEMS],  g_Vinl[PLANE_ELEMS];
__device__ __align__(16) __nv_bfloat16 g_Qouth[PLANE_ELEMS], g_Qoutl[PLANE_ELEMS];
__device__ __align__(16) __nv_bfloat16 g_Kouth[PLANE_ELEMS], g_Koutl[PLANE_ELEMS];
__device__ __align__(16) __nv_bfloat16 g_Vouth[PLANE_ELEMS], g_Voutl[PLANE_ELEMS];
__device__ __align__(16) float g_bias_in[Bdim * Hdim * Ndim * Ndim];   // [b,h,i,k]
__device__ __align__(16) float g_bias_out[Bdim * Hdim * Ndim * Ndim];  // [b,h,i,k]
__device__ __align__(16) __nv_bfloat16 g_vahi[ROWS * 2 * Cdim];
__device__ __align__(16) __nv_bfloat16 g_valo[ROWS * 2 * Cdim];

// ======================= per-pass parameter bundle =========================
struct QkvSet {
    const __nv_bfloat16 *wh, *wl;   // weights [NEXT][256]
    const float *bias;              // [768]
    const float *bE;                // [8]
    __nv_bfloat16 *qh, *ql, *kh, *kl, *vh, *vl;
    float *bp;                      // bias plane [b,h,i,k]
};

// ======================= weight converts ===================================
__global__ void convert_wqkv(const float* __restrict__ W, const float* __restrict__ WE,
                             __nv_bfloat16* __restrict__ th, __nv_bfloat16* __restrict__ tl)
{
    const int n = blockIdx.x;      // 0..831
    const int k = threadIdx.x;     // 0..255
    float w;
    if (n < QKVW) {
        int part = n >> 8, rem = n & 255;
        int h = rem >> 5, d = rem & 31;
        w = W[(size_t)k * QKVW + part * 256 + d * 8 + h];
    } else if (n < QKVW + 8) {
        w = WE[k * 8 + (n - QKVW)];
    } else {
        w = 0.f;
    }
    __nv_bfloat16 hi = __float2bfloat16(w);
    th[(size_t)n * Cdim + k] = hi;
    tl[(size_t)n * Cdim + k] = __float2bfloat16(w - __bfloat162float(hi));
}

__global__ void convert_wo(const float* __restrict__ W, __nv_bfloat16* __restrict__ th,
                           __nv_bfloat16* __restrict__ tl)
{
    const int n = blockIdx.x;      // 0..255
    const int k = threadIdx.x;     // 0..511
    int part = k >> 8, rem = k & 255;
    int h = rem >> 5, d = rem & 31;
    int orig_k = d * 16 + part * 8 + h;
    float w = W[(size_t)orig_k * Cdim + n];
    __nv_bfloat16 hi = __float2bfloat16(w);
    th[(size_t)n * 2 * Cdim + k] = hi;
    tl[(size_t)n * 2 * Cdim + k] = __float2bfloat16(w - __bfloat162float(hi));
}

// ======================= LayerNorm (warp per row) ==========================
__global__ __launch_bounds__(256) void ln_kernel(
    const float* __restrict__ e,
    const float* __restrict__ ln_g, const float* __restrict__ ln_b,
    __nv_bfloat16* __restrict__ ahi, __nv_bfloat16* __restrict__ alo)
{
    const int lane = threadIdx.x & 31;
    const int row = blockIdx.x * 8 + (threadIdx.x >> 5);
    const float4* er = (const float4*)(e + (size_t)row * Cdim);
    float4 a = er[lane];
    float4 b = er[lane + 32];

    float s = a.x + a.y + a.z + a.w + b.x + b.y + b.z + b.w;
    #pragma unroll
    for (int o = 16; o; o >>= 1) s += __shfl_xor_sync(0xffffffffu, s, o);
    const float mu = s * (1.0f / Cdim);

    float dx[8] = {a.x - mu, a.y - mu, a.z - mu, a.w - mu,
                   b.x - mu, b.y - mu, b.z - mu, b.w - mu};
    float v = 0.f;
    #pragma unroll
    for (int q = 0; q < 8; q++) v += dx[q] * dx[q];
    #pragma unroll
    for (int o = 16; o; o >>= 1) v += __shfl_xor_sync(0xffffffffu, v, o);
    const float rs = rsqrtf(v * (1.0f / Cdim) + LN_EPS);

    const float4* gp = (const float4*)ln_g;
    const float4* bp = (const float4*)ln_b;
    float4 g1 = gp[lane], g2 = gp[lane + 32];
    float4 b1 = bp[lane], b2 = bp[lane + 32];
    float y[8];
    y[0] = dx[0] * rs * g1.x + b1.x; y[1] = dx[1] * rs * g1.y + b1.y;
    y[2] = dx[2] * rs * g1.z + b1.z; y[3] = dx[3] * rs * g1.w + b1.w;
    y[4] = dx[4] * rs * g2.x + b2.x; y[5] = dx[5] * rs * g2.y + b2.y;
    y[6] = dx[6] * rs * g2.z + b2.z; y[7] = dx[7] * rs * g2.w + b2.w;

    uint32_t h01, l01, h23, l23, h45, l45, h67, l67;
    split2(y[0], y[1], h01, l01); split2(y[2], y[3], h23, l23);
    split2(y[4], y[5], h45, l45); split2(y[6], y[7], h67, l67);
    uint2* oh = (uint2*)(ahi + (size_t)row * Cdim);
    uint2* ol = (uint2*)(alo + (size_t)row * Cdim);
    oh[lane]      = make_uint2(h01, h23);
    ol[lane]      = make_uint2(l01, l23);
    oh[lane + 32] = make_uint2(h45, h67);
    ol[lane + 32] = make_uint2(l45, l67);
}

// ======================= qkv+E GEMM (both passes, grid.z=2) ================
#define SM_A_HI 0
#define SM_A_LO 16384
#define SM_B_HI 32768
#define SM_B_LO 40960
#define SM_TOTAL 49152

__global__ __launch_bounds__(256) void mma_gemm_qkv(
    const __nv_bfloat16* __restrict__ Ah, const __nv_bfloat16* __restrict__ Al,
    const float* __restrict__ mask, QkvSet s0, QkvSet s1)
{
    extern __shared__ __align__(1024) char smem[];
    const uint32_t sb = smem_u32(smem);
    const int mode = blockIdx.z;
    const QkvSet S = mode ? s1 : s0;
    const int tid = threadIdx.x;
    const int wid = tid >> 5, lane = tid & 31;
    const int bm = blockIdx.x * 128;
    const int bn = blockIdx.y * 64;
    const int m0 = (wid & 3) * 32;
    const int n0w = (wid >> 2) * 32;

    float acc[2][4][4];
    #pragma unroll
    for (int a = 0; a < 2; a++)
        #pragma unroll
        for (int b = 0; b < 4; b++)
            #pragma unroll
            for (int cc = 0; cc < 4; cc++) acc[a][b][cc] = 0.f;

    uint32_t aOff[2], aKey[2], bOff[2], bKey[2];
    #pragma unroll
    for (int mi = 0; mi < 2; mi++) {
        int r = m0 + mi * 16 + (lane & 15);
        aOff[mi] = r * 128; aKey[mi] = (r & 7) << 4;
    }
    #pragma unroll
    for (int pi = 0; pi < 2; pi++) {
        int r = n0w + pi * 16 + ((lane >> 4) << 3) + (lane & 7);
        bOff[pi] = r * 128; bKey[pi] = (r & 7) << 4;
    }
    const uint32_t aK = (lane >> 4) * 16;
    const uint32_t bK = ((lane >> 3) & 1) * 16;

    for (int c = 0; c < 4; c++) {
        if (c) __syncthreads();
        #pragma unroll
        for (int it = 0; it < 4; it++) {
            int t = tid + it * 256;
            int row = t >> 3, seg = t & 7;
            size_t gidx = (size_t)(bm + row) * Cdim + c * 64 + seg * 8;
            uint32_t off = row * 128 + ((seg * 16) ^ ((row & 7) << 4));
            *(uint4*)(smem + SM_A_HI + off) = *(const uint4*)(Ah + gidx);
            *(uint4*)(smem + SM_A_LO + off) = *(const uint4*)(Al + gidx);
        }
        #pragma unroll
        for (int it = 0; it < 2; it++) {
            int t = tid + it * 256;
            int row = t >> 3, seg = t & 7;
            size_t gidx = (size_t)(bn + row) * Cdim + c * 64 + seg * 8;
            uint32_t off = row * 128 + ((seg * 16) ^ ((row & 7) << 4));
            *(uint4*)(smem + SM_B_HI + off) = *(const uint4*)(S.wh + gidx);
            *(uint4*)(smem + SM_B_LO + off) = *(const uint4*)(S.wl + gidx);
        }
        __syncthreads();

        #pragma unroll
        for (int ks = 0; ks < 4; ks++) {
            const uint32_t ka = ks * 32 + aK;
            const uint32_t kb = ks * 32 + bK;
            uint32_t ah[2][4], al[2][4], bh2[2][4], bl2[2][4];
            #pragma unroll
            for (int mi = 0; mi < 2; mi++) {
                ldsm4(ah[mi], sb + SM_A_HI + aOff[mi] + (ka ^ aKey[mi]));
                ldsm4(al[mi], sb + SM_A_LO + aOff[mi] + (ka ^ aKey[mi]));
            }
            #pragma unroll
            for (int pi = 0; pi < 2; pi++) {
                ldsm4(bh2[pi], sb + SM_B_HI + bOff[pi] + (kb ^ bKey[pi]));
                ldsm4(bl2[pi], sb + SM_B_LO + bOff[pi] + (kb ^ bKey[pi]));
            }
            #pragma unroll
            for (int mi = 0; mi < 2; mi++)
                #pragma unroll
                for (int ni = 0; ni < 4; ni++) {
                    const uint32_t* bh_f = &bh2[ni >> 1][(ni & 1) * 2];
                    const uint32_t* bl_f = &bl2[ni >> 1][(ni & 1) * 2];
                    mma16816(acc[mi][ni], ah[mi], bh_f);
                    mma16816(acc[mi][ni], al[mi], bh_f);
                    mma16816(acc[mi][ni], ah[mi], bl_f);
                }
        }
    }

    const int lane4 = lane >> 2;
    const int col2 = (lane & 3) * 2;
    #pragma unroll
    for (int mi = 0; mi < 2; mi++) {
        #pragma unroll
        for (int half = 0; half < 2; half++) {
            const int row = bm + m0 + mi * 16 + lane4 + half * 8;
            const int b2 = row >> 14;
            const int rx = (row >> 7) & 127;
            const int ry = row & 127;
            const int xx = mode ? ry : rx;
            const int yy = mode ? rx : ry;
            #pragma unroll
            for (int ni = 0; ni < 4; ni++) {
                int cg = bn + n0w + ni * 8 + col2;
                if (cg < QKVW) {
                    int part = cg >> 8, hh = (cg >> 5) & 7, dd = cg & 31;
                    __nv_bfloat16 *ph, *pl;
                    if (part == 0)      { ph = S.qh; pl = S.ql; }
                    else if (part == 1) { ph = S.kh; pl = S.kl; }
                    else                { ph = S.vh; pl = S.vl; }
                    float sc = (part == 0) ? SCALE : 1.0f;
                    int px = xx, py = yy;
                    if (mode == 0 && part == 0) { px = yy; py = xx; }  // Q-in transposed
                    size_t pb = ((((size_t)b2 * Hdim + hh) * Ndim + px) * Ndim + py) * Ddim + dd;
                    float ox = (acc[mi][ni][half * 2 + 0] + S.bias[part * 256 + dd * 8 + hh]) * sc;
                    float oy = (acc[mi][ni][half * 2 + 1] + S.bias[part * 256 + (dd + 1) * 8 + hh]) * sc;
                    uint32_t hi, lo;
                    split2(ox, oy, hi, lo);
                    *(uint32_t*)&ph[pb] = hi;
                    *(uint32_t*)&pl[pb] = lo;
                } else if (cg < QKVW + 8) {
                    int h = cg - QKVW;   // even
                    float v0 = acc[mi][ni][half * 2 + 0] + S.bE[h]     + mask[(size_t)row * 8 + h];
                    float v1 = acc[mi][ni][half * 2 + 1] + S.bE[h + 1] + mask[(size_t)row * 8 + h + 1];
                    if (mode == 0) {
                        S.bp[(((size_t)(b2 * Hdim + h))     * Ndim + rx) * Ndim + ry] = v0;
                        S.bp[(((size_t)(b2 * Hdim + h + 1)) * Ndim + rx) * Ndim + ry] = v1;
                    } else {
                        S.bp[(((size_t)(b2 * Hdim + h))     * Ndim + ry) * Ndim + rx] = v0;
                        S.bp[(((size_t)(b2 * Hdim + h + 1)) * Ndim + ry) * Ndim + rx] = v1;
                    }
                }
            }
        }
    }
}

// ======================= out-GEMM (K=512, N=256) ===========================
__global__ __launch_bounds__(256) void mma_gemm_out(
    const __nv_bfloat16* __restrict__ Ah, const __nv_bfloat16* __restrict__ Al,
    const __nv_bfloat16* __restrict__ Bh, const __nv_bfloat16* __restrict__ Bl,
    const float* __restrict__ bias, float* __restrict__ outf)
{
    extern __shared__ __align__(1024) char smem[];
    const uint32_t sb = smem_u32(smem);
    const int tid = threadIdx.x;
    const int wid = tid >> 5, lane = tid & 31;
    const int bm = blockIdx.x * 128;
    const int bn = blockIdx.y * 64;
    const int K = 2 * Cdim;
    const int m0 = (wid & 3) * 32;
    const int n0w = (wid >> 2) * 32;

    float acc[2][4][4];
    #pragma unroll
    for (int a = 0; a < 2; a++)
        #pragma unroll
        for (int b = 0; b < 4; b++)
            #pragma unroll
            for (int cc = 0; cc < 4; cc++) acc[a][b][cc] = 0.f;

    uint32_t aOff[2], aKey[2], bOff[2], bKey[2];
    #pragma unroll
    for (int mi = 0; mi < 2; mi++) {
        int r = m0 + mi * 16 + (lane & 15);
        aOff[mi] = r * 128; aKey[mi] = (r & 7) << 4;
    }
    #pragma unroll
    for (int pi = 0; pi < 2; pi++) {
        int r = n0w + pi * 16 + ((lane >> 4) << 3) + (lane & 7);
        bOff[pi] = r * 128; bKey[pi] = (r & 7) << 4;
    }
    const uint32_t aK = (lane >> 4) * 16;
    const uint32_t bK = ((lane >> 3) & 1) * 16;

    for (int c = 0; c < 8; c++) {
        if (c) __syncthreads();
        #pragma unroll
        for (int it = 0; it < 4; it++) {
            int t = tid + it * 256;
            int row = t >> 3, seg = t & 7;
            size_t gidx = (size_t)(bm + row) * K + c * 64 + seg * 8;
            uint32_t off = row * 128 + ((seg * 16) ^ ((row & 7) << 4));
            *(uint4*)(smem + SM_A_HI + off) = *(const uint4*)(Ah + gidx);
            *(uint4*)(smem + SM_A_LO + off) = *(const uint4*)(Al + gidx);
        }
        #pragma unroll
        for (int it = 0; it < 2; it++) {
            int t = tid + it * 256;
            int row = t >> 3, seg = t & 7;
            size_t gidx = (size_t)(bn + row) * K + c * 64 + seg * 8;
            uint32_t off = row * 128 + ((seg * 16) ^ ((row & 7) << 4));
            *(uint4*)(smem + SM_B_HI + off) = *(const uint4*)(Bh + gidx);
            *(uint4*)(smem + SM_B_LO + off) = *(const uint4*)(Bl + gidx);
        }
        __syncthreads();

        #pragma unroll
        for (int ks = 0; ks < 4; ks++) {
            const uint32_t ka = ks * 32 + aK;
            const uint32_t kb = ks * 32 + bK;
            uint32_t ah[2][4], al[2][4], bh2[2][4], bl2[2][4];
            #pragma unroll
            for (int mi = 0; mi < 2; mi++) {
                ldsm4(ah[mi], sb + SM_A_HI + aOff[mi] + (ka ^ aKey[mi]));
                ldsm4(al[mi], sb + SM_A_LO + aOff[mi] + (ka ^ aKey[mi]));
            }
            #pragma unroll
            for (int pi = 0; pi < 2; pi++) {
                ldsm4(bh2[pi], sb + SM_B_HI + bOff[pi] + (kb ^ bKey[pi]));
                ldsm4(bl2[pi], sb + SM_B_LO + bOff[pi] + (kb ^ bKey[pi]));
            }
            #pragma unroll
            for (int mi = 0; mi < 2; mi++)
                #pragma unroll
                for (int ni = 0; ni < 4; ni++) {
                    const uint32_t* bh_f = &bh2[ni >> 1][(ni & 1) * 2];
                    const uint32_t* bl_f = &bl2[ni >> 1][(ni & 1) * 2];
                    mma16816(acc[mi][ni], ah[mi], bh_f);
                    mma16816(acc[mi][ni], al[mi], bh_f);
                    mma16816(acc[mi][ni], ah[mi], bl_f);
                }
        }
    }

    const int lane4 = lane >> 2;
    const int col2 = (lane & 3) * 2;
    #pragma unroll
    for (int mi = 0; mi < 2; mi++) {
        #pragma unroll
        for (int half = 0; half < 2; half++) {
            const int row = bm + m0 + mi * 16 + lane4 + half * 8;
            const int b2 = row >> 14;
            const int j2 = (row >> 7) & 127;
            const int i2 = row & 127;
            size_t ob = ((size_t)((b2 * Ndim + i2) * Ndim + j2)) * Cdim;
            #pragma unroll
            for (int ni = 0; ni < 4; ni++) {
                int cg = bn + n0w + ni * 8 + col2;
                float2 o;
                o.x = acc[mi][ni][half * 2 + 0] + bias[cg];
                o.y = acc[mi][ni][half * 2 + 1] + bias[cg + 1];
                *(float2*)&outf[ob + cg] = o;
            }
        }
    }
}

// ======================= HMMA attention ====================================
#define AT_Q 0
#define AT_K 20480
#define AT_V 40960
#define AT_LO 10240
#define AT_SMEM 61440

__global__ __launch_bounds__(256) void attn_mma(
    const __nv_bfloat16* __restrict__ Qinh, const __nv_bfloat16* __restrict__ Qinl,
    const __nv_bfloat16* __restrict__ Kinh, const __nv_bfloat16* __restrict__ Kinl,
    const __nv_bfloat16* __restrict__ Vinh, const __nv_bfloat16* __restrict__ Vinl,
    const __nv_bfloat16* __restrict__ Qouth, const __nv_bfloat16* __restrict__ Qoutl,
    const __nv_bfloat16* __restrict__ Kouth, const __nv_bfloat16* __restrict__ Koutl,
    const __nv_bfloat16* __restrict__ Vouth, const __nv_bfloat16* __restrict__ Voutl,
    const float* __restrict__ bias_in, const float* __restrict__ bias_out,
    __nv_bfloat16* __restrict__ vah, __nv_bfloat16* __restrict__ val)
{
    extern __shared__ __align__(128) char sm[];
    const uint32_t sb = smem_u32(sm);
    const int j = blockIdx.x;
    const int bh = blockIdx.y;
    const int pass = blockIdx.z;
    const int tid = threadIdx.x;
    const int wid = tid >> 5, lane = tid & 31;

    const size_t pbase = ((size_t)(bh * Ndim + j)) * (Ndim * Ddim);

    // ---- stage bf16 hi/lo planes -> smem (pure copy) ----
    {
        const int r = tid & 127;
        const int half = tid >> 7;
        const __nv_bfloat16* srcs[6];
        if (pass) {
            srcs[0] = Qouth; srcs[1] = Qoutl; srcs[2] = Kouth;
            srcs[3] = Koutl; srcs[4] = Vouth; srcs[5] = Voutl;
        } else {
            srcs[0] = Qinh; srcs[1] = Qinl; srcs[2] = Kinh;
            srcs[3] = Kinl; srcs[4] = Vinh; srcs[5] = Vinl;
        }
        const uint32_t dsto[6] = {AT_Q, AT_Q + AT_LO, AT_K, AT_K + AT_LO, AT_V, AT_V + AT_LO};
        const int eoff = r * 32 + half * 16;
        #pragma unroll
        for (int t = 0; t < 6; t++) {
            const uint4* s4 = (const uint4*)(srcs[t] + pbase + eoff);
            char* d = sm + dsto[t] + r * 80 + half * 32;
            *(uint4*)d = s4[0];
            *(uint4*)(d + 16) = s4[1];
        }
    }
    __syncthreads();

    const int m0 = wid * 16;

    // ---- S = Q K^T (3-term hi/lo) ----
    float accS[16][4];
    #pragma unroll
    for (int n = 0; n < 16; n++)
        #pragma unroll
        for (int c = 0; c < 4; c++) accS[n][c] = 0.f;

    #pragma unroll
    for (int kc = 0; kc < 2; kc++) {
        uint32_t qaddr = sb + AT_Q + (m0 + (lane & 15)) * 80 + kc * 32 + (lane >> 4) * 16;
        uint32_t qh[4], ql[4];
        ldsm4(qh, qaddr);
        ldsm4(ql, qaddr + AT_LO);
        #pragma unroll
        for (int pi = 0; pi < 8; pi++) {
            uint32_t kaddr = sb + AT_K + (pi * 16 + ((lane >> 4) << 3) + (lane & 7)) * 80
                           + kc * 32 + ((lane >> 3) & 1) * 16;
            uint32_t kh[4], kl[4];
            ldsm4(kh, kaddr);
            ldsm4(kl, kaddr + AT_LO);
            #pragma unroll
            for (int t = 0; t < 2; t++) {
                mma16816(accS[2 * pi + t], qh, &kh[t * 2]);
                mma16816(accS[2 * pi + t], ql, &kh[t * 2]);
                mma16816(accS[2 * pi + t], qh, &kl[t * 2]);
            }
        }
    }

    // ---- bias + softmax ----
    {
        const float* bb = (pass ? bias_out : bias_in) + (size_t)bh * Ndim * Ndim;
        const int r0 = m0 + (lane >> 2);
        const int r1 = r0 + 8;
        const int c0 = (lane & 3) * 2;
        #pragma unroll
        for (int ni = 0; ni < 16; ni++) {
            float2 b0 = *(const float2*)(bb + r0 * Ndim + ni * 8 + c0);
            float2 b1 = *(const float2*)(bb + r1 * Ndim + ni * 8 + c0);
            accS[ni][0] += b0.x; accS[ni][1] += b0.y;
            accS[ni][2] += b1.x; accS[ni][3] += b1.y;
        }
        float mx0 = -1e30f, mx1 = -1e30f;
        #pragma unroll
        for (int ni = 0; ni < 16; ni++) {
            mx0 = fmaxf(mx0, fmaxf(accS[ni][0], accS[ni][1]));
            mx1 = fmaxf(mx1, fmaxf(accS[ni][2], accS[ni][3]));
        }
        mx0 = fmaxf(mx0, __shfl_xor_sync(0xffffffffu, mx0, 1));
        mx0 = fmaxf(mx0, __shfl_xor_sync(0xffffffffu, mx0, 2));
        mx1 = fmaxf(mx1, __shfl_xor_sync(0xffffffffu, mx1, 1));
        mx1 = fmaxf(mx1, __shfl_xor_sync(0xffffffffu, mx1, 2));
        float s0 = 0.f, s1 = 0.f;
        #pragma unroll
        for (int ni = 0; ni < 16; ni++) {
            accS[ni][0] = __expf(accS[ni][0] - mx0);
            accS[ni][1] = __expf(accS[ni][1] - mx0);
            accS[ni][2] = __expf(accS[ni][2] - mx1);
            accS[ni][3] = __expf(accS[ni][3] - mx1);
            s0 += accS[ni][0] + accS[ni][1];
            s1 += accS[ni][2] + accS[ni][3];
        }
        s0 += __shfl_xor_sync(0xffffffffu, s0, 1);
        s0 += __shfl_xor_sync(0xffffffffu, s0, 2);
        s1 += __shfl_xor_sync(0xffffffffu, s1, 1);
        s1 += __shfl_xor_sync(0xffffffffu, s1, 2);

        // ---- O = P V (3-term hi/lo) ----
        float accO[4][4];
        #pragma unroll
        for (int n = 0; n < 4; n++)
            #pragma unroll
            for (int c = 0; c < 4; c++) accO[n][c] = 0.f;

        #pragma unroll
        for (int kc = 0; kc < 8; kc++) {
            uint32_t ph[4], pl[4];
            split2(accS[2 * kc][0], accS[2 * kc][1], ph[0], pl[0]);
            split2(accS[2 * kc][2], accS[2 * kc][3], ph[1], pl[1]);
            split2(accS[2 * kc + 1][0], accS[2 * kc + 1][1], ph[2], pl[2]);
            split2(accS[2 * kc + 1][2], accS[2 * kc + 1][3], ph[3], pl[3]);
            #pragma unroll
            for (int dh = 0; dh < 2; dh++) {
                uint32_t vaddr = sb + AT_V + (kc * 16 + ((lane >> 3) & 1) * 8 + (lane & 7)) * 80
                               + dh * 32 + (lane >> 4) * 16;
                uint32_t vh4[4], vl4[4];
                ldsm4t(vh4, vaddr);
                ldsm4t(vl4, vaddr + AT_LO);
                #pragma unroll
                for (int t = 0; t < 2; t++) {
                    mma16816(accO[dh * 2 + t], ph, &vh4[t * 2]);
                    mma16816(accO[dh * 2 + t], pl, &vh4[t * 2]);
                    mma16816(accO[dh * 2 + t], ph, &vl4[t * 2]);
                }
            }
        }

        // ---- normalize + write va (bf16 hi/lo) ----
        const float inv0 = 1.0f / s0;
        const float inv1 = 1.0f / s1;
        const int b2 = bh >> 3, h = bh & 7;
        const size_t R0 = (size_t)(b2 * Ndim + j) * Ndim;
        const int cb = (pass * 8 + h) * 32;
        #pragma unroll
        for (int nd = 0; nd < 4; nd++) {
            uint32_t hi, lo;
            split2(accO[nd][0] * inv0, accO[nd][1] * inv0, hi, lo);
            size_t idx = (R0 + r0) * (2 * Cdim) + cb + nd * 8 + c0;
            *(uint32_t*)&vah[idx] = hi;
            *(uint32_t*)&val[idx] = lo;
            split2(accO[nd][2] * inv1, accO[nd][3] * inv1, hi, lo);
            idx = (R0 + r1) * (2 * Cdim) + cb + nd * 8 + c0;
            *(uint32_t*)&vah[idx] = hi;
            *(uint32_t*)&val[idx] = lo;
        }
    }
}

// ======================= launcher ==========================================
extern "C" void kernel_launch(void* const* d_in, const int* in_sizes, int n_in,
                              void* d_out, int out_size)
{
    (void)in_sizes; (void)n_in; (void)out_size;
    const float* e        = (const float*)d_in[0];
    const float* mask     = (const float*)d_in[1];
    const float* ln_g     = (const float*)d_in[2];
    const float* ln_b     = (const float*)d_in[3];
    const float* W_qkv_in = (const float*)d_in[4];
    const float* b_qkv_in = (const float*)d_in[5];
    const float* W_E_in   = (const float*)d_in[6];
    const float* b_E_in   = (const float*)d_in[7];
    const float* W_qkv_out= (const float*)d_in[8];
    const float* b_qkv_out= (const float*)d_in[9];
    const float* W_E_out  = (const float*)d_in[10];
    const float* b_E_out  = (const float*)d_in[11];
    const float* W_O      = (const float*)d_in[12];
    const float* b_O      = (const float*)d_in[13];

    __nv_bfloat16 *p_ahi, *p_alo, *p_winh, *p_winl, *p_wouth, *p_woutl, *p_woh, *p_wol, *p_vah, *p_val;
    __nv_bfloat16 *pQih, *pQil, *pKih, *pKil, *pVih, *pVil, *pQoh, *pQol, *pKoh, *pKol, *pVoh, *pVol;
    float *p_bin, *p_bout;
    cudaGetSymbolAddress((void**)&p_ahi,  g_ahi);
    cudaGetSymbolAddress((void**)&p_alo,  g_alo);
    cudaGetSymbolAddress((void**)&p_winh, g_win_hi);
    cudaGetSymbolAddress((void**)&p_winl, g_win_lo);
    cudaGetSymbolAddress((void**)&p_wouth, g_wout_hi);
    cudaGetSymbolAddress((void**)&p_woutl, g_wout_lo);
    cudaGetSymbolAddress((void**)&p_woh,  g_wo_hi);
    cudaGetSymbolAddress((void**)&p_wol,  g_wo_lo);
    cudaGetSymbolAddress((void**)&pQih, g_Qinh);  cudaGetSymbolAddress((void**)&pQil, g_Qinl);
    cudaGetSymbolAddress((void**)&pKih, g_Kinh);  cudaGetSymbolAddress((void**)&pKil, g_Kinl);
    cudaGetSymbolAddress((void**)&pVih, g_Vinh);  cudaGetSymbolAddress((void**)&pVil, g_Vinl);
    cudaGetSymbolAddress((void**)&pQoh, g_Qouth); cudaGetSymbolAddress((void**)&pQol, g_Qoutl);
    cudaGetSymbolAddress((void**)&pKoh, g_Kouth); cudaGetSymbolAddress((void**)&pKol, g_Koutl);
    cudaGetSymbolAddress((void**)&pVoh, g_Vouth); cudaGetSymbolAddress((void**)&pVol, g_Voutl);
    cudaGetSymbolAddress((void**)&p_bin,  g_bias_in);
    cudaGetSymbolAddress((void**)&p_bout, g_bias_out);
    cudaGetSymbolAddress((void**)&p_vah,  g_vahi);
    cudaGetSymbolAddress((void**)&p_val,  g_valo);

    cudaFuncSetAttribute(mma_gemm_qkv, cudaFuncAttributeMaxDynamicSharedMemorySize, SM_TOTAL);
    cudaFuncSetAttribute(mma_gemm_out, cudaFuncAttributeMaxDynamicSharedMemorySize, SM_TOTAL);
    cudaFuncSetAttribute(attn_mma, cudaFuncAttributeMaxDynamicSharedMemorySize, AT_SMEM);

    convert_wqkv<<<NEXT, Cdim>>>(W_qkv_in,  W_E_in,  p_winh,  p_winl);
    convert_wqkv<<<NEXT, Cdim>>>(W_qkv_out, W_E_out, p_wouth, p_woutl);
    convert_wo<<<Cdim, 2 * Cdim>>>(W_O, p_woh, p_wol);

    ln_kernel<<<ROWS / 8, 256>>>(e, ln_g, ln_b, p_ahi, p_alo);

    QkvSet s0 = { p_winh,  p_winl,  b_qkv_in,  b_E_in,
                  pQih, pQil, pKih, pKil, pVih, pVil, p_bin };
    QkvSet s1 = { p_wouth, p_woutl, b_qkv_out, b_E_out,
                  pQoh, pQol, pKoh, pKol, pVoh, pVol, p_bout };

    mma_gemm_qkv<<<dim3(ROWS / 128, NEXT / 64, 2), 256, SM_TOTAL>>>(
        p_ahi, p_alo, mask, s0, s1);

    attn_mma<<<dim3(Ndim, Bdim * Hdim, 2), 256, AT_SMEM>>>(
        pQih, pQil, pKih, pKil, pVih, pVil,
        pQoh, pQol, pKoh, pKol, pVoh, pVol,
        p_bin, p_bout, p_vah, p_val);

    mma_gemm_out<<<dim3(ROWS / 128, Cdim / 64), 256, SM_TOTAL>>>(
        p_vah, p_val, p_woh, p_wol, b_O, (float*)d_out);
}

// round 16
// speedup vs baseline: 4.5481x; 1.1799x over previous
#include <cuda_runtime.h>
#include <cuda_bf16.h>
#include <cstdint>
#include <math.h>

#define Bdim 2
#define Ndim 128
#define Cdim 256
#define Hdim 8
#define Ddim 32
#define ROWS (Bdim*Ndim*Ndim)          // 32768
#define QKVW (3*Cdim)                   // 768
#define NEXT (QKVW + 64)                // 832 = qkv + E tile
#define SCALE 0.17677669529663687f
#define LN_EPS 1e-5f
#define PLANE_ELEMS (Bdim*Hdim*Ndim*Ndim*Ddim)   // 8388608

// ======================= helpers ==========================================
__device__ __forceinline__ uint32_t smem_u32(const void* p) {
    uint32_t a;
    asm("{ .reg .u64 t; cvta.to.shared.u64 t, %1; cvt.u32.u64 %0, t; }" : "=r"(a) : "l"(p));
    return a;
}
__device__ __forceinline__ void ldsm4(uint32_t* r, uint32_t addr) {
    asm volatile("ldmatrix.sync.aligned.m8n8.x4.shared.b16 {%0,%1,%2,%3}, [%4];"
        : "=r"(r[0]), "=r"(r[1]), "=r"(r[2]), "=r"(r[3]) : "r"(addr));
}
__device__ __forceinline__ void ldsm4t(uint32_t* r, uint32_t addr) {
    asm volatile("ldmatrix.sync.aligned.m8n8.x4.trans.shared.b16 {%0,%1,%2,%3}, [%4];"
        : "=r"(r[0]), "=r"(r[1]), "=r"(r[2]), "=r"(r[3]) : "r"(addr));
}
__device__ __forceinline__ void mma16816(float* d, const uint32_t* a, const uint32_t* b) {
    asm volatile("mma.sync.aligned.m16n8k16.row.col.f32.bf16.bf16.f32 "
        "{%0,%1,%2,%3}, {%4,%5,%6,%7}, {%8,%9}, {%0,%1,%2,%3};"
        : "+f"(d[0]), "+f"(d[1]), "+f"(d[2]), "+f"(d[3])
        : "r"(a[0]), "r"(a[1]), "r"(a[2]), "r"(a[3]), "r"(b[0]), "r"(b[1]));
}
__device__ __forceinline__ void split2(float x, float y, uint32_t& hi, uint32_t& lo) {
    __nv_bfloat162 h = __floats2bfloat162_rn(x, y);
    float hx = __bfloat162float(h.x), hy = __bfloat162float(h.y);
    __nv_bfloat162 l = __floats2bfloat162_rn(x - hx, y - hy);
    hi = *(uint32_t*)&h;
    lo = *(uint32_t*)&l;
}
__device__ __forceinline__ void cp_async16(uint32_t saddr, const void* gaddr) {
    asm volatile("cp.async.cg.shared.global [%0], [%1], 16;" :: "r"(saddr), "l"(gaddr));
}
#define CP_COMMIT() asm volatile("cp.async.commit_group;")
#define CP_WAIT(n)  asm volatile("cp.async.wait_group %0;" :: "n"(n))

// ======================= scratch (device globals) ==========================
__device__ __align__(16) __nv_bfloat16 g_ahi[ROWS * Cdim];
__device__ __align__(16) __nv_bfloat16 g_alo[ROWS * Cdim];
__device__ __align__(16) __nv_bfloat16 g_win_hi[NEXT * Cdim];
__device__ __align__(16) __nv_bfloat16 g_win_lo[NEXT * Cdim];
__device__ __align__(16) __nv_bfloat16 g_wout_hi[NEXT * Cdim];
__device__ __align__(16) __nv_bfloat16 g_wout_lo[NEXT * Cdim];
__device__ __align__(16) __nv_bfloat16 g_wo_hi[Cdim * 2 * Cdim];
__device__ __align__(16) __nv_bfloat16 g_wo_lo[Cdim * 2 * Cdim];
__device__ __align__(16) __nv_bfloat16 g_Qinh[PLANE_ELEMS],  g_Qinl[PLANE_ELEMS];
__device__ __align__(16) __nv_bfloat16 g_Kinh[PLANE_ELEMS],  g_Kinl[PLANE_ELEMS];
__device__ __align__(16) __nv_bfloat16 g_Vinh[PLANE_ELEMS],  g_Vinl[PLANE_ELEMS];
__device__ __align__(16) __nv_bfloat16 g_Qouth[PLANE_ELEMS], g_Qoutl[PLANE_ELEMS];
__device__ __align__(16) __nv_bfloat16 g_Kouth[PLANE_ELEMS], g_Koutl[PLANE_ELEMS];
__device__ __align__(16) __nv_bfloat16 g_Vouth[PLANE_ELEMS], g_Voutl[PLANE_ELEMS];
__device__ __align__(16) float g_bias_in[Bdim * Hdim * Ndim * Ndim];   // [b,h,i,k]
__device__ __align__(16) float g_bias_out[Bdim * Hdim * Ndim * Ndim];  // [b,h,i,k]
__device__ __align__(16) __nv_bfloat16 g_vahi[ROWS * 2 * Cdim];
__device__ __align__(16) __nv_bfloat16 g_valo[ROWS * 2 * Cdim];

// ======================= per-pass parameter bundle =========================
struct QkvSet {
    const __nv_bfloat16 *wh, *wl;   // weights [NEXT][256]
    const float *bias;              // [768]
    const float *bE;                // [8]
    __nv_bfloat16 *qh, *ql, *kh, *kl, *vh, *vl;
    float *bp;                      // bias plane [b,h,i,k]
};

// ======================= weight converts ===================================
__global__ void convert_wqkv(const float* __restrict__ W, const float* __restrict__ WE,
                             __nv_bfloat16* __restrict__ th, __nv_bfloat16* __restrict__ tl)
{
    const int n = blockIdx.x;      // 0..831
    const int k = threadIdx.x;     // 0..255
    float w;
    if (n < QKVW) {
        int part = n >> 8, rem = n & 255;
        int h = rem >> 5, d = rem & 31;
        w = W[(size_t)k * QKVW + part * 256 + d * 8 + h];
    } else if (n < QKVW + 8) {
        w = WE[k * 8 + (n - QKVW)];
    } else {
        w = 0.f;
    }
    __nv_bfloat16 hi = __float2bfloat16(w);
    th[(size_t)n * Cdim + k] = hi;
    tl[(size_t)n * Cdim + k] = __float2bfloat16(w - __bfloat162float(hi));
}

__global__ void convert_wo(const float* __restrict__ W, __nv_bfloat16* __restrict__ th,
                           __nv_bfloat16* __restrict__ tl)
{
    const int n = blockIdx.x;      // 0..255
    const int k = threadIdx.x;     // 0..511
    int part = k >> 8, rem = k & 255;
    int h = rem >> 5, d = rem & 31;
    int orig_k = d * 16 + part * 8 + h;
    float w = W[(size_t)orig_k * Cdim + n];
    __nv_bfloat16 hi = __float2bfloat16(w);
    th[(size_t)n * 2 * Cdim + k] = hi;
    tl[(size_t)n * 2 * Cdim + k] = __float2bfloat16(w - __bfloat162float(hi));
}

// ======================= LayerNorm (warp per row) ==========================
__global__ __launch_bounds__(256) void ln_kernel(
    const float* __restrict__ e,
    const float* __restrict__ ln_g, const float* __restrict__ ln_b,
    __nv_bfloat16* __restrict__ ahi, __nv_bfloat16* __restrict__ alo)
{
    const int lane = threadIdx.x & 31;
    const int row = blockIdx.x * 8 + (threadIdx.x >> 5);
    const float4* er = (const float4*)(e + (size_t)row * Cdim);
    float4 a = er[lane];
    float4 b = er[lane + 32];

    float s = a.x + a.y + a.z + a.w + b.x + b.y + b.z + b.w;
    #pragma unroll
    for (int o = 16; o; o >>= 1) s += __shfl_xor_sync(0xffffffffu, s, o);
    const float mu = s * (1.0f / Cdim);

    float dx[8] = {a.x - mu, a.y - mu, a.z - mu, a.w - mu,
                   b.x - mu, b.y - mu, b.z - mu, b.w - mu};
    float v = 0.f;
    #pragma unroll
    for (int q = 0; q < 8; q++) v += dx[q] * dx[q];
    #pragma unroll
    for (int o = 16; o; o >>= 1) v += __shfl_xor_sync(0xffffffffu, v, o);
    const float rs = rsqrtf(v * (1.0f / Cdim) + LN_EPS);

    const float4* gp = (const float4*)ln_g;
    const float4* bp = (const float4*)ln_b;
    float4 g1 = gp[lane], g2 = gp[lane + 32];
    float4 b1 = bp[lane], b2 = bp[lane + 32];
    float y[8];
    y[0] = dx[0] * rs * g1.x + b1.x; y[1] = dx[1] * rs * g1.y + b1.y;
    y[2] = dx[2] * rs * g1.z + b1.z; y[3] = dx[3] * rs * g1.w + b1.w;
    y[4] = dx[4] * rs * g2.x + b2.x; y[5] = dx[5] * rs * g2.y + b2.y;
    y[6] = dx[6] * rs * g2.z + b2.z; y[7] = dx[7] * rs * g2.w + b2.w;

    uint32_t h01, l01, h23, l23, h45, l45, h67, l67;
    split2(y[0], y[1], h01, l01); split2(y[2], y[3], h23, l23);
    split2(y[4], y[5], h45, l45); split2(y[6], y[7], h67, l67);
    uint2* oh = (uint2*)(ahi + (size_t)row * Cdim);
    uint2* ol = (uint2*)(alo + (size_t)row * Cdim);
    oh[lane]      = make_uint2(h01, h23);
    ol[lane]      = make_uint2(l01, l23);
    oh[lane + 32] = make_uint2(h45, h67);
    ol[lane + 32] = make_uint2(l45, l67);
}

// ======================= GEMM smem layout (per buffer) =====================
#define SM_A_HI 0
#define SM_A_LO 16384
#define SM_B_HI 32768
#define SM_B_LO 40960
#define SMB     49152
#define SM_TOTAL (2 * SMB)

// ======================= qkv+E GEMM (both passes, grid.z=2, cp.async) ======
__global__ __launch_bounds__(256) void mma_gemm_qkv(
    const __nv_bfloat16* __restrict__ Ah, const __nv_bfloat16* __restrict__ Al,
    const float* __restrict__ mask, QkvSet s0, QkvSet s1)
{
    extern __shared__ __align__(1024) char smem[];
    const uint32_t sb = smem_u32(smem);
    const int mode = blockIdx.z;
    const QkvSet S = mode ? s1 : s0;
    const int tid = threadIdx.x;
    const int wid = tid >> 5, lane = tid & 31;
    const int bm = blockIdx.x * 128;
    const int bn = blockIdx.y * 64;
    const int m0 = (wid & 3) * 32;
    const int n0w = (wid >> 2) * 32;

    float acc[2][4][4];
    #pragma unroll
    for (int a = 0; a < 2; a++)
        #pragma unroll
        for (int b = 0; b < 4; b++)
            #pragma unroll
            for (int cc = 0; cc < 4; cc++) acc[a][b][cc] = 0.f;

    // staging indices (per thread)
    const int sArow = tid >> 3, sAseg = tid & 7;
    const uint32_t sAoff = sArow * 128 + ((sAseg * 16) ^ ((sArow & 7) << 4));

    uint32_t aOff[2], aKey[2], bOff[2], bKey[2];
    #pragma unroll
    for (int mi = 0; mi < 2; mi++) {
        int r = m0 + mi * 16 + (lane & 15);
        aOff[mi] = r * 128; aKey[mi] = (r & 7) << 4;
    }
    #pragma unroll
    for (int pi = 0; pi < 2; pi++) {
        int r = n0w + pi * 16 + ((lane >> 4) << 3) + (lane & 7);
        bOff[pi] = r * 128; bKey[pi] = (r & 7) << 4;
    }
    const uint32_t aK = (lane >> 4) * 16;
    const uint32_t bK = ((lane >> 3) & 1) * 16;

    auto stage = [&](int c, int buf) {
        const uint32_t base = sb + buf * SMB;
        #pragma unroll
        for (int it = 0; it < 4; it++) {
            int t = tid + it * 256;
            int row = t >> 3, seg = t & 7;
            size_t gidx = (size_t)(bm + row) * Cdim + c * 64 + seg * 8;
            uint32_t off = row * 128 + ((seg * 16) ^ ((row & 7) << 4));
            cp_async16(base + SM_A_HI + off, Ah + gidx);
            cp_async16(base + SM_A_LO + off, Al + gidx);
        }
        #pragma unroll
        for (int it = 0; it < 2; it++) {
            int t = tid + it * 256;
            int row = t >> 3, seg = t & 7;
            size_t gidx = (size_t)(bn + row) * Cdim + c * 64 + seg * 8;
            uint32_t off = row * 128 + ((seg * 16) ^ ((row & 7) << 4));
            cp_async16(base + SM_B_HI + off, S.wh + gidx);
            cp_async16(base + SM_B_LO + off, S.wl + gidx);
        }
    };

    stage(0, 0);
    CP_COMMIT();

    for (int c = 0; c < 4; c++) {
        if (c + 1 < 4) {
            stage(c + 1, (c + 1) & 1);
            CP_COMMIT();
            CP_WAIT(1);
        } else {
            CP_WAIT(0);
        }
        __syncthreads();
        const uint32_t bufb = sb + (c & 1) * SMB;

        #pragma unroll
        for (int ks = 0; ks < 4; ks++) {
            const uint32_t ka = ks * 32 + aK;
            const uint32_t kb = ks * 32 + bK;
            uint32_t ah[2][4], al[2][4], bh2[2][4], bl2[2][4];
            #pragma unroll
            for (int mi = 0; mi < 2; mi++) {
                ldsm4(ah[mi], bufb + SM_A_HI + aOff[mi] + (ka ^ aKey[mi]));
                ldsm4(al[mi], bufb + SM_A_LO + aOff[mi] + (ka ^ aKey[mi]));
            }
            #pragma unroll
            for (int pi = 0; pi < 2; pi++) {
                ldsm4(bh2[pi], bufb + SM_B_HI + bOff[pi] + (kb ^ bKey[pi]));
                ldsm4(bl2[pi], bufb + SM_B_LO + bOff[pi] + (kb ^ bKey[pi]));
            }
            #pragma unroll
            for (int mi = 0; mi < 2; mi++)
                #pragma unroll
                for (int ni = 0; ni < 4; ni++) {
                    const uint32_t* bh_f = &bh2[ni >> 1][(ni & 1) * 2];
                    const uint32_t* bl_f = &bl2[ni >> 1][(ni & 1) * 2];
                    mma16816(acc[mi][ni], ah[mi], bh_f);
                    mma16816(acc[mi][ni], al[mi], bh_f);
                    mma16816(acc[mi][ni], ah[mi], bl_f);
                }
        }
        __syncthreads();
    }

    const int lane4 = lane >> 2;
    const int col2 = (lane & 3) * 2;
    #pragma unroll
    for (int mi = 0; mi < 2; mi++) {
        #pragma unroll
        for (int half = 0; half < 2; half++) {
            const int row = bm + m0 + mi * 16 + lane4 + half * 8;
            const int b2 = row >> 14;
            const int rx = (row >> 7) & 127;
            const int ry = row & 127;
            const int xx = mode ? ry : rx;
            const int yy = mode ? rx : ry;
            #pragma unroll
            for (int ni = 0; ni < 4; ni++) {
                int cg = bn + n0w + ni * 8 + col2;
                if (cg < QKVW) {
                    int part = cg >> 8, hh = (cg >> 5) & 7, dd = cg & 31;
                    __nv_bfloat16 *ph, *pl;
                    if (part == 0)      { ph = S.qh; pl = S.ql; }
                    else if (part == 1) { ph = S.kh; pl = S.kl; }
                    else                { ph = S.vh; pl = S.vl; }
                    float sc = (part == 0) ? SCALE : 1.0f;
                    int px = xx, py = yy;
                    if (mode == 0 && part == 0) { px = yy; py = xx; }  // Q-in transposed
                    size_t pb = ((((size_t)b2 * Hdim + hh) * Ndim + px) * Ndim + py) * Ddim + dd;
                    float ox = (acc[mi][ni][half * 2 + 0] + S.bias[part * 256 + dd * 8 + hh]) * sc;
                    float oy = (acc[mi][ni][half * 2 + 1] + S.bias[part * 256 + (dd + 1) * 8 + hh]) * sc;
                    uint32_t hi, lo;
                    split2(ox, oy, hi, lo);
                    *(uint32_t*)&ph[pb] = hi;
                    *(uint32_t*)&pl[pb] = lo;
                } else if (cg < QKVW + 8) {
                    int h = cg - QKVW;   // even
                    float v0 = acc[mi][ni][half * 2 + 0] + S.bE[h]     + mask[(size_t)row * 8 + h];
                    float v1 = acc[mi][ni][half * 2 + 1] + S.bE[h + 1] + mask[(size_t)row * 8 + h + 1];
                    if (mode == 0) {
                        S.bp[(((size_t)(b2 * Hdim + h))     * Ndim + rx) * Ndim + ry] = v0;
                        S.bp[(((size_t)(b2 * Hdim + h + 1)) * Ndim + rx) * Ndim + ry] = v1;
                    } else {
                        S.bp[(((size_t)(b2 * Hdim + h))     * Ndim + ry) * Ndim + rx] = v0;
                        S.bp[(((size_t)(b2 * Hdim + h + 1)) * Ndim + ry) * Ndim + rx] = v1;
                    }
                }
            }
        }
    }
}

// ======================= out-GEMM (K=512, N=256, cp.async) =================
__global__ __launch_bounds__(256) void mma_gemm_out(
    const __nv_bfloat16* __restrict__ Ah, const __nv_bfloat16* __restrict__ Al,
    const __nv_bfloat16* __restrict__ Bh, const __nv_bfloat16* __restrict__ Bl,
    const float* __restrict__ bias, float* __restrict__ outf)
{
    extern __shared__ __align__(1024) char smem[];
    const uint32_t sb = smem_u32(smem);
    const int tid = threadIdx.x;
    const int wid = tid >> 5, lane = tid & 31;
    const int bm = blockIdx.x * 128;
    const int bn = blockIdx.y * 64;
    const int K = 2 * Cdim;
    const int m0 = (wid & 3) * 32;
    const int n0w = (wid >> 2) * 32;

    float acc[2][4][4];
    #pragma unroll
    for (int a = 0; a < 2; a++)
        #pragma unroll
        for (int b = 0; b < 4; b++)
            #pragma unroll
            for (int cc = 0; cc < 4; cc++) acc[a][b][cc] = 0.f;

    uint32_t aOff[2], aKey[2], bOff[2], bKey[2];
    #pragma unroll
    for (int mi = 0; mi < 2; mi++) {
        int r = m0 + mi * 16 + (lane & 15);
        aOff[mi] = r * 128; aKey[mi] = (r & 7) << 4;
    }
    #pragma unroll
    for (int pi = 0; pi < 2; pi++) {
        int r = n0w + pi * 16 + ((lane >> 4) << 3) + (lane & 7);
        bOff[pi] = r * 128; bKey[pi] = (r & 7) << 4;
    }
    const uint32_t aK = (lane >> 4) * 16;
    const uint32_t bK = ((lane >> 3) & 1) * 16;

    auto stage = [&](int c, int buf) {
        const uint32_t base = sb + buf * SMB;
        #pragma unroll
        for (int it = 0; it < 4; it++) {
            int t = tid + it * 256;
            int row = t >> 3, seg = t & 7;
            size_t gidx = (size_t)(bm + row) * K + c * 64 + seg * 8;
            uint32_t off = row * 128 + ((seg * 16) ^ ((row & 7) << 4));
            cp_async16(base + SM_A_HI + off, Ah + gidx);
            cp_async16(base + SM_A_LO + off, Al + gidx);
        }
        #pragma unroll
        for (int it = 0; it < 2; it++) {
            int t = tid + it * 256;
            int row = t >> 3, seg = t & 7;
            size_t gidx = (size_t)(bn + row) * K + c * 64 + seg * 8;
            uint32_t off = row * 128 + ((seg * 16) ^ ((row & 7) << 4));
            cp_async16(base + SM_B_HI + off, Bh + gidx);
            cp_async16(base + SM_B_LO + off, Bl + gidx);
        }
    };

    stage(0, 0);
    CP_COMMIT();

    for (int c = 0; c < 8; c++) {
        if (c + 1 < 8) {
            stage(c + 1, (c + 1) & 1);
            CP_COMMIT();
            CP_WAIT(1);
        } else {
            CP_WAIT(0);
        }
        __syncthreads();
        const uint32_t bufb = sb + (c & 1) * SMB;

        #pragma unroll
        for (int ks = 0; ks < 4; ks++) {
            const uint32_t ka = ks * 32 + aK;
            const uint32_t kb = ks * 32 + bK;
            uint32_t ah[2][4], al[2][4], bh2[2][4], bl2[2][4];
            #pragma unroll
            for (int mi = 0; mi < 2; mi++) {
                ldsm4(ah[mi], bufb + SM_A_HI + aOff[mi] + (ka ^ aKey[mi]));
                ldsm4(al[mi], bufb + SM_A_LO + aOff[mi] + (ka ^ aKey[mi]));
            }
            #pragma unroll
            for (int pi = 0; pi < 2; pi++) {
                ldsm4(bh2[pi], bufb + SM_B_HI + bOff[pi] + (kb ^ bKey[pi]));
                ldsm4(bl2[pi], bufb + SM_B_LO + bOff[pi] + (kb ^ bKey[pi]));
            }
            #pragma unroll
            for (int mi = 0; mi < 2; mi++)
                #pragma unroll
                for (int ni = 0; ni < 4; ni++) {
                    const uint32_t* bh_f = &bh2[ni >> 1][(ni & 1) * 2];
                    const uint32_t* bl_f = &bl2[ni >> 1][(ni & 1) * 2];
                    mma16816(acc[mi][ni], ah[mi], bh_f);
                    mma16816(acc[mi][ni], al[mi], bh_f);
                    mma16816(acc[mi][ni], ah[mi], bl_f);
                }
        }
        __syncthreads();
    }

    const int lane4 = lane >> 2;
    const int col2 = (lane & 3) * 2;
    #pragma unroll
    for (int mi = 0; mi < 2; mi++) {
        #pragma unroll
        for (int half = 0; half < 2; half++) {
            const int row = bm + m0 + mi * 16 + lane4 + half * 8;
            const int b2 = row >> 14;
            const int j2 = (row >> 7) & 127;
            const int i2 = row & 127;
            size_t ob = ((size_t)((b2 * Ndim + i2) * Ndim + j2)) * Cdim;
            #pragma unroll
            for (int ni = 0; ni < 4; ni++) {
                int cg = bn + n0w + ni * 8 + col2;
                float2 o;
                o.x = acc[mi][ni][half * 2 + 0] + bias[cg];
                o.y = acc[mi][ni][half * 2 + 1] + bias[cg + 1];
                *(float2*)&outf[ob + cg] = o;
            }
        }
    }
}

// ======================= HMMA attention ====================================
#define AT_Q 0
#define AT_K 20480
#define AT_V 40960
#define AT_LO 10240
#define AT_SMEM 61440

__global__ __launch_bounds__(256) void attn_mma(
    const __nv_bfloat16* __restrict__ Qinh, const __nv_bfloat16* __restrict__ Qinl,
    const __nv_bfloat16* __restrict__ Kinh, const __nv_bfloat16* __restrict__ Kinl,
    const __nv_bfloat16* __restrict__ Vinh, const __nv_bfloat16* __restrict__ Vinl,
    const __nv_bfloat16* __restrict__ Qouth, const __nv_bfloat16* __restrict__ Qoutl,
    const __nv_bfloat16* __restrict__ Kouth, const __nv_bfloat16* __restrict__ Koutl,
    const __nv_bfloat16* __restrict__ Vouth, const __nv_bfloat16* __restrict__ Voutl,
    const float* __restrict__ bias_in, const float* __restrict__ bias_out,
    __nv_bfloat16* __restrict__ vah, __nv_bfloat16* __restrict__ val)
{
    extern __shared__ __align__(128) char sm[];
    const uint32_t sb = smem_u32(sm);
    const int j = blockIdx.x;
    const int bh = blockIdx.y;
    const int pass = blockIdx.z;
    const int tid = threadIdx.x;
    const int wid = tid >> 5, lane = tid & 31;

    const size_t pbase = ((size_t)(bh * Ndim + j)) * (Ndim * Ddim);

    // ---- stage bf16 hi/lo planes -> smem (pure copy) ----
    {
        const int r = tid & 127;
        const int half = tid >> 7;
        const __nv_bfloat16* srcs[6];
        if (pass) {
            srcs[0] = Qouth; srcs[1] = Qoutl; srcs[2] = Kouth;
            srcs[3] = Koutl; srcs[4] = Vouth; srcs[5] = Voutl;
        } else {
            srcs[0] = Qinh; srcs[1] = Qinl; srcs[2] = Kinh;
            srcs[3] = Kinl; srcs[4] = Vinh; srcs[5] = Vinl;
        }
        const uint32_t dsto[6] = {AT_Q, AT_Q + AT_LO, AT_K, AT_K + AT_LO, AT_V, AT_V + AT_LO};
        const int eoff = r * 32 + half * 16;
        #pragma unroll
        for (int t = 0; t < 6; t++) {
            const uint4* s4 = (const uint4*)(srcs[t] + pbase + eoff);
            char* d = sm + dsto[t] + r * 80 + half * 32;
            *(uint4*)d = s4[0];
            *(uint4*)(d + 16) = s4[1];
        }
    }
    __syncthreads();

    const int m0 = wid * 16;

    // ---- S = Q K^T (3-term hi/lo) ----
    float accS[16][4];
    #pragma unroll
    for (int n = 0; n < 16; n++)
        #pragma unroll
        for (int c = 0; c < 4; c++) accS[n][c] = 0.f;

    #pragma unroll
    for (int kc = 0; kc < 2; kc++) {
        uint32_t qaddr = sb + AT_Q + (m0 + (lane & 15)) * 80 + kc * 32 + (lane >> 4) * 16;
        uint32_t qh[4], ql[4];
        ldsm4(qh, qaddr);
        ldsm4(ql, qaddr + AT_LO);
        #pragma unroll
        for (int pi = 0; pi < 8; pi++) {
            uint32_t kaddr = sb + AT_K + (pi * 16 + ((lane >> 4) << 3) + (lane & 7)) * 80
                           + kc * 32 + ((lane >> 3) & 1) * 16;
            uint32_t kh[4], kl[4];
            ldsm4(kh, kaddr);
            ldsm4(kl, kaddr + AT_LO);
            #pragma unroll
            for (int t = 0; t < 2; t++) {
                mma16816(accS[2 * pi + t], qh, &kh[t * 2]);
                mma16816(accS[2 * pi + t], ql, &kh[t * 2]);
                mma16816(accS[2 * pi + t], qh, &kl[t * 2]);
            }
        }
    }

    // ---- bias + softmax ----
    {
        const float* bb = (pass ? bias_out : bias_in) + (size_t)bh * Ndim * Ndim;
        const int r0 = m0 + (lane >> 2);
        const int r1 = r0 + 8;
        const int c0 = (lane & 3) * 2;
        #pragma unroll
        for (int ni = 0; ni < 16; ni++) {
            float2 b0 = *(const float2*)(bb + r0 * Ndim + ni * 8 + c0);
            float2 b1 = *(const float2*)(bb + r1 * Ndim + ni * 8 + c0);
            accS[ni][0] += b0.x; accS[ni][1] += b0.y;
            accS[ni][2] += b1.x; accS[ni][3] += b1.y;
        }
        float mx0 = -1e30f, mx1 = -1e30f;
        #pragma unroll
        for (int ni = 0; ni < 16; ni++) {
            mx0 = fmaxf(mx0, fmaxf(accS[ni][0], accS[ni][1]));
            mx1 = fmaxf(mx1, fmaxf(accS[ni][2], accS[ni][3]));
        }
        mx0 = fmaxf(mx0, __shfl_xor_sync(0xffffffffu, mx0, 1));
        mx0 = fmaxf(mx0, __shfl_xor_sync(0xffffffffu, mx0, 2));
        mx1 = fmaxf(mx1, __shfl_xor_sync(0xffffffffu, mx1, 1));
        mx1 = fmaxf(mx1, __shfl_xor_sync(0xffffffffu, mx1, 2));
        float s0 = 0.f, s1 = 0.f;
        #pragma unroll
        for (int ni = 0; ni < 16; ni++) {
            accS[ni][0] = __expf(accS[ni][0] - mx0);
            accS[ni][1] = __expf(accS[ni][1] - mx0);
            accS[ni][2] = __expf(accS[ni][2] - mx1);
            accS[ni][3] = __expf(accS[ni][3] - mx1);
            s0 += accS[ni][0] + accS[ni][1];
            s1 += accS[ni][2] + accS[ni][3];
        }
        s0 += __shfl_xor_sync(0xffffffffu, s0, 1);
        s0 += __shfl_xor_sync(0xffffffffu, s0, 2);
        s1 += __shfl_xor_sync(0xffffffffu, s1, 1);
        s1 += __shfl_xor_sync(0xffffffffu, s1, 2);

        // ---- O = P V (3-term hi/lo) ----
        float accO[4][4];
        #pragma unroll
        for (int n = 0; n < 4; n++)
            #pragma unroll
            for (int c = 0; c < 4; c++) accO[n][c] = 0.f;

        #pragma unroll
        for (int kc = 0; kc < 8; kc++) {
            uint32_t ph[4], pl[4];
            split2(accS[2 * kc][0], accS[2 * kc][1], ph[0], pl[0]);
            split2(accS[2 * kc][2], accS[2 * kc][3], ph[1], pl[1]);
            split2(accS[2 * kc + 1][0], accS[2 * kc + 1][1], ph[2], pl[2]);
            split2(accS[2 * kc + 1][2], accS[2 * kc + 1][3], ph[3], pl[3]);
            #pragma unroll
            for (int dh = 0; dh < 2; dh++) {
                uint32_t vaddr = sb + AT_V + (kc * 16 + ((lane >> 3) & 1) * 8 + (lane & 7)) * 80
                               + dh * 32 + (lane >> 4) * 16;
                uint32_t vh4[4], vl4[4];
                ldsm4t(vh4, vaddr);
                ldsm4t(vl4, vaddr + AT_LO);
                #pragma unroll
                for (int t = 0; t < 2; t++) {
                    mma16816(accO[dh * 2 + t], ph, &vh4[t * 2]);
                    mma16816(accO[dh * 2 + t], pl, &vh4[t * 2]);
                    mma16816(accO[dh * 2 + t], ph, &vl4[t * 2]);
                }
            }
        }

        // ---- normalize + write va (bf16 hi/lo) ----
        const float inv0 = 1.0f / s0;
        const float inv1 = 1.0f / s1;
        const int b2 = bh >> 3, h = bh & 7;
        const size_t R0 = (size_t)(b2 * Ndim + j) * Ndim;
        const int cb = (pass * 8 + h) * 32;
        #pragma unroll
        for (int nd = 0; nd < 4; nd++) {
            uint32_t hi, lo;
            split2(accO[nd][0] * inv0, accO[nd][1] * inv0, hi, lo);
            size_t idx = (R0 + r0) * (2 * Cdim) + cb + nd * 8 + c0;
            *(uint32_t*)&vah[idx] = hi;
            *(uint32_t*)&val[idx] = lo;
            split2(accO[nd][2] * inv1, accO[nd][3] * inv1, hi, lo);
            idx = (R0 + r1) * (2 * Cdim) + cb + nd * 8 + c0;
            *(uint32_t*)&vah[idx] = hi;
            *(uint32_t*)&val[idx] = lo;
        }
    }
}

// ======================= launcher ==========================================
extern "C" void kernel_launch(void* const* d_in, const int* in_sizes, int n_in,
                              void* d_out, int out_size)
{
    (void)in_sizes; (void)n_in; (void)out_size;
    const float* e        = (const float*)d_in[0];
    const float* mask     = (const float*)d_in[1];
    const float* ln_g     = (const float*)d_in[2];
    const float* ln_b     = (const float*)d_in[3];
    const float* W_qkv_in = (const float*)d_in[4];
    const float* b_qkv_in = (const float*)d_in[5];
    const float* W_E_in   = (const float*)d_in[6];
    const float* b_E_in   = (const float*)d_in[7];
    const float* W_qkv_out= (const float*)d_in[8];
    const float* b_qkv_out= (const float*)d_in[9];
    const float* W_E_out  = (const float*)d_in[10];
    const float* b_E_out  = (const float*)d_in[11];
    const float* W_O      = (const float*)d_in[12];
    const float* b_O      = (const float*)d_in[13];

    __nv_bfloat16 *p_ahi, *p_alo, *p_winh, *p_winl, *p_wouth, *p_woutl, *p_woh, *p_wol, *p_vah, *p_val;
    __nv_bfloat16 *pQih, *pQil, *pKih, *pKil, *pVih, *pVil, *pQoh, *pQol, *pKoh, *pKol, *pVoh, *pVol;
    float *p_bin, *p_bout;
    cudaGetSymbolAddress((void**)&p_ahi,  g_ahi);
    cudaGetSymbolAddress((void**)&p_alo,  g_alo);
    cudaGetSymbolAddress((void**)&p_winh, g_win_hi);
    cudaGetSymbolAddress((void**)&p_winl, g_win_lo);
    cudaGetSymbolAddress((void**)&p_wouth, g_wout_hi);
    cudaGetSymbolAddress((void**)&p_woutl, g_wout_lo);
    cudaGetSymbolAddress((void**)&p_woh,  g_wo_hi);
    cudaGetSymbolAddress((void**)&p_wol,  g_wo_lo);
    cudaGetSymbolAddress((void**)&pQih, g_Qinh);  cudaGetSymbolAddress((void**)&pQil, g_Qinl);
    cudaGetSymbolAddress((void**)&pKih, g_Kinh);  cudaGetSymbolAddress((void**)&pKil, g_Kinl);
    cudaGetSymbolAddress((void**)&pVih, g_Vinh);  cudaGetSymbolAddress((void**)&pVil, g_Vinl);
    cudaGetSymbolAddress((void**)&pQoh, g_Qouth); cudaGetSymbolAddress((void**)&pQol, g_Qoutl);
    cudaGetSymbolAddress((void**)&pKoh, g_Kouth); cudaGetSymbolAddress((void**)&pKol, g_Koutl);
    cudaGetSymbolAddress((void**)&pVoh, g_Vouth); cudaGetSymbolAddress((void**)&pVol, g_Voutl);
    cudaGetSymbolAddress((void**)&p_bin,  g_bias_in);
    cudaGetSymbolAddress((void**)&p_bout, g_bias_out);
    cudaGetSymbolAddress((void**)&p_vah,  g_vahi);
    cudaGetSymbolAddress((void**)&p_val,  g_valo);

    cudaFuncSetAttribute(mma_gemm_qkv, cudaFuncAttributeMaxDynamicSharedMemorySize, SM_TOTAL);
    cudaFuncSetAttribute(mma_gemm_out, cudaFuncAttributeMaxDynamicSharedMemorySize, SM_TOTAL);
    cudaFuncSetAttribute(attn_mma, cudaFuncAttributeMaxDynamicSharedMemorySize, AT_SMEM);

    convert_wqkv<<<NEXT, Cdim>>>(W_qkv_in,  W_E_in,  p_winh,  p_winl);
    convert_wqkv<<<NEXT, Cdim>>>(W_qkv_out, W_E_out, p_wouth, p_woutl);
    convert_wo<<<Cdim, 2 * Cdim>>>(W_O, p_woh, p_wol);

    ln_kernel<<<ROWS / 8, 256>>>(e, ln_g, ln_b, p_ahi, p_alo);

    QkvSet s0 = { p_winh,  p_winl,  b_qkv_in,  b_E_in,
                  pQih, pQil, pKih, pKil, pVih, pVil, p_bin };
    QkvSet s1 = { p_wouth, p_woutl, b_qkv_out, b_E_out,
                  pQoh, pQol, pKoh, pKol, pVoh, pVol, p_bout };

    mma_gemm_qkv<<<dim3(ROWS / 128, NEXT / 64, 2), 256, SM_TOTAL>>>(
        p_ahi, p_alo, mask, s0, s1);

    attn_mma<<<dim3(Ndim, Bdim * Hdim, 2), 256, AT_SMEM>>>(
        pQih, pQil, pKih, pKil, pVih, pVil,
        pQoh, pQol, pKoh, pKol, pVoh, pVol,
        p_bin, p_bout, p_vah, p_val);

    mma_gemm_out<<<dim3(ROWS / 128, Cdim / 64), 256, SM_TOTAL>>>(
        p_vah, p_val, p_woh, p_wol, b_O, (float*)d_out);
}

// round 17
// speedup vs baseline: 4.5941x; 1.0101x over previous
#include <cuda_runtime.h>
#include <cuda_bf16.h>
#include <cstdint>
#include <math.h>

#define Bdim 2
#define Ndim 128
#define Cdim 256
#define Hdim 8
#define Ddim 32
#define ROWS (Bdim*Ndim*Ndim)          // 32768
#define QKVW (3*Cdim)                   // 768
#define NEXT (QKVW + 64)                // 832 = qkv + E tile
#define SCALE 0.17677669529663687f
#define LN_EPS 1e-5f
#define PLANE_ELEMS (Bdim*Hdim*Ndim*Ndim*Ddim)   // 8388608

// ======================= helpers ==========================================
__device__ __forceinline__ uint32_t smem_u32(const void* p) {
    uint32_t a;
    asm("{ .reg .u64 t; cvta.to.shared.u64 t, %1; cvt.u32.u64 %0, t; }" : "=r"(a) : "l"(p));
    return a;
}
__device__ __forceinline__ void ldsm4(uint32_t* r, uint32_t addr) {
    asm volatile("ldmatrix.sync.aligned.m8n8.x4.shared.b16 {%0,%1,%2,%3}, [%4];"
        : "=r"(r[0]), "=r"(r[1]), "=r"(r[2]), "=r"(r[3]) : "r"(addr));
}
__device__ __forceinline__ void ldsm4t(uint32_t* r, uint32_t addr) {
    asm volatile("ldmatrix.sync.aligned.m8n8.x4.trans.shared.b16 {%0,%1,%2,%3}, [%4];"
        : "=r"(r[0]), "=r"(r[1]), "=r"(r[2]), "=r"(r[3]) : "r"(addr));
}
__device__ __forceinline__ void mma16816(float* d, const uint32_t* a, const uint32_t* b) {
    asm volatile("mma.sync.aligned.m16n8k16.row.col.f32.bf16.bf16.f32 "
        "{%0,%1,%2,%3}, {%4,%5,%6,%7}, {%8,%9}, {%0,%1,%2,%3};"
        : "+f"(d[0]), "+f"(d[1]), "+f"(d[2]), "+f"(d[3])
        : "r"(a[0]), "r"(a[1]), "r"(a[2]), "r"(a[3]), "r"(b[0]), "r"(b[1]));
}
__device__ __forceinline__ void split2(float x, float y, uint32_t& hi, uint32_t& lo) {
    __nv_bfloat162 h = __floats2bfloat162_rn(x, y);
    float hx = __bfloat162float(h.x), hy = __bfloat162float(h.y);
    __nv_bfloat162 l = __floats2bfloat162_rn(x - hx, y - hy);
    hi = *(uint32_t*)&h;
    lo = *(uint32_t*)&l;
}
__device__ __forceinline__ void cp_async16(uint32_t saddr, const void* gaddr) {
    asm volatile("cp.async.cg.shared.global [%0], [%1], 16;" :: "r"(saddr), "l"(gaddr));
}
#define CP_COMMIT() asm volatile("cp.async.commit_group;")
#define CP_WAIT(n)  asm volatile("cp.async.wait_group %0;" :: "n"(n))

// ======================= scratch (device globals) ==========================
__device__ __align__(16) __nv_bfloat16 g_ahi[ROWS * Cdim];
__device__ __align__(16) __nv_bfloat16 g_alo[ROWS * Cdim];
__device__ __align__(16) __nv_bfloat16 g_win_hi[NEXT * Cdim];
__device__ __align__(16) __nv_bfloat16 g_win_lo[NEXT * Cdim];
__device__ __align__(16) __nv_bfloat16 g_wout_hi[NEXT * Cdim];
__device__ __align__(16) __nv_bfloat16 g_wout_lo[NEXT * Cdim];
__device__ __align__(16) __nv_bfloat16 g_wo_hi[Cdim * 2 * Cdim];
__device__ __align__(16) __nv_bfloat16 g_wo_lo[Cdim * 2 * Cdim];
__device__ __align__(16) __nv_bfloat16 g_Qinh[PLANE_ELEMS],  g_Qinl[PLANE_ELEMS];
__device__ __align__(16) __nv_bfloat16 g_Kinh[PLANE_ELEMS],  g_Kinl[PLANE_ELEMS];
__device__ __align__(16) __nv_bfloat16 g_Vinh[PLANE_ELEMS],  g_Vinl[PLANE_ELEMS];
__device__ __align__(16) __nv_bfloat16 g_Qouth[PLANE_ELEMS], g_Qoutl[PLANE_ELEMS];
__device__ __align__(16) __nv_bfloat16 g_Kouth[PLANE_ELEMS], g_Koutl[PLANE_ELEMS];
__device__ __align__(16) __nv_bfloat16 g_Vouth[PLANE_ELEMS], g_Voutl[PLANE_ELEMS];
__device__ __align__(16) float g_bias_in[Bdim * Hdim * Ndim * Ndim];   // [b,h,i,k]
__device__ __align__(16) float g_bias_out[Bdim * Hdim * Ndim * Ndim];  // [b,h,i,k]
__device__ __align__(16) __nv_bfloat16 g_vahi[ROWS * 2 * Cdim];
__device__ __align__(16) __nv_bfloat16 g_valo[ROWS * 2 * Cdim];

// ======================= per-pass parameter bundle =========================
struct QkvSet {
    const __nv_bfloat16 *wh, *wl;   // weights [NEXT][256]
    const float *bias;              // [768]
    const float *bE;                // [8]
    __nv_bfloat16 *qh, *ql, *kh, *kl, *vh, *vl;
    float *bp;                      // bias plane [b,h,i,k]
};

// ======================= weight converts ===================================
__global__ void convert_wqkv(const float* __restrict__ W, const float* __restrict__ WE,
                             __nv_bfloat16* __restrict__ th, __nv_bfloat16* __restrict__ tl)
{
    const int n = blockIdx.x;      // 0..831
    const int k = threadIdx.x;     // 0..255
    float w;
    if (n < QKVW) {
        int part = n >> 8, rem = n & 255;
        int h = rem >> 5, d = rem & 31;
        w = W[(size_t)k * QKVW + part * 256 + d * 8 + h];
    } else if (n < QKVW + 8) {
        w = WE[k * 8 + (n - QKVW)];
    } else {
        w = 0.f;
    }
    __nv_bfloat16 hi = __float2bfloat16(w);
    th[(size_t)n * Cdim + k] = hi;
    tl[(size_t)n * Cdim + k] = __float2bfloat16(w - __bfloat162float(hi));
}

__global__ void convert_wo(const float* __restrict__ W, __nv_bfloat16* __restrict__ th,
                           __nv_bfloat16* __restrict__ tl)
{
    const int n = blockIdx.x;      // 0..255
    const int k = threadIdx.x;     // 0..511
    int part = k >> 8, rem = k & 255;
    int h = rem >> 5, d = rem & 31;
    int orig_k = d * 16 + part * 8 + h;
    float w = W[(size_t)orig_k * Cdim + n];
    __nv_bfloat16 hi = __float2bfloat16(w);
    th[(size_t)n * 2 * Cdim + k] = hi;
    tl[(size_t)n * 2 * Cdim + k] = __float2bfloat16(w - __bfloat162float(hi));
}

// ======================= LayerNorm (warp per row) ==========================
__global__ __launch_bounds__(256) void ln_kernel(
    const float* __restrict__ e,
    const float* __restrict__ ln_g, const float* __restrict__ ln_b,
    __nv_bfloat16* __restrict__ ahi, __nv_bfloat16* __restrict__ alo)
{
    const int lane = threadIdx.x & 31;
    const int row = blockIdx.x * 8 + (threadIdx.x >> 5);
    const float4* er = (const float4*)(e + (size_t)row * Cdim);
    float4 a = er[lane];
    float4 b = er[lane + 32];

    float s = a.x + a.y + a.z + a.w + b.x + b.y + b.z + b.w;
    #pragma unroll
    for (int o = 16; o; o >>= 1) s += __shfl_xor_sync(0xffffffffu, s, o);
    const float mu = s * (1.0f / Cdim);

    float dx[8] = {a.x - mu, a.y - mu, a.z - mu, a.w - mu,
                   b.x - mu, b.y - mu, b.z - mu, b.w - mu};
    float v = 0.f;
    #pragma unroll
    for (int q = 0; q < 8; q++) v += dx[q] * dx[q];
    #pragma unroll
    for (int o = 16; o; o >>= 1) v += __shfl_xor_sync(0xffffffffu, v, o);
    const float rs = rsqrtf(v * (1.0f / Cdim) + LN_EPS);

    const float4* gp = (const float4*)ln_g;
    const float4* bp = (const float4*)ln_b;
    float4 g1 = gp[lane], g2 = gp[lane + 32];
    float4 b1 = bp[lane], b2 = bp[lane + 32];
    float y[8];
    y[0] = dx[0] * rs * g1.x + b1.x; y[1] = dx[1] * rs * g1.y + b1.y;
    y[2] = dx[2] * rs * g1.z + b1.z; y[3] = dx[3] * rs * g1.w + b1.w;
    y[4] = dx[4] * rs * g2.x + b2.x; y[5] = dx[5] * rs * g2.y + b2.y;
    y[6] = dx[6] * rs * g2.z + b2.z; y[7] = dx[7] * rs * g2.w + b2.w;

    uint32_t h01, l01, h23, l23, h45, l45, h67, l67;
    split2(y[0], y[1], h01, l01); split2(y[2], y[3], h23, l23);
    split2(y[4], y[5], h45, l45); split2(y[6], y[7], h67, l67);
    uint2* oh = (uint2*)(ahi + (size_t)row * Cdim);
    uint2* ol = (uint2*)(alo + (size_t)row * Cdim);
    oh[lane]      = make_uint2(h01, h23);
    ol[lane]      = make_uint2(l01, l23);
    oh[lane + 32] = make_uint2(h45, h67);
    ol[lane + 32] = make_uint2(l45, l67);
}

// ======================= GEMM smem layout (per buffer) =====================
#define SM_A_HI 0
#define SM_A_LO 16384
#define SM_B_HI 32768
#define SM_B_LO 40960
#define SMB     49152
#define SM_TOTAL (2 * SMB)

// ======================= qkv+E GEMM (both passes, grid.z=2, cp.async) ======
// grid: x = bn (fast, 13) -> A tile L2-reused across all bn; y = bm (256); z = pass
__global__ __launch_bounds__(256) void mma_gemm_qkv(
    const __nv_bfloat16* __restrict__ Ah, const __nv_bfloat16* __restrict__ Al,
    const float* __restrict__ mask, QkvSet s0, QkvSet s1)
{
    extern __shared__ __align__(1024) char smem[];
    const uint32_t sb = smem_u32(smem);
    const int mode = blockIdx.z;
    const QkvSet S = mode ? s1 : s0;
    const int tid = threadIdx.x;
    const int wid = tid >> 5, lane = tid & 31;
    const int bm = blockIdx.y * 128;
    const int bn = blockIdx.x * 64;
    const int m0 = (wid & 3) * 32;
    const int n0w = (wid >> 2) * 32;

    float acc[2][4][4];
    #pragma unroll
    for (int a = 0; a < 2; a++)
        #pragma unroll
        for (int b = 0; b < 4; b++)
            #pragma unroll
            for (int cc = 0; cc < 4; cc++) acc[a][b][cc] = 0.f;

    uint32_t aOff[2], aKey[2], bOff[2], bKey[2];
    #pragma unroll
    for (int mi = 0; mi < 2; mi++) {
        int r = m0 + mi * 16 + (lane & 15);
        aOff[mi] = r * 128; aKey[mi] = (r & 7) << 4;
    }
    #pragma unroll
    for (int pi = 0; pi < 2; pi++) {
        int r = n0w + pi * 16 + ((lane >> 4) << 3) + (lane & 7);
        bOff[pi] = r * 128; bKey[pi] = (r & 7) << 4;
    }
    const uint32_t aK = (lane >> 4) * 16;
    const uint32_t bK = ((lane >> 3) & 1) * 16;

    auto stage = [&](int c, int buf) {
        const uint32_t base = sb + buf * SMB;
        #pragma unroll
        for (int it = 0; it < 4; it++) {
            int t = tid + it * 256;
            int row = t >> 3, seg = t & 7;
            size_t gidx = (size_t)(bm + row) * Cdim + c * 64 + seg * 8;
            uint32_t off = row * 128 + ((seg * 16) ^ ((row & 7) << 4));
            cp_async16(base + SM_A_HI + off, Ah + gidx);
            cp_async16(base + SM_A_LO + off, Al + gidx);
        }
        #pragma unroll
        for (int it = 0; it < 2; it++) {
            int t = tid + it * 256;
            int row = t >> 3, seg = t & 7;
            size_t gidx = (size_t)(bn + row) * Cdim + c * 64 + seg * 8;
            uint32_t off = row * 128 + ((seg * 16) ^ ((row & 7) << 4));
            cp_async16(base + SM_B_HI + off, S.wh + gidx);
            cp_async16(base + SM_B_LO + off, S.wl + gidx);
        }
    };

    stage(0, 0);
    CP_COMMIT();

    for (int c = 0; c < 4; c++) {
        if (c + 1 < 4) {
            stage(c + 1, (c + 1) & 1);
            CP_COMMIT();
            CP_WAIT(1);
        } else {
            CP_WAIT(0);
        }
        __syncthreads();
        const uint32_t bufb = sb + (c & 1) * SMB;

        #pragma unroll
        for (int ks = 0; ks < 4; ks++) {
            const uint32_t ka = ks * 32 + aK;
            const uint32_t kb = ks * 32 + bK;
            uint32_t ah[2][4], al[2][4], bh2[2][4], bl2[2][4];
            #pragma unroll
            for (int mi = 0; mi < 2; mi++) {
                ldsm4(ah[mi], bufb + SM_A_HI + aOff[mi] + (ka ^ aKey[mi]));
                ldsm4(al[mi], bufb + SM_A_LO + aOff[mi] + (ka ^ aKey[mi]));
            }
            #pragma unroll
            for (int pi = 0; pi < 2; pi++) {
                ldsm4(bh2[pi], bufb + SM_B_HI + bOff[pi] + (kb ^ bKey[pi]));
                ldsm4(bl2[pi], bufb + SM_B_LO + bOff[pi] + (kb ^ bKey[pi]));
            }
            #pragma unroll
            for (int mi = 0; mi < 2; mi++)
                #pragma unroll
                for (int ni = 0; ni < 4; ni++) {
                    const uint32_t* bh_f = &bh2[ni >> 1][(ni & 1) * 2];
                    const uint32_t* bl_f = &bl2[ni >> 1][(ni & 1) * 2];
                    mma16816(acc[mi][ni], ah[mi], bh_f);
                    mma16816(acc[mi][ni], al[mi], bh_f);
                    mma16816(acc[mi][ni], ah[mi], bl_f);
                }
        }
        __syncthreads();
    }

    const int lane4 = lane >> 2;
    const int col2 = (lane & 3) * 2;
    #pragma unroll
    for (int mi = 0; mi < 2; mi++) {
        #pragma unroll
        for (int half = 0; half < 2; half++) {
            const int row = bm + m0 + mi * 16 + lane4 + half * 8;
            const int b2 = row >> 14;
            const int rx = (row >> 7) & 127;
            const int ry = row & 127;
            const int xx = mode ? ry : rx;
            const int yy = mode ? rx : ry;
            #pragma unroll
            for (int ni = 0; ni < 4; ni++) {
                int cg = bn + n0w + ni * 8 + col2;
                if (cg < QKVW) {
                    int part = cg >> 8, hh = (cg >> 5) & 7, dd = cg & 31;
                    __nv_bfloat16 *ph, *pl;
                    if (part == 0)      { ph = S.qh; pl = S.ql; }
                    else if (part == 1) { ph = S.kh; pl = S.kl; }
                    else                { ph = S.vh; pl = S.vl; }
                    float sc = (part == 0) ? SCALE : 1.0f;
                    int px = xx, py = yy;
                    if (mode == 0 && part == 0) { px = yy; py = xx; }  // Q-in transposed
                    size_t pb = ((((size_t)b2 * Hdim + hh) * Ndim + px) * Ndim + py) * Ddim + dd;
                    float ox = (acc[mi][ni][half * 2 + 0] + S.bias[part * 256 + dd * 8 + hh]) * sc;
                    float oy = (acc[mi][ni][half * 2 + 1] + S.bias[part * 256 + (dd + 1) * 8 + hh]) * sc;
                    uint32_t hi, lo;
                    split2(ox, oy, hi, lo);
                    *(uint32_t*)&ph[pb] = hi;
                    *(uint32_t*)&pl[pb] = lo;
                } else if (cg < QKVW + 8) {
                    int h = cg - QKVW;   // even
                    float v0 = acc[mi][ni][half * 2 + 0] + S.bE[h]     + mask[(size_t)row * 8 + h];
                    float v1 = acc[mi][ni][half * 2 + 1] + S.bE[h + 1] + mask[(size_t)row * 8 + h + 1];
                    if (mode == 0) {
                        S.bp[(((size_t)(b2 * Hdim + h))     * Ndim + rx) * Ndim + ry] = v0;
                        S.bp[(((size_t)(b2 * Hdim + h + 1)) * Ndim + rx) * Ndim + ry] = v1;
                    } else {
                        S.bp[(((size_t)(b2 * Hdim + h))     * Ndim + ry) * Ndim + rx] = v0;
                        S.bp[(((size_t)(b2 * Hdim + h + 1)) * Ndim + ry) * Ndim + rx] = v1;
                    }
                }
            }
        }
    }
}

// ======================= out-GEMM (K=512, N=256, cp.async) =================
// grid: x = bn (fast, 4), y = bm (256)
__global__ __launch_bounds__(256) void mma_gemm_out(
    const __nv_bfloat16* __restrict__ Ah, const __nv_bfloat16* __restrict__ Al,
    const __nv_bfloat16* __restrict__ Bh, const __nv_bfloat16* __restrict__ Bl,
    const float* __restrict__ bias, float* __restrict__ outf)
{
    extern __shared__ __align__(1024) char smem[];
    const uint32_t sb = smem_u32(smem);
    const int tid = threadIdx.x;
    const int wid = tid >> 5, lane = tid & 31;
    const int bm = blockIdx.y * 128;
    const int bn = blockIdx.x * 64;
    const int K = 2 * Cdim;
    const int m0 = (wid & 3) * 32;
    const int n0w = (wid >> 2) * 32;

    float acc[2][4][4];
    #pragma unroll
    for (int a = 0; a < 2; a++)
        #pragma unroll
        for (int b = 0; b < 4; b++)
            #pragma unroll
            for (int cc = 0; cc < 4; cc++) acc[a][b][cc] = 0.f;

    uint32_t aOff[2], aKey[2], bOff[2], bKey[2];
    #pragma unroll
    for (int mi = 0; mi < 2; mi++) {
        int r = m0 + mi * 16 + (lane & 15);
        aOff[mi] = r * 128; aKey[mi] = (r & 7) << 4;
    }
    #pragma unroll
    for (int pi = 0; pi < 2; pi++) {
        int r = n0w + pi * 16 + ((lane >> 4) << 3) + (lane & 7);
        bOff[pi] = r * 128; bKey[pi] = (r & 7) << 4;
    }
    const uint32_t aK = (lane >> 4) * 16;
    const uint32_t bK = ((lane >> 3) & 1) * 16;

    auto stage = [&](int c, int buf) {
        const uint32_t base = sb + buf * SMB;
        #pragma unroll
        for (int it = 0; it < 4; it++) {
            int t = tid + it * 256;
            int row = t >> 3, seg = t & 7;
            size_t gidx = (size_t)(bm + row) * K + c * 64 + seg * 8;
            uint32_t off = row * 128 + ((seg * 16) ^ ((row & 7) << 4));
            cp_async16(base + SM_A_HI + off, Ah + gidx);
            cp_async16(base + SM_A_LO + off, Al + gidx);
        }
        #pragma unroll
        for (int it = 0; it < 2; it++) {
            int t = tid + it * 256;
            int row = t >> 3, seg = t & 7;
            size_t gidx = (size_t)(bn + row) * K + c * 64 + seg * 8;
            uint32_t off = row * 128 + ((seg * 16) ^ ((row & 7) << 4));
            cp_async16(base + SM_B_HI + off, Bh + gidx);
            cp_async16(base + SM_B_LO + off, Bl + gidx);
        }
    };

    stage(0, 0);
    CP_COMMIT();

    for (int c = 0; c < 8; c++) {
        if (c + 1 < 8) {
            stage(c + 1, (c + 1) & 1);
            CP_COMMIT();
            CP_WAIT(1);
        } else {
            CP_WAIT(0);
        }
        __syncthreads();
        const uint32_t bufb = sb + (c & 1) * SMB;

        #pragma unroll
        for (int ks = 0; ks < 4; ks++) {
            const uint32_t ka = ks * 32 + aK;
            const uint32_t kb = ks * 32 + bK;
            uint32_t ah[2][4], al[2][4], bh2[2][4], bl2[2][4];
            #pragma unroll
            for (int mi = 0; mi < 2; mi++) {
                ldsm4(ah[mi], bufb + SM_A_HI + aOff[mi] + (ka ^ aKey[mi]));
                ldsm4(al[mi], bufb + SM_A_LO + aOff[mi] + (ka ^ aKey[mi]));
            }
            #pragma unroll
            for (int pi = 0; pi < 2; pi++) {
                ldsm4(bh2[pi], bufb + SM_B_HI + bOff[pi] + (kb ^ bKey[pi]));
                ldsm4(bl2[pi], bufb + SM_B_LO + bOff[pi] + (kb ^ bKey[pi]));
            }
            #pragma unroll
            for (int mi = 0; mi < 2; mi++)
                #pragma unroll
                for (int ni = 0; ni < 4; ni++) {
                    const uint32_t* bh_f = &bh2[ni >> 1][(ni & 1) * 2];
                    const uint32_t* bl_f = &bl2[ni >> 1][(ni & 1) * 2];
                    mma16816(acc[mi][ni], ah[mi], bh_f);
                    mma16816(acc[mi][ni], al[mi], bh_f);
                    mma16816(acc[mi][ni], ah[mi], bl_f);
                }
        }
        __syncthreads();
    }

    const int lane4 = lane >> 2;
    const int col2 = (lane & 3) * 2;
    #pragma unroll
    for (int mi = 0; mi < 2; mi++) {
        #pragma unroll
        for (int half = 0; half < 2; half++) {
            const int row = bm + m0 + mi * 16 + lane4 + half * 8;
            const int b2 = row >> 14;
            const int j2 = (row >> 7) & 127;
            const int i2 = row & 127;
            size_t ob = ((size_t)((b2 * Ndim + i2) * Ndim + j2)) * Cdim;
            #pragma unroll
            for (int ni = 0; ni < 4; ni++) {
                int cg = bn + n0w + ni * 8 + col2;
                float2 o;
                o.x = acc[mi][ni][half * 2 + 0] + bias[cg];
                o.y = acc[mi][ni][half * 2 + 1] + bias[cg + 1];
                *(float2*)&outf[ob + cg] = o;
            }
        }
    }
}

// ======================= HMMA attention ====================================
#define AT_Q 0
#define AT_K 20480
#define AT_V 40960
#define AT_LO 10240
#define AT_SMEM 61440

__global__ __launch_bounds__(256) void attn_mma(
    const __nv_bfloat16* __restrict__ Qinh, const __nv_bfloat16* __restrict__ Qinl,
    const __nv_bfloat16* __restrict__ Kinh, const __nv_bfloat16* __restrict__ Kinl,
    const __nv_bfloat16* __restrict__ Vinh, const __nv_bfloat16* __restrict__ Vinl,
    const __nv_bfloat16* __restrict__ Qouth, const __nv_bfloat16* __restrict__ Qoutl,
    const __nv_bfloat16* __restrict__ Kouth, const __nv_bfloat16* __restrict__ Koutl,
    const __nv_bfloat16* __restrict__ Vouth, const __nv_bfloat16* __restrict__ Voutl,
    const float* __restrict__ bias_in, const float* __restrict__ bias_out,
    __nv_bfloat16* __restrict__ vah, __nv_bfloat16* __restrict__ val)
{
    extern __shared__ __align__(128) char sm[];
    const uint32_t sb = smem_u32(sm);
    const int j = blockIdx.x;
    const int bh = blockIdx.y;
    const int pass = blockIdx.z;
    const int tid = threadIdx.x;
    const int wid = tid >> 5, lane = tid & 31;

    const size_t pbase = ((size_t)(bh * Ndim + j)) * (Ndim * Ddim);

    // ---- stage bf16 hi/lo planes -> smem (pure copy) ----
    {
        const int r = tid & 127;
        const int half = tid >> 7;
        const __nv_bfloat16* srcs[6];
        if (pass) {
            srcs[0] = Qouth; srcs[1] = Qoutl; srcs[2] = Kouth;
            srcs[3] = Koutl; srcs[4] = Vouth; srcs[5] = Voutl;
        } else {
            srcs[0] = Qinh; srcs[1] = Qinl; srcs[2] = Kinh;
            srcs[3] = Kinl; srcs[4] = Vinh; srcs[5] = Vinl;
        }
        const uint32_t dsto[6] = {AT_Q, AT_Q + AT_LO, AT_K, AT_K + AT_LO, AT_V, AT_V + AT_LO};
        const int eoff = r * 32 + half * 16;
        #pragma unroll
        for (int t = 0; t < 6; t++) {
            const uint4* s4 = (const uint4*)(srcs[t] + pbase + eoff);
            char* d = sm + dsto[t] + r * 80 + half * 32;
            *(uint4*)d = s4[0];
            *(uint4*)(d + 16) = s4[1];
        }
    }
    __syncthreads();

    const int m0 = wid * 16;

    // ---- S = Q K^T (3-term hi/lo) ----
    float accS[16][4];
    #pragma unroll
    for (int n = 0; n < 16; n++)
        #pragma unroll
        for (int c = 0; c < 4; c++) accS[n][c] = 0.f;

    #pragma unroll
    for (int kc = 0; kc < 2; kc++) {
        uint32_t qaddr = sb + AT_Q + (m0 + (lane & 15)) * 80 + kc * 32 + (lane >> 4) * 16;
        uint32_t qh[4], ql[4];
        ldsm4(qh, qaddr);
        ldsm4(ql, qaddr + AT_LO);
        #pragma unroll
        for (int pi = 0; pi < 8; pi++) {
            uint32_t kaddr = sb + AT_K + (pi * 16 + ((lane >> 4) << 3) + (lane & 7)) * 80
                           + kc * 32 + ((lane >> 3) & 1) * 16;
            uint32_t kh[4], kl[4];
            ldsm4(kh, kaddr);
            ldsm4(kl, kaddr + AT_LO);
            #pragma unroll
            for (int t = 0; t < 2; t++) {
                mma16816(accS[2 * pi + t], qh, &kh[t * 2]);
                mma16816(accS[2 * pi + t], ql, &kh[t * 2]);
                mma16816(accS[2 * pi + t], qh, &kl[t * 2]);
            }
        }
    }

    // ---- bias + softmax ----
    {
        const float* bb = (pass ? bias_out : bias_in) + (size_t)bh * Ndim * Ndim;
        const int r0 = m0 + (lane >> 2);
        const int r1 = r0 + 8;
        const int c0 = (lane & 3) * 2;
        #pragma unroll
        for (int ni = 0; ni < 16; ni++) {
            float2 b0 = *(const float2*)(bb + r0 * Ndim + ni * 8 + c0);
            float2 b1 = *(const float2*)(bb + r1 * Ndim + ni * 8 + c0);
            accS[ni][0] += b0.x; accS[ni][1] += b0.y;
            accS[ni][2] += b1.x; accS[ni][3] += b1.y;
        }
        float mx0 = -1e30f, mx1 = -1e30f;
        #pragma unroll
        for (int ni = 0; ni < 16; ni++) {
            mx0 = fmaxf(mx0, fmaxf(accS[ni][0], accS[ni][1]));
            mx1 = fmaxf(mx1, fmaxf(accS[ni][2], accS[ni][3]));
        }
        mx0 = fmaxf(mx0, __shfl_xor_sync(0xffffffffu, mx0, 1));
        mx0 = fmaxf(mx0, __shfl_xor_sync(0xffffffffu, mx0, 2));
        mx1 = fmaxf(mx1, __shfl_xor_sync(0xffffffffu, mx1, 1));
        mx1 = fmaxf(mx1, __shfl_xor_sync(0xffffffffu, mx1, 2));
        float s0 = 0.f, s1 = 0.f;
        #pragma unroll
        for (int ni = 0; ni < 16; ni++) {
            accS[ni][0] = __expf(accS[ni][0] - mx0);
            accS[ni][1] = __expf(accS[ni][1] - mx0);
            accS[ni][2] = __expf(accS[ni][2] - mx1);
            accS[ni][3] = __expf(accS[ni][3] - mx1);
            s0 += accS[ni][0] + accS[ni][1];
            s1 += accS[ni][2] + accS[ni][3];
        }
        s0 += __shfl_xor_sync(0xffffffffu, s0, 1);
        s0 += __shfl_xor_sync(0xffffffffu, s0, 2);
        s1 += __shfl_xor_sync(0xffffffffu, s1, 1);
        s1 += __shfl_xor_sync(0xffffffffu, s1, 2);

        // ---- O = P V (3-term hi/lo) ----
        float accO[4][4];
        #pragma unroll
        for (int n = 0; n < 4; n++)
            #pragma unroll
            for (int c = 0; c < 4; c++) accO[n][c] = 0.f;

        #pragma unroll
        for (int kc = 0; kc < 8; kc++) {
            uint32_t ph[4], pl[4];
            split2(accS[2 * kc][0], accS[2 * kc][1], ph[0], pl[0]);
            split2(accS[2 * kc][2], accS[2 * kc][3], ph[1], pl[1]);
            split2(accS[2 * kc + 1][0], accS[2 * kc + 1][1], ph[2], pl[2]);
            split2(accS[2 * kc + 1][2], accS[2 * kc + 1][3], ph[3], pl[3]);
            #pragma unroll
            for (int dh = 0; dh < 2; dh++) {
                uint32_t vaddr = sb + AT_V + (kc * 16 + ((lane >> 3) & 1) * 8 + (lane & 7)) * 80
                               + dh * 32 + (lane >> 4) * 16;
                uint32_t vh4[4], vl4[4];
                ldsm4t(vh4, vaddr);
                ldsm4t(vl4, vaddr + AT_LO);
                #pragma unroll
                for (int t = 0; t < 2; t++) {
                    mma16816(accO[dh * 2 + t], ph, &vh4[t * 2]);
                    mma16816(accO[dh * 2 + t], pl, &vh4[t * 2]);
                    mma16816(accO[dh * 2 + t], ph, &vl4[t * 2]);
                }
            }
        }

        // ---- normalize + write va (bf16 hi/lo) ----
        const float inv0 = 1.0f / s0;
        const float inv1 = 1.0f / s1;
        const int b2 = bh >> 3, h = bh & 7;
        const size_t R0 = (size_t)(b2 * Ndim + j) * Ndim;
        const int cb = (pass * 8 + h) * 32;
        #pragma unroll
        for (int nd = 0; nd < 4; nd++) {
            uint32_t hi, lo;
            split2(accO[nd][0] * inv0, accO[nd][1] * inv0, hi, lo);
            size_t idx = (R0 + r0) * (2 * Cdim) + cb + nd * 8 + c0;
            *(uint32_t*)&vah[idx] = hi;
            *(uint32_t*)&val[idx] = lo;
            split2(accO[nd][2] * inv1, accO[nd][3] * inv1, hi, lo);
            idx = (R0 + r1) * (2 * Cdim) + cb + nd * 8 + c0;
            *(uint32_t*)&vah[idx] = hi;
            *(uint32_t*)&val[idx] = lo;
        }
    }
}

// ======================= launcher ==========================================
extern "C" void kernel_launch(void* const* d_in, const int* in_sizes, int n_in,
                              void* d_out, int out_size)
{
    (void)in_sizes; (void)n_in; (void)out_size;
    const float* e        = (const float*)d_in[0];
    const float* mask     = (const float*)d_in[1];
    const float* ln_g     = (const float*)d_in[2];
    const float* ln_b     = (const float*)d_in[3];
    const float* W_qkv_in = (const float*)d_in[4];
    const float* b_qkv_in = (const float*)d_in[5];
    const float* W_E_in   = (const float*)d_in[6];
    const float* b_E_in   = (const float*)d_in[7];
    const float* W_qkv_out= (const float*)d_in[8];
    const float* b_qkv_out= (const float*)d_in[9];
    const float* W_E_out  = (const float*)d_in[10];
    const float* b_E_out  = (const float*)d_in[11];
    const float* W_O      = (const float*)d_in[12];
    const float* b_O      = (const float*)d_in[13];

    __nv_bfloat16 *p_ahi, *p_alo, *p_winh, *p_winl, *p_wouth, *p_woutl, *p_woh, *p_wol, *p_vah, *p_val;
    __nv_bfloat16 *pQih, *pQil, *pKih, *pKil, *pVih, *pVil, *pQoh, *pQol, *pKoh, *pKol, *pVoh, *pVol;
    float *p_bin, *p_bout;
    cudaGetSymbolAddress((void**)&p_ahi,  g_ahi);
    cudaGetSymbolAddress((void**)&p_alo,  g_alo);
    cudaGetSymbolAddress((void**)&p_winh, g_win_hi);
    cudaGetSymbolAddress((void**)&p_winl, g_win_lo);
    cudaGetSymbolAddress((void**)&p_wouth, g_wout_hi);
    cudaGetSymbolAddress((void**)&p_woutl, g_wout_lo);
    cudaGetSymbolAddress((void**)&p_woh,  g_wo_hi);
    cudaGetSymbolAddress((void**)&p_wol,  g_wo_lo);
    cudaGetSymbolAddress((void**)&pQih, g_Qinh);  cudaGetSymbolAddress((void**)&pQil, g_Qinl);
    cudaGetSymbolAddress((void**)&pKih, g_Kinh);  cudaGetSymbolAddress((void**)&pKil, g_Kinl);
    cudaGetSymbolAddress((void**)&pVih, g_Vinh);  cudaGetSymbolAddress((void**)&pVil, g_Vinl);
    cudaGetSymbolAddress((void**)&pQoh, g_Qouth); cudaGetSymbolAddress((void**)&pQol, g_Qoutl);
    cudaGetSymbolAddress((void**)&pKoh, g_Kouth); cudaGetSymbolAddress((void**)&pKol, g_Koutl);
    cudaGetSymbolAddress((void**)&pVoh, g_Vouth); cudaGetSymbolAddress((void**)&pVol, g_Voutl);
    cudaGetSymbolAddress((void**)&p_bin,  g_bias_in);
    cudaGetSymbolAddress((void**)&p_bout, g_bias_out);
    cudaGetSymbolAddress((void**)&p_vah,  g_vahi);
    cudaGetSymbolAddress((void**)&p_val,  g_valo);

    cudaFuncSetAttribute(mma_gemm_qkv, cudaFuncAttributeMaxDynamicSharedMemorySize, SM_TOTAL);
    cudaFuncSetAttribute(mma_gemm_out, cudaFuncAttributeMaxDynamicSharedMemorySize, SM_TOTAL);
    cudaFuncSetAttribute(attn_mma, cudaFuncAttributeMaxDynamicSharedMemorySize, AT_SMEM);

    convert_wqkv<<<NEXT, Cdim>>>(W_qkv_in,  W_E_in,  p_winh,  p_winl);
    convert_wqkv<<<NEXT, Cdim>>>(W_qkv_out, W_E_out, p_wouth, p_woutl);
    convert_wo<<<Cdim, 2 * Cdim>>>(W_O, p_woh, p_wol);

    ln_kernel<<<ROWS / 8, 256>>>(e, ln_g, ln_b, p_ahi, p_alo);

    QkvSet s0 = { p_winh,  p_winl,  b_qkv_in,  b_E_in,
                  pQih, pQil, pKih, pKil, pVih, pVil, p_bin };
    QkvSet s1 = { p_wouth, p_woutl, b_qkv_out, b_E_out,
                  pQoh, pQol, pKoh, pKol, pVoh, pVol, p_bout };

    mma_gemm_qkv<<<dim3(NEXT / 64, ROWS / 128, 2), 256, SM_TOTAL>>>(
        p_ahi, p_alo, mask, s0, s1);

    attn_mma<<<dim3(Ndim, Bdim * Hdim, 2), 256, AT_SMEM>>>(
        pQih, pQil, pKih, pKil, pVih, pVil,
        pQoh, pQol, pKoh, pKol, pVoh, pVol,
        p_bin, p_bout, p_vah, p_val);

    mma_gemm_out<<<dim3(Cdim / 64, ROWS / 128), 256, SM_TOTAL>>>(
        p_vah, p_val, p_woh, p_wol, b_O, (float*)d_out);
}